// round 7
// baseline (speedup 1.0000x reference)
#include <cuda_runtime.h>
#include <cuda_bf16.h>
#include <math.h>
#include <stdint.h>

#define NN 50000
#define EE 400000
#define NBLK 391            // ceil(NN/128)
#define EBLK 3125           // EE/128
#define ZBLK 391            // zero-agg blocks appended to node gemm launch
#define INV_SCALE 0.17677669529663687f   // 1/sqrt(32)
#define LN_EPS 1e-5f

// Scratch: q, k, v, nres, agg (5*N*128 = 32M floats)
__device__ float g_scratch[32000000];
// bf16 hi/lo swizzled weight tiles: 6 weights x (32KB hi + 32KB lo)
__device__ __align__(256) unsigned char g_wbf[6 * 65536];
// pre-converted swizzled X tiles (32KB hi + 32KB lo per 128-row tile)
__device__ __align__(256) unsigned char g_xnbf[NBLK * 65536];   // node feats
__device__ __align__(256) unsigned char g_xebf[EBLK * 65536];   // edge feats

// ---- smem byte offsets ----
#define SW1HI 0
#define SW2HI 65536
#define SXHI  131072
#define SMEM_GEMM 196608
// P (float[128][132]) aliases the X region in the edge kernel
#define SP_OFF 131072
#define SMEM_EDGE (131072 + 128 * 132 * 4)   // 198656

// Swizzled byte offset in a 128x128 bf16 K-major tile (256B rows, 16B chunks,
// chunk ^= row&7 -> conflict-free for both row-parallel and k-parallel access).
__device__ __forceinline__ int sw_off(int row, int col) {
    return row * 256 + ((((col >> 3) ^ (row & 7)) & 15) << 4) + (col & 7) * 2;
}

__device__ __forceinline__ uint32_t smem_u32(const void* p) {
    uint32_t a;
    asm("{ .reg .u64 t; cvta.to.shared.u64 t, %1; cvt.u32.u64 %0, t; }"
        : "=r"(a) : "l"(p));
    return a;
}

__device__ __forceinline__ void hmma(float* c, uint32_t a0, uint32_t a1,
                                     uint32_t a2, uint32_t a3,
                                     uint32_t b0, uint32_t b1) {
    asm("mma.sync.aligned.m16n8k16.row.col.f32.bf16.bf16.f32 "
        "{%0,%1,%2,%3}, {%4,%5,%6,%7}, {%8,%9}, {%0,%1,%2,%3};"
        : "+f"(c[0]), "+f"(c[1]), "+f"(c[2]), "+f"(c[3])
        : "r"(a0), "r"(a1), "r"(a2), "r"(a3), "r"(b0), "r"(b1));
}

// pack two f32 -> bf16x2 {low=a, high=b} (rn)
__device__ __forceinline__ uint32_t pack_bf16x2(float a, float b) {
    uint32_t r;
    asm("cvt.rn.bf16x2.f32 %0, %1, %2;" : "=r"(r) : "f"(b), "f"(a));
    return r;
}

// ---------------------------------------------------------------------------
// Weight prep: split 6 weights into bf16 hi(trunc)/lo swizzled tiles
// ---------------------------------------------------------------------------
__global__ void prep_w(const float* __restrict__ W0, const float* __restrict__ W1,
                       const float* __restrict__ W2, const float* __restrict__ W3,
                       const float* __restrict__ W4, const float* __restrict__ W5)
{
    const float* W;
    switch (blockIdx.x) {
        case 0: W = W0; break; case 1: W = W1; break; case 2: W = W2; break;
        case 3: W = W3; break; case 4: W = W4; break; default: W = W5; break;
    }
    unsigned char* out = g_wbf + (size_t)blockIdx.x * 65536;
    for (int idx = threadIdx.x; idx < 16384; idx += blockDim.x) {
        int row = idx >> 7, col = idx & 127;
        float x = W[idx];
        uint32_t xu = __float_as_uint(x);
        uint32_t hi = xu & 0xffff0000u;                  // truncated bf16
        float lo = x - __uint_as_float(hi);
        __nv_bfloat16 lb = __float2bfloat16(lo);
        int off = sw_off(row, col);
        *reinterpret_cast<uint16_t*>(out + off) = (uint16_t)(hi >> 16);
        *reinterpret_cast<__nv_bfloat16*>(out + 32768 + off) = lb;
    }
}

// ---------------------------------------------------------------------------
// Pre-convert X (node + edge feats) into swizzled bf16 hi/lo tiles in global.
// Block b < NBLK -> node tile b; else edge tile (b - NBLK). 256 threads.
// ---------------------------------------------------------------------------
__global__ __launch_bounds__(256) void preconv(
    const float* __restrict__ node_feats, const float* __restrict__ edge_feats)
{
    const int b = blockIdx.x;
    const float* X;
    unsigned char* out;
    int m0, M;
    if (b < NBLK) {
        X = node_feats; out = g_xnbf + (size_t)b * 65536; m0 = b * 128; M = NN;
    } else {
        X = edge_feats; out = g_xebf + (size_t)(b - NBLK) * 65536; m0 = (b - NBLK) * 128; M = EE;
    }

    int tid = threadIdx.x;
    int r = tid >> 1;               // 0..127
    int ch = (tid & 1) * 64;        // 64-col strip
    bool valid = (m0 + r) < M;
    const float* xp = X + (size_t)(m0 + r) * 128 + ch;
    #pragma unroll
    for (int u = 0; u < 16; u++) {
        int c = ch + u * 4;
        float4 xv = make_float4(0.f, 0.f, 0.f, 0.f);
        if (valid) xv = __ldg(reinterpret_cast<const float4*>(xp + u * 4));
        uint32_t u0 = __float_as_uint(xv.x), u1 = __float_as_uint(xv.y);
        uint32_t u2 = __float_as_uint(xv.z), u3 = __float_as_uint(xv.w);
        uint32_t h01 = __byte_perm(u0, u1, 0x7632);
        uint32_t h23 = __byte_perm(u2, u3, 0x7632);
        float l0 = xv.x - __uint_as_float(u0 & 0xffff0000u);
        float l1 = xv.y - __uint_as_float(u1 & 0xffff0000u);
        float l2 = xv.z - __uint_as_float(u2 & 0xffff0000u);
        float l3 = xv.w - __uint_as_float(u3 & 0xffff0000u);
        int off = sw_off(r, c);
        *reinterpret_cast<uint2*>(out + off) = make_uint2(h01, h23);
        *reinterpret_cast<uint2*>(out + 32768 + off) =
            make_uint2(pack_bf16x2(l0, l1), pack_bf16x2(l2, l3));
    }
}

// ---------------------------------------------------------------------------
// Shared pieces. Block = 512 threads (16 warps).
// Warp tile: M=32 (2 m16 frags), N=64 (8 n8 frags). acc[2][8][4].
// ---------------------------------------------------------------------------
__device__ __forceinline__ void copy_weights_async(char* sm, int w1idx, int w2idx) {
    uint32_t d1 = smem_u32(sm + SW1HI);
    uint32_t d2 = smem_u32(sm + SW2HI);
    const char* s1 = reinterpret_cast<const char*>(g_wbf + (size_t)w1idx * 65536);
    const char* s2 = reinterpret_cast<const char*>(g_wbf + (size_t)w2idx * 65536);
    int tid = threadIdx.x;
    #pragma unroll
    for (int i = 0; i < 8; i++) {
        int j = (tid + i * 512) * 16;   // 64KB per weight (hi+lo contiguous)
        asm volatile("cp.async.cg.shared.global [%0], [%1], 16;"
                     :: "r"(d1 + j), "l"(s1 + j));
        asm volatile("cp.async.cg.shared.global [%0], [%1], 16;"
                     :: "r"(d2 + j), "l"(s2 + j));
    }
}

__device__ __forceinline__ void copy_x_async(char* sm, const unsigned char* xt) {
    uint32_t dx = smem_u32(sm + SXHI);
    const char* sx = reinterpret_cast<const char*>(xt);
    int tid = threadIdx.x;
    #pragma unroll
    for (int i = 0; i < 8; i++) {
        int j = (tid + i * 512) * 16;   // 64KB (hi+lo contiguous)
        asm volatile("cp.async.cg.shared.global [%0], [%1], 16;"
                     :: "r"(dx + j), "l"(sx + j));
    }
    asm volatile("cp.async.commit_group;");
}

__device__ __forceinline__ void mma_tile(const char* sm, float acc[2][8][4]) {
    const int lane = threadIdx.x & 31;
    const int wid  = threadIdx.x >> 5;   // 0..15
    const int wm = wid & 3;        // M slice: wm*32
    const int wn = wid >> 2;       // combined N slice: wn*64 (0..3)
    const int g  = lane >> 2;
    const int t4 = (lane & 3) * 4;

    const char* xhi = sm + SXHI;
    const char* xlo = sm + SXHI + 32768;
    const char* wh = sm + ((wn >= 2) ? SW2HI : SW1HI);
    const char* wl = wh + 32768;

    const int arow = (wm * 32 + g) * 256 + t4;
    const int brow = ((wn & 1) * 64 + g) * 256 + t4;

    #pragma unroll
    for (int i = 0; i < 2; i++)
        #pragma unroll
        for (int j = 0; j < 8; j++)
            #pragma unroll
            for (int r = 0; r < 4; r++) acc[i][j][r] = 0.f;

    #pragma unroll
    for (int ks = 0; ks < 8; ks++) {
        const int cx0 = (((2 * ks) ^ g) << 4);
        const int cx1 = (((2 * ks + 1) ^ g) << 4);

        uint32_t ah[2][4], al[2][4];
        #pragma unroll
        for (int i = 0; i < 2; i++) {
            int r0 = arow + i * 16 * 256;
            int r8 = r0 + 8 * 256;
            ah[i][0] = *reinterpret_cast<const uint32_t*>(xhi + r0 + cx0);
            ah[i][1] = *reinterpret_cast<const uint32_t*>(xhi + r8 + cx0);
            ah[i][2] = *reinterpret_cast<const uint32_t*>(xhi + r0 + cx1);
            ah[i][3] = *reinterpret_cast<const uint32_t*>(xhi + r8 + cx1);
            al[i][0] = *reinterpret_cast<const uint32_t*>(xlo + r0 + cx0);
            al[i][1] = *reinterpret_cast<const uint32_t*>(xlo + r8 + cx0);
            al[i][2] = *reinterpret_cast<const uint32_t*>(xlo + r0 + cx1);
            al[i][3] = *reinterpret_cast<const uint32_t*>(xlo + r8 + cx1);
        }
        #pragma unroll
        for (int j = 0; j < 8; j++) {
            int rb = brow + j * 8 * 256;
            uint32_t bh0 = *reinterpret_cast<const uint32_t*>(wh + rb + cx0);
            uint32_t bh1 = *reinterpret_cast<const uint32_t*>(wh + rb + cx1);
            uint32_t bl0 = *reinterpret_cast<const uint32_t*>(wl + rb + cx0);
            uint32_t bl1 = *reinterpret_cast<const uint32_t*>(wl + rb + cx1);
            #pragma unroll
            for (int i = 0; i < 2; i++) {
                hmma(acc[i][j], ah[i][0], ah[i][1], ah[i][2], ah[i][3], bh0, bh1);
                hmma(acc[i][j], al[i][0], al[i][1], al[i][2], al[i][3], bh0, bh1);
                hmma(acc[i][j], ah[i][0], ah[i][1], ah[i][2], ah[i][3], bl0, bl1);
            }
        }
    }
}

// ---------------------------------------------------------------------------
// Node GEMMs merged: half 0 -> (Wq,Wk)->(q,k), half 1 -> (Wv,Wout)->(v,nres).
// Trailing ZBLK blocks zero the agg buffer.
// ---------------------------------------------------------------------------
__global__ __launch_bounds__(512, 1) void gemm_node(
    const float* __restrict__ bq, const float* __restrict__ bk,
    const float* __restrict__ bv, const float* __restrict__ bout,
    float* __restrict__ q, float* __restrict__ kk,
    float* __restrict__ vv, float* __restrict__ nres,
    float* __restrict__ agg)
{
    if (blockIdx.x >= 2 * NBLK) {
        int idx = (blockIdx.x - 2 * NBLK) * 512 + threadIdx.x;
        const int stride = ZBLK * 512;
        float4 z = make_float4(0.f, 0.f, 0.f, 0.f);
        for (int i = idx; i < NN * 32; i += stride)
            reinterpret_cast<float4*>(agg)[i] = z;
        return;
    }

    extern __shared__ char sm[];
    const int half = blockIdx.x / NBLK;
    const int tile = blockIdx.x % NBLK;
    const int m0 = tile * 128;
    const float* b1 = half ? bv : bq;
    const float* b2 = half ? bout : bk;
    float* Y1 = half ? vv : q;
    float* Y2 = half ? nres : kk;

    copy_weights_async(sm, half * 2, half * 2 + 1);
    copy_x_async(sm, g_xnbf + (size_t)tile * 65536);
    asm volatile("cp.async.wait_group 0;");
    __syncthreads();

    float acc[2][8][4];
    mma_tile(sm, acc);

    const int lane = threadIdx.x & 31;
    const int wid  = threadIdx.x >> 5;
    const int wm = wid & 3, wn = wid >> 2;
    const int g = lane >> 2, t2 = (lane & 3) * 2;

    const float* bias = (wn >= 2) ? b2 : b1;
    float* Y = (wn >= 2) ? Y2 : Y1;
    float2 bb[8];
    #pragma unroll
    for (int j = 0; j < 8; j++) {
        int colw = (wn & 1) * 64 + j * 8 + t2;
        bb[j] = *reinterpret_cast<const float2*>(&bias[colw]);
    }
    #pragma unroll
    for (int i = 0; i < 2; i++) {
        int rlo = m0 + wm * 32 + i * 16 + g;
        int rhi = rlo + 8;
        #pragma unroll
        for (int j = 0; j < 8; j++) {
            int colw = (wn & 1) * 64 + j * 8 + t2;
            if (rlo < NN) {
                float2 o = make_float2(acc[i][j][0] + bb[j].x, acc[i][j][1] + bb[j].y);
                *reinterpret_cast<float2*>(&Y[(size_t)rlo * 128 + colw]) = o;
            }
            if (rhi < NN) {
                float2 o = make_float2(acc[i][j][2] + bb[j].x, acc[i][j][3] + bb[j].y);
                *reinterpret_cast<float2*>(&Y[(size_t)rhi * 128 + colw]) = o;
            }
        }
    }
}

// ---------------------------------------------------------------------------
// Fused edge kernel: block = 128 edges, 512 threads.
// ---------------------------------------------------------------------------
__global__ __launch_bounds__(512, 1) void edge_fused(
    const float* __restrict__ be, const float* __restrict__ bev,
    const int* __restrict__ src, const int* __restrict__ dst,
    const float* __restrict__ q, const float* __restrict__ k,
    const float* __restrict__ v,
    const float* __restrict__ ln_eg, const float* __restrict__ ln_eb,
    float* __restrict__ agg, float* __restrict__ y_out)
{
    extern __shared__ char sm[];
    float* P = reinterpret_cast<float*>(sm + SP_OFF);   // [128][132]
    const int e0 = blockIdx.x * 128;

    copy_weights_async(sm, 4, 5);      // We, Wev
    copy_x_async(sm, g_xebf + (size_t)blockIdx.x * 65536);

    const int lane = threadIdx.x & 31;
    const int wid  = threadIdx.x >> 5;   // 0..15
    const int wm = wid & 3, wn = wid >> 2;
    const int g = lane >> 2, t2 = (lane & 3) * 2;

    // Preload this warp's 8 edges' src (lanes 0-7) / dst (lanes 8-15) indices
    // while cp.async streams in.
    int sd = 0;
    {
        int eidx = e0 + wid * 8 + (lane & 7);
        if (lane < 16) sd = __ldg((lane < 8) ? &src[eidx] : &dst[eidx]);
    }
    const float* bias = (wn >= 2) ? bev : be;
    float2 bb[8];
    #pragma unroll
    for (int j = 0; j < 8; j++) {
        int colw = (wn & 1) * 64 + j * 8 + t2;
        bb[j] = *reinterpret_cast<const float2*>(&bias[colw]);
    }

    asm volatile("cp.async.wait_group 0;");
    __syncthreads();

    float acc[2][8][4];
    mma_tile(sm, acc);
    __syncthreads();   // X region dead; P can be written

    // Phase A: eproj + be -> P (warps wn<2 hold the We product)
    if (wn < 2) {
        #pragma unroll
        for (int i = 0; i < 2; i++) {
            int rlo = wm * 32 + i * 16 + g;
            int rhi = rlo + 8;
            #pragma unroll
            for (int j = 0; j < 8; j++) {
                int colw = (wn & 1) * 64 + j * 8 + t2;
                P[rlo * 132 + colw]     = acc[i][j][0] + bb[j].x;
                P[rlo * 132 + colw + 1] = acc[i][j][1] + bb[j].y;
                P[rhi * 132 + colw]     = acc[i][j][2] + bb[j].x;
                P[rhi * 132 + colw + 1] = acc[i][j][3] + bb[j].y;
            }
        }
    }
    __syncthreads();

    // Phase B: edge math; 16 warps x 8 rows = 128 edges.
    // Lane owns 4 consecutive cols (head = lane>>3). q/k/v gathers prefetched
    // one iteration ahead; indices come from the sd register via shfl.
    {
        const unsigned FULL = 0xffffffffu;
        float4 ge = *reinterpret_cast<const float4*>(&ln_eg[4 * lane]);
        float4 gb = *reinterpret_cast<const float4*>(&ln_eb[4 * lane]);

        int s = __shfl_sync(FULL, sd, 0);
        int d = __shfl_sync(FULL, sd, 8);
        float4 q4 = __ldg(reinterpret_cast<const float4*>(&q[(size_t)s * 128 + 4 * lane]));
        float4 k4 = __ldg(reinterpret_cast<const float4*>(&k[(size_t)d * 128 + 4 * lane]));
        float4 v4 = __ldg(reinterpret_cast<const float4*>(&v[(size_t)s * 128 + 4 * lane]));

        #pragma unroll 1
        for (int it = 0; it < 8; it++) {
            int sn = 0, dn = 0;
            float4 qn, kn, vn;
            if (it < 7) {
                sn = __shfl_sync(FULL, sd, it + 1);
                dn = __shfl_sync(FULL, sd, it + 9);
                qn = __ldg(reinterpret_cast<const float4*>(&q[(size_t)sn * 128 + 4 * lane]));
                kn = __ldg(reinterpret_cast<const float4*>(&k[(size_t)dn * 128 + 4 * lane]));
                vn = __ldg(reinterpret_cast<const float4*>(&v[(size_t)sn * 128 + 4 * lane]));
            }

            int row = wid * 8 + it;
            float pd = q4.x * k4.x + q4.y * k4.y + q4.z * k4.z + q4.w * k4.w;
            pd += __shfl_xor_sync(FULL, pd, 1);
            pd += __shfl_xor_sync(FULL, pd, 2);
            pd += __shfl_xor_sync(FULL, pd, 4);

            float4 m4 = *reinterpret_cast<const float4*>(&P[row * 132 + 4 * lane]);
            m4.x = fmaf(pd, INV_SCALE, m4.x);
            m4.y = fmaf(pd, INV_SCALE, m4.y);
            m4.z = fmaf(pd, INV_SCALE, m4.z);
            m4.w = fmaf(pd, INV_SCALE, m4.w);

            // softmax over the 4 heads: partners at lane^8, lane^16
            float4 mx = m4;
            #pragma unroll
            for (int off = 8; off <= 16; off <<= 1) {
                mx.x = fmaxf(mx.x, __shfl_xor_sync(FULL, mx.x, off));
                mx.y = fmaxf(mx.y, __shfl_xor_sync(FULL, mx.y, off));
                mx.z = fmaxf(mx.z, __shfl_xor_sync(FULL, mx.z, off));
                mx.w = fmaxf(mx.w, __shfl_xor_sync(FULL, mx.w, off));
            }
            float4 ex;
            ex.x = __expf(m4.x - mx.x); ex.y = __expf(m4.y - mx.y);
            ex.z = __expf(m4.z - mx.z); ex.w = __expf(m4.w - mx.w);
            float4 sx = ex;
            #pragma unroll
            for (int off = 8; off <= 16; off <<= 1) {
                sx.x += __shfl_xor_sync(FULL, sx.x, off);
                sx.y += __shfl_xor_sync(FULL, sx.y, off);
                sx.z += __shfl_xor_sync(FULL, sx.z, off);
                sx.w += __shfl_xor_sync(FULL, sx.w, off);
            }
            float4 msg;
            msg.x = v4.x * ex.x / sx.x;
            msg.y = v4.y * ex.y / sx.y;
            msg.z = v4.z * ex.z / sx.z;
            msg.w = v4.w * ex.w / sx.w;
            float* ap = &agg[(size_t)d * 128 + 4 * lane];
            asm volatile("red.global.add.v4.f32 [%0], {%1, %2, %3, %4};"
                         :: "l"(ap), "f"(msg.x), "f"(msg.y), "f"(msg.z), "f"(msg.w)
                         : "memory");

            // layernorm over 128 cols
            float ls = m4.x + m4.y + m4.z + m4.w;
            float lq = m4.x * m4.x + m4.y * m4.y + m4.z * m4.z + m4.w * m4.w;
            #pragma unroll
            for (int off = 16; off > 0; off >>= 1) {
                ls += __shfl_xor_sync(FULL, ls, off);
                lq += __shfl_xor_sync(FULL, lq, off);
            }
            float mu = ls * (1.0f / 128.0f);
            float var = lq * (1.0f / 128.0f) - mu * mu;
            float rs = rsqrtf(var + LN_EPS);

            float4 sil;
            {
                float t0 = fmaf((m4.x - mu) * rs, ge.x, gb.x);
                float t1 = fmaf((m4.y - mu) * rs, ge.y, gb.y);
                float t2f = fmaf((m4.z - mu) * rs, ge.z, gb.z);
                float t3 = fmaf((m4.w - mu) * rs, ge.w, gb.w);
                sil.x = t0 / (1.0f + __expf(-t0));
                sil.y = t1 / (1.0f + __expf(-t1));
                sil.z = t2f / (1.0f + __expf(-t2f));
                sil.w = t3 / (1.0f + __expf(-t3));
            }
            *reinterpret_cast<float4*>(&P[row * 132 + 4 * lane]) = sil;

            s = sn; d = dn; q4 = qn; k4 = kn; v4 = vn;
        }
    }
    __syncthreads();

    // Phase C: y = eres + bev + silu   (warps wn>=2 hold the Wev product)
    if (wn >= 2) {
        #pragma unroll
        for (int i = 0; i < 2; i++) {
            int rlo = wm * 32 + i * 16 + g;
            int rhi = rlo + 8;
            #pragma unroll
            for (int j = 0; j < 8; j++) {
                int colw = (wn & 1) * 64 + j * 8 + t2;
                float2 o0, o1;
                o0.x = acc[i][j][0] + bb[j].x + P[rlo * 132 + colw];
                o0.y = acc[i][j][1] + bb[j].y + P[rlo * 132 + colw + 1];
                o1.x = acc[i][j][2] + bb[j].x + P[rhi * 132 + colw];
                o1.y = acc[i][j][3] + bb[j].y + P[rhi * 132 + colw + 1];
                *reinterpret_cast<float2*>(&y_out[(size_t)(e0 + rlo) * 128 + colw]) = o0;
                *reinterpret_cast<float2*>(&y_out[(size_t)(e0 + rhi) * 128 + colw]) = o1;
            }
        }
    }
}

// ---------------------------------------------------------------------------
// Node finalize: x = node_res + silu(LN_128(agg)), float4 lanes
// ---------------------------------------------------------------------------
__global__ __launch_bounds__(256) void node_kernel(
    const float* __restrict__ agg, const float* __restrict__ nres,
    const float* __restrict__ ln_ng, const float* __restrict__ ln_nb,
    float* __restrict__ x_out)
{
    int node = (blockIdx.x * blockDim.x + threadIdx.x) >> 5;
    int lane = threadIdx.x & 31;
    if (node >= NN) return;
    const unsigned FULL = 0xffffffffu;

    size_t base = (size_t)node * 128 + 4 * lane;
    float4 a = __ldg(reinterpret_cast<const float4*>(&agg[base]));

    float ls = a.x + a.y + a.z + a.w;
    float lq = a.x * a.x + a.y * a.y + a.z * a.z + a.w * a.w;
    #pragma unroll
    for (int off = 16; off > 0; off >>= 1) {
        ls += __shfl_xor_sync(FULL, ls, off);
        lq += __shfl_xor_sync(FULL, lq, off);
    }
    float mu  = ls * (1.0f / 128.0f);
    float var = lq * (1.0f / 128.0f) - mu * mu;
    float rs  = rsqrtf(var + LN_EPS);

    float4 g = __ldg(reinterpret_cast<const float4*>(&ln_ng[4 * lane]));
    float4 b = __ldg(reinterpret_cast<const float4*>(&ln_nb[4 * lane]));
    float4 r = __ldg(reinterpret_cast<const float4*>(&nres[base]));

    float t0 = fmaf((a.x - mu) * rs, g.x, b.x);
    float t1 = fmaf((a.y - mu) * rs, g.y, b.y);
    float t2 = fmaf((a.z - mu) * rs, g.z, b.z);
    float t3 = fmaf((a.w - mu) * rs, g.w, b.w);
    float4 o;
    o.x = t0 / (1.0f + __expf(-t0)) + r.x;
    o.y = t1 / (1.0f + __expf(-t1)) + r.y;
    o.z = t2 / (1.0f + __expf(-t2)) + r.z;
    o.w = t3 / (1.0f + __expf(-t3)) + r.w;
    *reinterpret_cast<float4*>(&x_out[base]) = o;
}

// ---------------------------------------------------------------------------
// Launch
// ---------------------------------------------------------------------------
extern "C" void kernel_launch(void* const* d_in, const int* in_sizes, int n_in,
                              void* d_out, int out_size)
{
    const float* node_feats = (const float*)d_in[0];
    const float* edge_feats = (const float*)d_in[1];
    const int*   src        = (const int*)d_in[2];
    const int*   dst        = (const int*)d_in[3];
    const float* Wq   = (const float*)d_in[4];
    const float* bq   = (const float*)d_in[5];
    const float* Wk   = (const float*)d_in[6];
    const float* bk   = (const float*)d_in[7];
    const float* Wv   = (const float*)d_in[8];
    const float* bv   = (const float*)d_in[9];
    const float* We   = (const float*)d_in[10];
    const float* be   = (const float*)d_in[11];
    const float* Wev  = (const float*)d_in[12];
    const float* bev  = (const float*)d_in[13];
    const float* Wout = (const float*)d_in[14];
    const float* bout = (const float*)d_in[15];
    const float* ln_ng = (const float*)d_in[16];
    const float* ln_nb = (const float*)d_in[17];
    const float* ln_eg = (const float*)d_in[18];
    const float* ln_eb = (const float*)d_in[19];

    float* scratch = nullptr;
    cudaGetSymbolAddress((void**)&scratch, g_scratch);
    float* q    = scratch;
    float* kk   = q    + (size_t)NN * 128;
    float* vv   = kk   + (size_t)NN * 128;
    float* nres = vv   + (size_t)NN * 128;
    float* agg  = nres + (size_t)NN * 128;

    float* x_out = (float*)d_out;
    float* y_out = x_out + (size_t)NN * 128;

    static bool attr_set = false;
    if (!attr_set) {
        cudaFuncSetAttribute(gemm_node, cudaFuncAttributeMaxDynamicSharedMemorySize, SMEM_GEMM);
        cudaFuncSetAttribute(edge_fused, cudaFuncAttributeMaxDynamicSharedMemorySize, SMEM_EDGE);
        attr_set = true;
    }

    // launch order matters for ncu (-s puts launch index 3 under the profiler):
    // 0 prep_w, 1 preconv, 2 gemm_node, 3 edge_fused, 4 node_kernel
    prep_w<<<6, 256>>>(Wq, Wk, Wv, Wout, We, Wev);
    preconv<<<NBLK + EBLK, 256>>>(node_feats, edge_feats);
    gemm_node<<<2 * NBLK + ZBLK, 512, SMEM_GEMM>>>(
        bq, bk, bv, bout, q, kk, vv, nres, agg);
    edge_fused<<<EBLK, 512, SMEM_EDGE>>>(
        be, bev, src, dst, q, kk, vv, ln_eg, ln_eb, agg, y_out);
    node_kernel<<<NN / 8, 256>>>(agg, nres, ln_ng, ln_nb, x_out);
}

// round 8
// speedup vs baseline: 1.1654x; 1.1654x over previous
#include <cuda_runtime.h>
#include <cuda_bf16.h>
#include <math.h>
#include <stdint.h>

#define NN 50000
#define EE 400000
#define NBLK 391            // ceil(NN/128) node tiles
#define ETILES 6250         // EE/64 edge tiles
#define ZBLK 391            // zero-agg blocks appended to node gemm launch
#define INV_SCALE 0.17677669529663687f   // 1/sqrt(32)
#define LN_EPS 1e-5f

// Scratch: q, k, v, nres, agg (5*N*128 = 32M floats)
__device__ float g_scratch[32000000];
// bf16 hi/lo swizzled weight tiles: 6 weights x (32KB hi + 32KB lo)
__device__ __align__(256) unsigned char g_wbf[6 * 65536];
// pre-converted swizzled X tiles
__device__ __align__(256) unsigned char g_xnbf[(size_t)NBLK * 65536];   // node: 128-row tiles
__device__ __align__(256) unsigned char g_xebf[(size_t)ETILES * 32768]; // edge: 64-row tiles

// ---- node gemm smem layout ----
#define SW1HI 0
#define SW2HI 65536
#define SXHI  131072
#define SMEM_GEMM 196608
// ---- edge persistent smem layout ----
#define EXB   131072                     // two 32KB X buffers
#define EP    196608                     // P: 64 x 132 floats = 33792
#define SMEM_EDGE_P (196608 + 64 * 132 * 4)   // 230400 (max 232448)

// Swizzled byte offset in a K-major bf16 tile (256B rows, 16B chunks,
// chunk ^= row&7 -> conflict-free for row-parallel and k-parallel access).
__device__ __forceinline__ int sw_off(int row, int col) {
    return row * 256 + ((((col >> 3) ^ (row & 7)) & 15) << 4) + (col & 7) * 2;
}

__device__ __forceinline__ uint32_t smem_u32(const void* p) {
    uint32_t a;
    asm("{ .reg .u64 t; cvta.to.shared.u64 t, %1; cvt.u32.u64 %0, t; }"
        : "=r"(a) : "l"(p));
    return a;
}

__device__ __forceinline__ void hmma(float* c, uint32_t a0, uint32_t a1,
                                     uint32_t a2, uint32_t a3,
                                     uint32_t b0, uint32_t b1) {
    asm("mma.sync.aligned.m16n8k16.row.col.f32.bf16.bf16.f32 "
        "{%0,%1,%2,%3}, {%4,%5,%6,%7}, {%8,%9}, {%0,%1,%2,%3};"
        : "+f"(c[0]), "+f"(c[1]), "+f"(c[2]), "+f"(c[3])
        : "r"(a0), "r"(a1), "r"(a2), "r"(a3), "r"(b0), "r"(b1));
}

__device__ __forceinline__ uint32_t pack_bf16x2(float a, float b) {
    uint32_t r;
    asm("cvt.rn.bf16x2.f32 %0, %1, %2;" : "=r"(r) : "f"(b), "f"(a));
    return r;
}

// ---------------------------------------------------------------------------
// Weight prep: split 6 weights into bf16 hi(trunc)/lo swizzled tiles
// ---------------------------------------------------------------------------
__global__ void prep_w(const float* __restrict__ W0, const float* __restrict__ W1,
                       const float* __restrict__ W2, const float* __restrict__ W3,
                       const float* __restrict__ W4, const float* __restrict__ W5)
{
    const float* W;
    switch (blockIdx.x) {
        case 0: W = W0; break; case 1: W = W1; break; case 2: W = W2; break;
        case 3: W = W3; break; case 4: W = W4; break; default: W = W5; break;
    }
    unsigned char* out = g_wbf + (size_t)blockIdx.x * 65536;
    for (int idx = threadIdx.x; idx < 16384; idx += blockDim.x) {
        int row = idx >> 7, col = idx & 127;
        float x = W[idx];
        uint32_t xu = __float_as_uint(x);
        uint32_t hi = xu & 0xffff0000u;
        float lo = x - __uint_as_float(hi);
        __nv_bfloat16 lb = __float2bfloat16(lo);
        int off = sw_off(row, col);
        *reinterpret_cast<uint16_t*>(out + off) = (uint16_t)(hi >> 16);
        *reinterpret_cast<__nv_bfloat16*>(out + 32768 + off) = lb;
    }
}

// ---------------------------------------------------------------------------
// Pre-convert X: node feats -> 128-row tiles (64KB), edge feats -> 64-row (32KB)
// ---------------------------------------------------------------------------
__global__ __launch_bounds__(256) void preconv(
    const float* __restrict__ node_feats, const float* __restrict__ edge_feats)
{
    const int b = blockIdx.x;
    int tid = threadIdx.x;
    if (b < NBLK) {
        unsigned char* out = g_xnbf + (size_t)b * 65536;
        int m0 = b * 128;
        int r = tid >> 1;               // 0..127
        int ch = (tid & 1) * 64;
        bool valid = (m0 + r) < NN;
        const float* xp = node_feats + (size_t)(m0 + r) * 128 + ch;
        #pragma unroll
        for (int u = 0; u < 16; u++) {
            int c = ch + u * 4;
            float4 xv = make_float4(0.f, 0.f, 0.f, 0.f);
            if (valid) xv = __ldg(reinterpret_cast<const float4*>(xp + u * 4));
            uint32_t u0 = __float_as_uint(xv.x), u1 = __float_as_uint(xv.y);
            uint32_t u2 = __float_as_uint(xv.z), u3 = __float_as_uint(xv.w);
            uint32_t h01 = __byte_perm(u0, u1, 0x7632);
            uint32_t h23 = __byte_perm(u2, u3, 0x7632);
            float l0 = xv.x - __uint_as_float(u0 & 0xffff0000u);
            float l1 = xv.y - __uint_as_float(u1 & 0xffff0000u);
            float l2 = xv.z - __uint_as_float(u2 & 0xffff0000u);
            float l3 = xv.w - __uint_as_float(u3 & 0xffff0000u);
            int off = sw_off(r, c);
            *reinterpret_cast<uint2*>(out + off) = make_uint2(h01, h23);
            *reinterpret_cast<uint2*>(out + 32768 + off) =
                make_uint2(pack_bf16x2(l0, l1), pack_bf16x2(l2, l3));
        }
    } else {
        int tile = b - NBLK;
        unsigned char* out = g_xebf + (size_t)tile * 32768;
        int m0 = tile * 64;
        int r = tid >> 2;               // 0..63
        int ch = (tid & 3) * 32;
        const float* xp = edge_feats + (size_t)(m0 + r) * 128 + ch;
        #pragma unroll
        for (int u = 0; u < 8; u++) {
            int c = ch + u * 4;
            float4 xv = __ldg(reinterpret_cast<const float4*>(xp + u * 4));
            uint32_t u0 = __float_as_uint(xv.x), u1 = __float_as_uint(xv.y);
            uint32_t u2 = __float_as_uint(xv.z), u3 = __float_as_uint(xv.w);
            uint32_t h01 = __byte_perm(u0, u1, 0x7632);
            uint32_t h23 = __byte_perm(u2, u3, 0x7632);
            float l0 = xv.x - __uint_as_float(u0 & 0xffff0000u);
            float l1 = xv.y - __uint_as_float(u1 & 0xffff0000u);
            float l2 = xv.z - __uint_as_float(u2 & 0xffff0000u);
            float l3 = xv.w - __uint_as_float(u3 & 0xffff0000u);
            int off = sw_off(r, c);   // < 16384 for r < 64
            *reinterpret_cast<uint2*>(out + off) = make_uint2(h01, h23);
            *reinterpret_cast<uint2*>(out + 16384 + off) =
                make_uint2(pack_bf16x2(l0, l1), pack_bf16x2(l2, l3));
        }
    }
}

// ---------------------------------------------------------------------------
// cp.async helpers
// ---------------------------------------------------------------------------
__device__ __forceinline__ void copy_weights_async(char* sm, int w1idx, int w2idx) {
    uint32_t d1 = smem_u32(sm + SW1HI);
    uint32_t d2 = smem_u32(sm + SW2HI);
    const char* s1 = reinterpret_cast<const char*>(g_wbf + (size_t)w1idx * 65536);
    const char* s2 = reinterpret_cast<const char*>(g_wbf + (size_t)w2idx * 65536);
    int tid = threadIdx.x;
    #pragma unroll
    for (int i = 0; i < 8; i++) {
        int j = (tid + i * 512) * 16;
        asm volatile("cp.async.cg.shared.global [%0], [%1], 16;"
                     :: "r"(d1 + j), "l"(s1 + j));
        asm volatile("cp.async.cg.shared.global [%0], [%1], 16;"
                     :: "r"(d2 + j), "l"(s2 + j));
    }
}

__device__ __forceinline__ void copy_xn_async(char* sm, const unsigned char* xt) {
    uint32_t dx = smem_u32(sm + SXHI);
    const char* sx = reinterpret_cast<const char*>(xt);
    int tid = threadIdx.x;
    #pragma unroll
    for (int i = 0; i < 8; i++) {
        int j = (tid + i * 512) * 16;   // 64KB
        asm volatile("cp.async.cg.shared.global [%0], [%1], 16;"
                     :: "r"(dx + j), "l"(sx + j));
    }
    asm volatile("cp.async.commit_group;");
}

__device__ __forceinline__ void copy_xe_async(char* sm, int bufsel,
                                              const unsigned char* xt) {
    uint32_t dx = smem_u32(sm + EXB + bufsel * 32768);
    const char* sx = reinterpret_cast<const char*>(xt);
    int tid = threadIdx.x;
    #pragma unroll
    for (int i = 0; i < 4; i++) {
        int j = (tid + i * 512) * 16;   // 32KB
        asm volatile("cp.async.cg.shared.global [%0], [%1], 16;"
                     :: "r"(dx + j), "l"(sx + j));
    }
}

// ---------------------------------------------------------------------------
// MMA cores. 512 threads = 16 warps: wm = wid&3 (M slice), wn = wid>>2
// (combined N slice over [W1 cols | W2 cols]). 3-term bf16 split.
// ---------------------------------------------------------------------------
__device__ __forceinline__ void mma_tile128(const char* sm, float acc[2][8][4]) {
    const int lane = threadIdx.x & 31;
    const int wid  = threadIdx.x >> 5;
    const int wm = wid & 3, wn = wid >> 2;
    const int g  = lane >> 2;
    const int t4 = (lane & 3) * 4;

    const char* xhi = sm + SXHI;
    const char* xlo = sm + SXHI + 32768;
    const char* wh = sm + ((wn >= 2) ? SW2HI : SW1HI);
    const char* wl = wh + 32768;

    const int arow = (wm * 32 + g) * 256 + t4;
    const int brow = ((wn & 1) * 64 + g) * 256 + t4;

    #pragma unroll
    for (int i = 0; i < 2; i++)
        #pragma unroll
        for (int j = 0; j < 8; j++)
            #pragma unroll
            for (int r = 0; r < 4; r++) acc[i][j][r] = 0.f;

    #pragma unroll
    for (int ks = 0; ks < 8; ks++) {
        const int cx0 = (((2 * ks) ^ g) << 4);
        const int cx1 = (((2 * ks + 1) ^ g) << 4);
        uint32_t ah[2][4], al[2][4];
        #pragma unroll
        for (int i = 0; i < 2; i++) {
            int r0 = arow + i * 16 * 256;
            int r8 = r0 + 8 * 256;
            ah[i][0] = *reinterpret_cast<const uint32_t*>(xhi + r0 + cx0);
            ah[i][1] = *reinterpret_cast<const uint32_t*>(xhi + r8 + cx0);
            ah[i][2] = *reinterpret_cast<const uint32_t*>(xhi + r0 + cx1);
            ah[i][3] = *reinterpret_cast<const uint32_t*>(xhi + r8 + cx1);
            al[i][0] = *reinterpret_cast<const uint32_t*>(xlo + r0 + cx0);
            al[i][1] = *reinterpret_cast<const uint32_t*>(xlo + r8 + cx0);
            al[i][2] = *reinterpret_cast<const uint32_t*>(xlo + r0 + cx1);
            al[i][3] = *reinterpret_cast<const uint32_t*>(xlo + r8 + cx1);
        }
        #pragma unroll
        for (int j = 0; j < 8; j++) {
            int rb = brow + j * 8 * 256;
            uint32_t bh0 = *reinterpret_cast<const uint32_t*>(wh + rb + cx0);
            uint32_t bh1 = *reinterpret_cast<const uint32_t*>(wh + rb + cx1);
            uint32_t bl0 = *reinterpret_cast<const uint32_t*>(wl + rb + cx0);
            uint32_t bl1 = *reinterpret_cast<const uint32_t*>(wl + rb + cx1);
            #pragma unroll
            for (int i = 0; i < 2; i++) {
                hmma(acc[i][j], ah[i][0], ah[i][1], ah[i][2], ah[i][3], bh0, bh1);
                hmma(acc[i][j], al[i][0], al[i][1], al[i][2], al[i][3], bh0, bh1);
                hmma(acc[i][j], ah[i][0], ah[i][1], ah[i][2], ah[i][3], bl0, bl1);
            }
        }
    }
}

// M=64 variant reading from one of the two edge X buffers
__device__ __forceinline__ void mma_tile64(const char* sm, int bufsel,
                                           float acc[8][4]) {
    const int lane = threadIdx.x & 31;
    const int wid  = threadIdx.x >> 5;
    const int wm = wid & 3, wn = wid >> 2;
    const int g  = lane >> 2;
    const int t4 = (lane & 3) * 4;

    const char* xb  = sm + EXB + bufsel * 32768;
    const char* xhi = xb;
    const char* xlo = xb + 16384;
    const char* wh = sm + ((wn >= 2) ? SW2HI : SW1HI);
    const char* wl = wh + 32768;

    const int arow = (wm * 16 + g) * 256 + t4;
    const int brow = ((wn & 1) * 64 + g) * 256 + t4;

    #pragma unroll
    for (int j = 0; j < 8; j++)
        #pragma unroll
        for (int r = 0; r < 4; r++) acc[j][r] = 0.f;

    #pragma unroll
    for (int ks = 0; ks < 8; ks++) {
        const int cx0 = (((2 * ks) ^ g) << 4);
        const int cx1 = (((2 * ks + 1) ^ g) << 4);
        int r8 = arow + 8 * 256;
        uint32_t a0h = *reinterpret_cast<const uint32_t*>(xhi + arow + cx0);
        uint32_t a1h = *reinterpret_cast<const uint32_t*>(xhi + r8 + cx0);
        uint32_t a2h = *reinterpret_cast<const uint32_t*>(xhi + arow + cx1);
        uint32_t a3h = *reinterpret_cast<const uint32_t*>(xhi + r8 + cx1);
        uint32_t a0l = *reinterpret_cast<const uint32_t*>(xlo + arow + cx0);
        uint32_t a1l = *reinterpret_cast<const uint32_t*>(xlo + r8 + cx0);
        uint32_t a2l = *reinterpret_cast<const uint32_t*>(xlo + arow + cx1);
        uint32_t a3l = *reinterpret_cast<const uint32_t*>(xlo + r8 + cx1);
        #pragma unroll
        for (int j = 0; j < 8; j++) {
            int rb = brow + j * 8 * 256;
            uint32_t bh0 = *reinterpret_cast<const uint32_t*>(wh + rb + cx0);
            uint32_t bh1 = *reinterpret_cast<const uint32_t*>(wh + rb + cx1);
            uint32_t bl0 = *reinterpret_cast<const uint32_t*>(wl + rb + cx0);
            uint32_t bl1 = *reinterpret_cast<const uint32_t*>(wl + rb + cx1);
            hmma(acc[j], a0h, a1h, a2h, a3h, bh0, bh1);
            hmma(acc[j], a0l, a1l, a2l, a3l, bh0, bh1);
            hmma(acc[j], a0h, a1h, a2h, a3h, bl0, bl1);
        }
    }
}

// ---------------------------------------------------------------------------
// Node GEMMs merged + trailing agg-zero blocks
// ---------------------------------------------------------------------------
__global__ __launch_bounds__(512, 1) void gemm_node(
    const float* __restrict__ bq, const float* __restrict__ bk,
    const float* __restrict__ bv, const float* __restrict__ bout,
    float* __restrict__ q, float* __restrict__ kk,
    float* __restrict__ vv, float* __restrict__ nres,
    float* __restrict__ agg)
{
    if (blockIdx.x >= 2 * NBLK) {
        int idx = (blockIdx.x - 2 * NBLK) * 512 + threadIdx.x;
        const int stride = ZBLK * 512;
        float4 z = make_float4(0.f, 0.f, 0.f, 0.f);
        for (int i = idx; i < NN * 32; i += stride)
            reinterpret_cast<float4*>(agg)[i] = z;
        return;
    }

    extern __shared__ char sm[];
    const int half = blockIdx.x / NBLK;
    const int tile = blockIdx.x % NBLK;
    const int m0 = tile * 128;
    const float* b1 = half ? bv : bq;
    const float* b2 = half ? bout : bk;
    float* Y1 = half ? vv : q;
    float* Y2 = half ? nres : kk;

    copy_weights_async(sm, half * 2, half * 2 + 1);
    copy_xn_async(sm, g_xnbf + (size_t)tile * 65536);
    asm volatile("cp.async.wait_group 0;");
    __syncthreads();

    float acc[2][8][4];
    mma_tile128(sm, acc);

    const int lane = threadIdx.x & 31;
    const int wid  = threadIdx.x >> 5;
    const int wm = wid & 3, wn = wid >> 2;
    const int g = lane >> 2, t2 = (lane & 3) * 2;

    const float* bias = (wn >= 2) ? b2 : b1;
    float* Y = (wn >= 2) ? Y2 : Y1;
    float2 bb[8];
    #pragma unroll
    for (int j = 0; j < 8; j++) {
        int colw = (wn & 1) * 64 + j * 8 + t2;
        bb[j] = *reinterpret_cast<const float2*>(&bias[colw]);
    }
    #pragma unroll
    for (int i = 0; i < 2; i++) {
        int rlo = m0 + wm * 32 + i * 16 + g;
        int rhi = rlo + 8;
        #pragma unroll
        for (int j = 0; j < 8; j++) {
            int colw = (wn & 1) * 64 + j * 8 + t2;
            if (rlo < NN) {
                float2 o = make_float2(acc[i][j][0] + bb[j].x, acc[i][j][1] + bb[j].y);
                *reinterpret_cast<float2*>(&Y[(size_t)rlo * 128 + colw]) = o;
            }
            if (rhi < NN) {
                float2 o = make_float2(acc[i][j][2] + bb[j].x, acc[i][j][3] + bb[j].y);
                *reinterpret_cast<float2*>(&Y[(size_t)rhi * 128 + colw]) = o;
            }
        }
    }
}

// ---------------------------------------------------------------------------
// Persistent fused edge kernel: weights resident, 64-edge tiles, X double-buffer
// ---------------------------------------------------------------------------
__global__ __launch_bounds__(512, 1) void edge_persist(
    const float* __restrict__ be, const float* __restrict__ bev,
    const int* __restrict__ src, const int* __restrict__ dst,
    const float* __restrict__ q, const float* __restrict__ k,
    const float* __restrict__ v,
    const float* __restrict__ ln_eg, const float* __restrict__ ln_eb,
    float* __restrict__ agg, float* __restrict__ y_out)
{
    extern __shared__ char sm[];
    float* P = reinterpret_cast<float*>(sm + EP);   // [64][132]

    const int lane = threadIdx.x & 31;
    const int wid  = threadIdx.x >> 5;
    const int wm = wid & 3, wn = wid >> 2;
    const int g = lane >> 2, t2 = (lane & 3) * 2;
    const int stride = gridDim.x;
    const unsigned FULL = 0xffffffffu;

    // prologue: weights (once) + first X tile, one cp.async group
    copy_weights_async(sm, 4, 5);
    copy_xe_async(sm, 0, g_xebf + (size_t)blockIdx.x * 32768);
    asm volatile("cp.async.commit_group;");

    // loop-invariant params
    const float* bias = (wn >= 2) ? bev : be;
    float2 bb[8];
    #pragma unroll
    for (int j = 0; j < 8; j++) {
        int colw = (wn & 1) * 64 + j * 8 + t2;
        bb[j] = *reinterpret_cast<const float2*>(&bias[colw]);
    }
    float4 ge = *reinterpret_cast<const float4*>(&ln_eg[4 * lane]);
    float4 gb = *reinterpret_cast<const float4*>(&ln_eb[4 * lane]);

    int cur = 0;
    for (int t = blockIdx.x; t < ETILES; t += stride) {
        int tn = t + stride;
        if (tn < ETILES) {
            copy_xe_async(sm, cur ^ 1, g_xebf + (size_t)tn * 32768);
            asm volatile("cp.async.commit_group;");
            asm volatile("cp.async.wait_group 1;");
        } else {
            asm volatile("cp.async.wait_group 0;");
        }
        __syncthreads();

        const int e0 = t * 64;
        // warp's 4 edges: lanes 0-3 src, lanes 4-7 dst
        int sd = 0;
        if (lane < 8)
            sd = __ldg(((lane < 4) ? src : dst) + e0 + wid * 4 + (lane & 3));

        float acc[8][4];
        mma_tile64(sm, cur, acc);
        __syncthreads();

        // Phase A: eproj + be -> P (warps wn<2)
        if (wn < 2) {
            int rlo = wm * 16 + g;
            int rhi = rlo + 8;
            #pragma unroll
            for (int j = 0; j < 8; j++) {
                int colw = (wn & 1) * 64 + j * 8 + t2;
                P[rlo * 132 + colw]     = acc[j][0] + bb[j].x;
                P[rlo * 132 + colw + 1] = acc[j][1] + bb[j].y;
                P[rhi * 132 + colw]     = acc[j][2] + bb[j].x;
                P[rhi * 132 + colw + 1] = acc[j][3] + bb[j].y;
            }
        }
        __syncthreads();

        // Phase B: 4 edges per warp. Gathers batched up front (MLP).
        {
            int s[4], d[4];
            #pragma unroll
            for (int e = 0; e < 4; e++) {
                s[e] = __shfl_sync(FULL, sd, e);
                d[e] = __shfl_sync(FULL, sd, e + 4);
            }
            float4 Q[4], K[4];
            #pragma unroll
            for (int e = 0; e < 4; e++) {
                Q[e] = __ldg(reinterpret_cast<const float4*>(&q[(size_t)s[e] * 128 + 4 * lane]));
                K[e] = __ldg(reinterpret_cast<const float4*>(&k[(size_t)d[e] * 128 + 4 * lane]));
            }
            #pragma unroll
            for (int e = 0; e < 4; e++) {
                float4 v4 = __ldg(reinterpret_cast<const float4*>(&v[(size_t)s[e] * 128 + 4 * lane]));
                int row = wid * 4 + e;

                float pd = Q[e].x * K[e].x + Q[e].y * K[e].y
                         + Q[e].z * K[e].z + Q[e].w * K[e].w;
                pd += __shfl_xor_sync(FULL, pd, 1);
                pd += __shfl_xor_sync(FULL, pd, 2);
                pd += __shfl_xor_sync(FULL, pd, 4);

                float4 m4 = *reinterpret_cast<const float4*>(&P[row * 132 + 4 * lane]);
                m4.x = fmaf(pd, INV_SCALE, m4.x);
                m4.y = fmaf(pd, INV_SCALE, m4.y);
                m4.z = fmaf(pd, INV_SCALE, m4.z);
                m4.w = fmaf(pd, INV_SCALE, m4.w);

                // softmax over 4 heads: partners at lane^8, lane^16
                float4 mx = m4;
                #pragma unroll
                for (int off = 8; off <= 16; off <<= 1) {
                    mx.x = fmaxf(mx.x, __shfl_xor_sync(FULL, mx.x, off));
                    mx.y = fmaxf(mx.y, __shfl_xor_sync(FULL, mx.y, off));
                    mx.z = fmaxf(mx.z, __shfl_xor_sync(FULL, mx.z, off));
                    mx.w = fmaxf(mx.w, __shfl_xor_sync(FULL, mx.w, off));
                }
                float4 ex;
                ex.x = __expf(m4.x - mx.x); ex.y = __expf(m4.y - mx.y);
                ex.z = __expf(m4.z - mx.z); ex.w = __expf(m4.w - mx.w);
                float4 sx = ex;
                #pragma unroll
                for (int off = 8; off <= 16; off <<= 1) {
                    sx.x += __shfl_xor_sync(FULL, sx.x, off);
                    sx.y += __shfl_xor_sync(FULL, sx.y, off);
                    sx.z += __shfl_xor_sync(FULL, sx.z, off);
                    sx.w += __shfl_xor_sync(FULL, sx.w, off);
                }
                float4 msg;
                msg.x = v4.x * ex.x / sx.x;
                msg.y = v4.y * ex.y / sx.y;
                msg.z = v4.z * ex.z / sx.z;
                msg.w = v4.w * ex.w / sx.w;
                float* ap = &agg[(size_t)d[e] * 128 + 4 * lane];
                asm volatile("red.global.add.v4.f32 [%0], {%1, %2, %3, %4};"
                             :: "l"(ap), "f"(msg.x), "f"(msg.y), "f"(msg.z), "f"(msg.w)
                             : "memory");

                // layernorm over 128 cols
                float ls = m4.x + m4.y + m4.z + m4.w;
                float lq = m4.x * m4.x + m4.y * m4.y + m4.z * m4.z + m4.w * m4.w;
                #pragma unroll
                for (int off = 16; off > 0; off >>= 1) {
                    ls += __shfl_xor_sync(FULL, ls, off);
                    lq += __shfl_xor_sync(FULL, lq, off);
                }
                float mu = ls * (1.0f / 128.0f);
                float var = lq * (1.0f / 128.0f) - mu * mu;
                float rs = rsqrtf(var + LN_EPS);

                float t0 = fmaf((m4.x - mu) * rs, ge.x, gb.x);
                float t1 = fmaf((m4.y - mu) * rs, ge.y, gb.y);
                float t2f = fmaf((m4.z - mu) * rs, ge.z, gb.z);
                float t3 = fmaf((m4.w - mu) * rs, ge.w, gb.w);
                float4 sil;
                sil.x = t0 / (1.0f + __expf(-t0));
                sil.y = t1 / (1.0f + __expf(-t1));
                sil.z = t2f / (1.0f + __expf(-t2f));
                sil.w = t3 / (1.0f + __expf(-t3));
                *reinterpret_cast<float4*>(&P[row * 132 + 4 * lane]) = sil;
            }
        }
        __syncthreads();

        // Phase C: y = eres + bev + silu   (warps wn>=2)
        if (wn >= 2) {
            int rlo = wm * 16 + g;
            int rhi = rlo + 8;
            #pragma unroll
            for (int j = 0; j < 8; j++) {
                int colw = (wn & 1) * 64 + j * 8 + t2;
                float2 o0, o1;
                o0.x = acc[j][0] + bb[j].x + P[rlo * 132 + colw];
                o0.y = acc[j][1] + bb[j].y + P[rlo * 132 + colw + 1];
                o1.x = acc[j][2] + bb[j].x + P[rhi * 132 + colw];
                o1.y = acc[j][3] + bb[j].y + P[rhi * 132 + colw + 1];
                *reinterpret_cast<float2*>(&y_out[(size_t)(e0 + rlo) * 128 + colw]) = o0;
                *reinterpret_cast<float2*>(&y_out[(size_t)(e0 + rhi) * 128 + colw]) = o1;
            }
        }
        cur ^= 1;
    }
}

// ---------------------------------------------------------------------------
// Node finalize: x = node_res + silu(LN_128(agg)), float4 lanes
// ---------------------------------------------------------------------------
__global__ __launch_bounds__(256) void node_kernel(
    const float* __restrict__ agg, const float* __restrict__ nres,
    const float* __restrict__ ln_ng, const float* __restrict__ ln_nb,
    float* __restrict__ x_out)
{
    int node = (blockIdx.x * blockDim.x + threadIdx.x) >> 5;
    int lane = threadIdx.x & 31;
    if (node >= NN) return;
    const unsigned FULL = 0xffffffffu;

    size_t base = (size_t)node * 128 + 4 * lane;
    float4 a = __ldg(reinterpret_cast<const float4*>(&agg[base]));

    float ls = a.x + a.y + a.z + a.w;
    float lq = a.x * a.x + a.y * a.y + a.z * a.z + a.w * a.w;
    #pragma unroll
    for (int off = 16; off > 0; off >>= 1) {
        ls += __shfl_xor_sync(FULL, ls, off);
        lq += __shfl_xor_sync(FULL, lq, off);
    }
    float mu  = ls * (1.0f / 128.0f);
    float var = lq * (1.0f / 128.0f) - mu * mu;
    float rs  = rsqrtf(var + LN_EPS);

    float4 g = __ldg(reinterpret_cast<const float4*>(&ln_ng[4 * lane]));
    float4 b = __ldg(reinterpret_cast<const float4*>(&ln_nb[4 * lane]));
    float4 r = __ldg(reinterpret_cast<const float4*>(&nres[base]));

    float t0 = fmaf((a.x - mu) * rs, g.x, b.x);
    float t1 = fmaf((a.y - mu) * rs, g.y, b.y);
    float t2 = fmaf((a.z - mu) * rs, g.z, b.z);
    float t3 = fmaf((a.w - mu) * rs, g.w, b.w);
    float4 o;
    o.x = t0 / (1.0f + __expf(-t0)) + r.x;
    o.y = t1 / (1.0f + __expf(-t1)) + r.y;
    o.z = t2 / (1.0f + __expf(-t2)) + r.z;
    o.w = t3 / (1.0f + __expf(-t3)) + r.w;
    *reinterpret_cast<float4*>(&x_out[base]) = o;
}

// ---------------------------------------------------------------------------
// Launch
// ---------------------------------------------------------------------------
extern "C" void kernel_launch(void* const* d_in, const int* in_sizes, int n_in,
                              void* d_out, int out_size)
{
    const float* node_feats = (const float*)d_in[0];
    const float* edge_feats = (const float*)d_in[1];
    const int*   src        = (const int*)d_in[2];
    const int*   dst        = (const int*)d_in[3];
    const float* Wq   = (const float*)d_in[4];
    const float* bq   = (const float*)d_in[5];
    const float* Wk   = (const float*)d_in[6];
    const float* bk   = (const float*)d_in[7];
    const float* Wv   = (const float*)d_in[8];
    const float* bv   = (const float*)d_in[9];
    const float* We   = (const float*)d_in[10];
    const float* be   = (const float*)d_in[11];
    const float* Wev  = (const float*)d_in[12];
    const float* bev  = (const float*)d_in[13];
    const float* Wout = (const float*)d_in[14];
    const float* bout = (const float*)d_in[15];
    const float* ln_ng = (const float*)d_in[16];
    const float* ln_nb = (const float*)d_in[17];
    const float* ln_eg = (const float*)d_in[18];
    const float* ln_eb = (const float*)d_in[19];

    float* scratch = nullptr;
    cudaGetSymbolAddress((void**)&scratch, g_scratch);
    float* q    = scratch;
    float* kk   = q    + (size_t)NN * 128;
    float* vv   = kk   + (size_t)NN * 128;
    float* nres = vv   + (size_t)NN * 128;
    float* agg  = nres + (size_t)NN * 128;

    float* x_out = (float*)d_out;
    float* y_out = x_out + (size_t)NN * 128;

    static bool attr_set = false;
    if (!attr_set) {
        cudaFuncSetAttribute(gemm_node, cudaFuncAttributeMaxDynamicSharedMemorySize, SMEM_GEMM);
        cudaFuncSetAttribute(edge_persist, cudaFuncAttributeMaxDynamicSharedMemorySize, SMEM_EDGE_P);
        attr_set = true;
    }

    int nsm = 148;
    cudaDeviceGetAttribute(&nsm, cudaDevAttrMultiProcessorCount, 0);
    if (nsm > ETILES) nsm = ETILES;

    // launch order: 0 prep_w, 1 preconv, 2 gemm_node, 3 edge_persist, 4 node
    prep_w<<<6, 256>>>(Wq, Wk, Wv, Wout, We, Wev);
    preconv<<<NBLK + ETILES, 256>>>(node_feats, edge_feats);
    gemm_node<<<2 * NBLK + ZBLK, 512, SMEM_GEMM>>>(
        bq, bk, bv, bout, q, kk, vv, nres, agg);
    edge_persist<<<nsm, 512, SMEM_EDGE_P>>>(
        be, bev, src, dst, q, kk, vv, ln_eg, ln_eb, agg, y_out);
    node_kernel<<<NN / 8, 256>>>(agg, nres, ln_ng, ln_nb, x_out);
}

// round 9
// speedup vs baseline: 1.4025x; 1.2035x over previous
#include <cuda_runtime.h>
#include <cuda_bf16.h>
#include <math.h>
#include <stdint.h>

#define NN 50000
#define EE 400000
#define NBLK 391            // ceil(NN/128) node tiles
#define ETILES 6250         // EE/64 edge tiles
#define INV_SCALE 0.17677669529663687f   // 1/sqrt(32)
#define LN_EPS 1e-5f

// Scratch: q, k, v, nres, agg (5*N*128 = 32M floats)
__device__ float g_scratch[32000000];
// bf16 hi/lo swizzled weight tiles: 6 weights x (32KB hi + 32KB lo)
__device__ __align__(256) unsigned char g_wbf[6 * 65536];

// ---- node gemm smem layout ----
#define SW1HI 0
#define SW2HI 65536
#define SXHI  131072
#define SMEM_GEMM 196608
// ---- edge persistent smem layout: W 128KB + per-half 32KB X/P buffer ----
#define EXB0  131072
#define SMEM_EDGE 196608

// Swizzled byte offset in a K-major bf16 tile (256B rows, 16B chunks,
// chunk ^= row&7 -> conflict-free for row-parallel and k-parallel access).
__device__ __forceinline__ int sw_off(int row, int col) {
    return row * 256 + ((((col >> 3) ^ (row & 7)) & 15) << 4) + (col & 7) * 2;
}

__device__ __forceinline__ uint32_t smem_u32(const void* p) {
    uint32_t a;
    asm("{ .reg .u64 t; cvta.to.shared.u64 t, %1; cvt.u32.u64 %0, t; }"
        : "=r"(a) : "l"(p));
    return a;
}

__device__ __forceinline__ void hmma(float* c, uint32_t a0, uint32_t a1,
                                     uint32_t a2, uint32_t a3,
                                     uint32_t b0, uint32_t b1) {
    asm("mma.sync.aligned.m16n8k16.row.col.f32.bf16.bf16.f32 "
        "{%0,%1,%2,%3}, {%4,%5,%6,%7}, {%8,%9}, {%0,%1,%2,%3};"
        : "+f"(c[0]), "+f"(c[1]), "+f"(c[2]), "+f"(c[3])
        : "r"(a0), "r"(a1), "r"(a2), "r"(a3), "r"(b0), "r"(b1));
}

__device__ __forceinline__ uint32_t pack_bf16x2(float a, float b) {
    uint32_t r;
    asm("cvt.rn.bf16x2.f32 %0, %1, %2;" : "=r"(r) : "f"(b), "f"(a));
    return r;
}

#define BARH(id) asm volatile("bar.sync %0, 256;" :: "r"(id) : "memory")

// ---------------------------------------------------------------------------
// Weight prep: split 6 weights into bf16 hi(trunc)/lo swizzled tiles
// ---------------------------------------------------------------------------
__global__ void prep_w(const float* __restrict__ W0, const float* __restrict__ W1,
                       const float* __restrict__ W2, const float* __restrict__ W3,
                       const float* __restrict__ W4, const float* __restrict__ W5)
{
    const float* W;
    switch (blockIdx.x) {
        case 0: W = W0; break; case 1: W = W1; break; case 2: W = W2; break;
        case 3: W = W3; break; case 4: W = W4; break; default: W = W5; break;
    }
    unsigned char* out = g_wbf + (size_t)blockIdx.x * 65536;
    for (int idx = threadIdx.x; idx < 16384; idx += blockDim.x) {
        int row = idx >> 7, col = idx & 127;
        float x = W[idx];
        uint32_t xu = __float_as_uint(x);
        uint32_t hi = xu & 0xffff0000u;
        float lo = x - __uint_as_float(hi);
        __nv_bfloat16 lb = __float2bfloat16(lo);
        int off = sw_off(row, col);
        *reinterpret_cast<uint16_t*>(out + off) = (uint16_t)(hi >> 16);
        *reinterpret_cast<__nv_bfloat16*>(out + 32768 + off) = lb;
    }
}

// ---------------------------------------------------------------------------
// Zero agg buffer
// ---------------------------------------------------------------------------
__global__ void zero_kernel(float* __restrict__ p)
{
    int i = blockIdx.x * blockDim.x + threadIdx.x;
    reinterpret_cast<float4*>(p)[i] = make_float4(0.f, 0.f, 0.f, 0.f);
}

// ---------------------------------------------------------------------------
// cp.async weight staging (no commit — caller commits)
// ---------------------------------------------------------------------------
__device__ __forceinline__ void copy_weights_async(char* sm, int w1idx, int w2idx) {
    uint32_t d1 = smem_u32(sm + SW1HI);
    uint32_t d2 = smem_u32(sm + SW2HI);
    const char* s1 = reinterpret_cast<const char*>(g_wbf + (size_t)w1idx * 65536);
    const char* s2 = reinterpret_cast<const char*>(g_wbf + (size_t)w2idx * 65536);
    int tid = threadIdx.x;
    #pragma unroll
    for (int i = 0; i < 8; i++) {
        int j = (tid + i * 512) * 16;
        asm volatile("cp.async.cg.shared.global [%0], [%1], 16;"
                     :: "r"(d1 + j), "l"(s1 + j));
        asm volatile("cp.async.cg.shared.global [%0], [%1], 16;"
                     :: "r"(d2 + j), "l"(s2 + j));
    }
}

// ---------------------------------------------------------------------------
// Node-side convert: 128-row tile of X fp32 -> swizzled hi/lo bf16 in smem
// (512 threads)
// ---------------------------------------------------------------------------
__device__ __forceinline__ void convert_x128(char* sm, const float* __restrict__ X,
                                             int m0, int M) {
    int tid = threadIdx.x;
    int r = tid >> 2;
    int ch = (tid & 3) * 32;
    bool valid = (m0 + r) < M;
    const float* xp = X + (size_t)(m0 + r) * 128 + ch;
    #pragma unroll
    for (int u = 0; u < 8; u++) {
        int c = ch + u * 4;
        float4 xv = make_float4(0.f, 0.f, 0.f, 0.f);
        if (valid) xv = __ldg(reinterpret_cast<const float4*>(xp + u * 4));
        uint32_t u0 = __float_as_uint(xv.x), u1 = __float_as_uint(xv.y);
        uint32_t u2 = __float_as_uint(xv.z), u3 = __float_as_uint(xv.w);
        uint32_t h01 = __byte_perm(u0, u1, 0x7632);
        uint32_t h23 = __byte_perm(u2, u3, 0x7632);
        float l0 = xv.x - __uint_as_float(u0 & 0xffff0000u);
        float l1 = xv.y - __uint_as_float(u1 & 0xffff0000u);
        float l2 = xv.z - __uint_as_float(u2 & 0xffff0000u);
        float l3 = xv.w - __uint_as_float(u3 & 0xffff0000u);
        int off = sw_off(r, c);
        *reinterpret_cast<uint2*>(sm + SXHI + off) = make_uint2(h01, h23);
        *reinterpret_cast<uint2*>(sm + SXHI + 32768 + off) =
            make_uint2(pack_bf16x2(l0, l1), pack_bf16x2(l2, l3));
    }
}

// Edge-side convert: 64-row tile into a half's 32KB buffer (256 threads/half)
__device__ __forceinline__ void convert_x64(char* xbuf, const float* __restrict__ X,
                                            int e0, int htid) {
    int r = htid >> 2;              // 0..63
    int ch = (htid & 3) * 32;
    const float* xp = X + (size_t)(e0 + r) * 128 + ch;
    #pragma unroll
    for (int u = 0; u < 8; u++) {
        int c = ch + u * 4;
        float4 xv = __ldg(reinterpret_cast<const float4*>(xp + u * 4));
        uint32_t u0 = __float_as_uint(xv.x), u1 = __float_as_uint(xv.y);
        uint32_t u2 = __float_as_uint(xv.z), u3 = __float_as_uint(xv.w);
        uint32_t h01 = __byte_perm(u0, u1, 0x7632);
        uint32_t h23 = __byte_perm(u2, u3, 0x7632);
        float l0 = xv.x - __uint_as_float(u0 & 0xffff0000u);
        float l1 = xv.y - __uint_as_float(u1 & 0xffff0000u);
        float l2 = xv.z - __uint_as_float(u2 & 0xffff0000u);
        float l3 = xv.w - __uint_as_float(u3 & 0xffff0000u);
        int off = sw_off(r, c);     // < 16384 for r < 64
        *reinterpret_cast<uint2*>(xbuf + off) = make_uint2(h01, h23);
        *reinterpret_cast<uint2*>(xbuf + 16384 + off) =
            make_uint2(pack_bf16x2(l0, l1), pack_bf16x2(l2, l3));
    }
}

// ---------------------------------------------------------------------------
// Node MMA (16 warps, M=128): wm = wid&3 (32 rows), wn = wid>>2 (64 cols of 256)
// ---------------------------------------------------------------------------
__device__ __forceinline__ void mma_tile128(const char* sm, float acc[2][8][4]) {
    const int lane = threadIdx.x & 31;
    const int wid  = threadIdx.x >> 5;
    const int wm = wid & 3, wn = wid >> 2;
    const int g  = lane >> 2;
    const int t4 = (lane & 3) * 4;

    const char* xhi = sm + SXHI;
    const char* xlo = sm + SXHI + 32768;
    const char* wh = sm + ((wn >= 2) ? SW2HI : SW1HI);
    const char* wl = wh + 32768;

    const int arow = (wm * 32 + g) * 256 + t4;
    const int brow = ((wn & 1) * 64 + g) * 256 + t4;

    #pragma unroll
    for (int i = 0; i < 2; i++)
        #pragma unroll
        for (int j = 0; j < 8; j++)
            #pragma unroll
            for (int r = 0; r < 4; r++) acc[i][j][r] = 0.f;

    #pragma unroll
    for (int ks = 0; ks < 8; ks++) {
        const int cx0 = (((2 * ks) ^ g) << 4);
        const int cx1 = (((2 * ks + 1) ^ g) << 4);
        uint32_t ah[2][4], al[2][4];
        #pragma unroll
        for (int i = 0; i < 2; i++) {
            int r0 = arow + i * 16 * 256;
            int r8 = r0 + 8 * 256;
            ah[i][0] = *reinterpret_cast<const uint32_t*>(xhi + r0 + cx0);
            ah[i][1] = *reinterpret_cast<const uint32_t*>(xhi + r8 + cx0);
            ah[i][2] = *reinterpret_cast<const uint32_t*>(xhi + r0 + cx1);
            ah[i][3] = *reinterpret_cast<const uint32_t*>(xhi + r8 + cx1);
            al[i][0] = *reinterpret_cast<const uint32_t*>(xlo + r0 + cx0);
            al[i][1] = *reinterpret_cast<const uint32_t*>(xlo + r8 + cx0);
            al[i][2] = *reinterpret_cast<const uint32_t*>(xlo + r0 + cx1);
            al[i][3] = *reinterpret_cast<const uint32_t*>(xlo + r8 + cx1);
        }
        #pragma unroll
        for (int j = 0; j < 8; j++) {
            int rb = brow + j * 8 * 256;
            uint32_t bh0 = *reinterpret_cast<const uint32_t*>(wh + rb + cx0);
            uint32_t bh1 = *reinterpret_cast<const uint32_t*>(wh + rb + cx1);
            uint32_t bl0 = *reinterpret_cast<const uint32_t*>(wl + rb + cx0);
            uint32_t bl1 = *reinterpret_cast<const uint32_t*>(wl + rb + cx1);
            #pragma unroll
            for (int i = 0; i < 2; i++) {
                hmma(acc[i][j], ah[i][0], ah[i][1], ah[i][2], ah[i][3], bh0, bh1);
                hmma(acc[i][j], al[i][0], al[i][1], al[i][2], al[i][3], bh0, bh1);
                hmma(acc[i][j], ah[i][0], ah[i][1], ah[i][2], ah[i][3], bl0, bl1);
            }
        }
    }
}

// Edge half-MMA (8 warps, M=64): wm = hw&1 (32 rows), wn = hw>>1 (64 cols of 256)
__device__ __forceinline__ void mma_tile64h(const char* sm, const char* xbuf,
                                            int wm, int wn, int g, int t4,
                                            float acc[2][8][4]) {
    const char* xhi = xbuf;
    const char* xlo = xbuf + 16384;
    const char* wh = sm + ((wn >= 2) ? SW2HI : SW1HI);
    const char* wl = wh + 32768;

    const int arow = (wm * 32 + g) * 256 + t4;
    const int brow = ((wn & 1) * 64 + g) * 256 + t4;

    #pragma unroll
    for (int i = 0; i < 2; i++)
        #pragma unroll
        for (int j = 0; j < 8; j++)
            #pragma unroll
            for (int r = 0; r < 4; r++) acc[i][j][r] = 0.f;

    #pragma unroll
    for (int ks = 0; ks < 8; ks++) {
        const int cx0 = (((2 * ks) ^ g) << 4);
        const int cx1 = (((2 * ks + 1) ^ g) << 4);
        uint32_t ah[2][4], al[2][4];
        #pragma unroll
        for (int i = 0; i < 2; i++) {
            int r0 = arow + i * 16 * 256;
            int r8 = r0 + 8 * 256;
            ah[i][0] = *reinterpret_cast<const uint32_t*>(xhi + r0 + cx0);
            ah[i][1] = *reinterpret_cast<const uint32_t*>(xhi + r8 + cx0);
            ah[i][2] = *reinterpret_cast<const uint32_t*>(xhi + r0 + cx1);
            ah[i][3] = *reinterpret_cast<const uint32_t*>(xhi + r8 + cx1);
            al[i][0] = *reinterpret_cast<const uint32_t*>(xlo + r0 + cx0);
            al[i][1] = *reinterpret_cast<const uint32_t*>(xlo + r8 + cx0);
            al[i][2] = *reinterpret_cast<const uint32_t*>(xlo + r0 + cx1);
            al[i][3] = *reinterpret_cast<const uint32_t*>(xlo + r8 + cx1);
        }
        #pragma unroll
        for (int j = 0; j < 8; j++) {
            int rb = brow + j * 8 * 256;
            uint32_t bh0 = *reinterpret_cast<const uint32_t*>(wh + rb + cx0);
            uint32_t bh1 = *reinterpret_cast<const uint32_t*>(wh + rb + cx1);
            uint32_t bl0 = *reinterpret_cast<const uint32_t*>(wl + rb + cx0);
            uint32_t bl1 = *reinterpret_cast<const uint32_t*>(wl + rb + cx1);
            #pragma unroll
            for (int i = 0; i < 2; i++) {
                hmma(acc[i][j], ah[i][0], ah[i][1], ah[i][2], ah[i][3], bh0, bh1);
                hmma(acc[i][j], al[i][0], al[i][1], al[i][2], al[i][3], bh0, bh1);
                hmma(acc[i][j], ah[i][0], ah[i][1], ah[i][2], ah[i][3], bl0, bl1);
            }
        }
    }
}

// ---------------------------------------------------------------------------
// Node GEMMs merged: half 0 -> (Wq,Wk)->(q,k), half 1 -> (Wv,Wout)->(v,nres)
// ---------------------------------------------------------------------------
__global__ __launch_bounds__(512, 1) void gemm_node(
    const float* __restrict__ X,
    const float* __restrict__ bq, const float* __restrict__ bk,
    const float* __restrict__ bv, const float* __restrict__ bout,
    float* __restrict__ q, float* __restrict__ kk,
    float* __restrict__ vv, float* __restrict__ nres)
{
    extern __shared__ char sm[];
    const int half = blockIdx.x / NBLK;
    const int tile = blockIdx.x % NBLK;
    const int m0 = tile * 128;
    const float* b1 = half ? bv : bq;
    const float* b2 = half ? bout : bk;
    float* Y1 = half ? vv : q;
    float* Y2 = half ? nres : kk;

    copy_weights_async(sm, half * 2, half * 2 + 1);
    asm volatile("cp.async.commit_group;");
    convert_x128(sm, X, m0, NN);
    asm volatile("cp.async.wait_group 0;");
    __syncthreads();

    float acc[2][8][4];
    mma_tile128(sm, acc);

    const int lane = threadIdx.x & 31;
    const int wid  = threadIdx.x >> 5;
    const int wm = wid & 3, wn = wid >> 2;
    const int g = lane >> 2, t2 = (lane & 3) * 2;

    const float* bias = (wn >= 2) ? b2 : b1;
    float* Y = (wn >= 2) ? Y2 : Y1;
    float2 bb[8];
    #pragma unroll
    for (int j = 0; j < 8; j++) {
        int colw = (wn & 1) * 64 + j * 8 + t2;
        bb[j] = *reinterpret_cast<const float2*>(&bias[colw]);
    }
    #pragma unroll
    for (int i = 0; i < 2; i++) {
        int rlo = m0 + wm * 32 + i * 16 + g;
        int rhi = rlo + 8;
        #pragma unroll
        for (int j = 0; j < 8; j++) {
            int colw = (wn & 1) * 64 + j * 8 + t2;
            if (rlo < NN) {
                float2 o = make_float2(acc[i][j][0] + bb[j].x, acc[i][j][1] + bb[j].y);
                *reinterpret_cast<float2*>(&Y[(size_t)rlo * 128 + colw]) = o;
            }
            if (rhi < NN) {
                float2 o = make_float2(acc[i][j][2] + bb[j].x, acc[i][j][3] + bb[j].y);
                *reinterpret_cast<float2*>(&Y[(size_t)rhi * 128 + colw]) = o;
            }
        }
    }
}

// ---------------------------------------------------------------------------
// Persistent edge kernel: two independent 256-thread halves per CTA, each
// pipelining its own 64-edge tiles with named barriers. Weights resident.
// Per half: 32KB X buffer (hi 16K + lo 16K) aliased by P[64][128] after MMA.
// ---------------------------------------------------------------------------
__global__ __launch_bounds__(512, 1) void edge_persist(
    const float* __restrict__ edge_feats,
    const float* __restrict__ be, const float* __restrict__ bev,
    const int* __restrict__ src, const int* __restrict__ dst,
    const float* __restrict__ q, const float* __restrict__ k,
    const float* __restrict__ v,
    const float* __restrict__ ln_eg, const float* __restrict__ ln_eb,
    float* __restrict__ agg, float* __restrict__ y_out)
{
    extern __shared__ char sm[];
    const int tid  = threadIdx.x;
    const int lane = tid & 31;
    const int wid  = tid >> 5;
    const int h    = wid >> 3;          // half 0/1
    const int hw   = wid & 7;           // warp within half
    const int htid = tid & 255;
    const int wm = hw & 1, wn = hw >> 1;
    const int g = lane >> 2, t2 = (lane & 3) * 2, t4 = (lane & 3) * 4;
    const int barid = 1 + h;
    const unsigned FULL = 0xffffffffu;

    char* xbuf = sm + EXB0 + h * 32768;
    float* P = reinterpret_cast<float*>(xbuf);   // [64][128], aliases X

    const int tstride = gridDim.x * 2;
    int t = blockIdx.x * 2 + h;

    // prologue: weights via cp.async + first tile converted directly
    copy_weights_async(sm, 4, 5);
    asm volatile("cp.async.commit_group;");
    if (t < ETILES) convert_x64(xbuf, edge_feats, t * 64, htid);
    asm volatile("cp.async.wait_group 0;");
    __syncthreads();

    // loop-invariant params
    const float* bias = (wn >= 2) ? bev : be;
    float2 bb[8];
    #pragma unroll
    for (int j = 0; j < 8; j++) {
        int colw = (wn & 1) * 64 + j * 8 + t2;
        bb[j] = *reinterpret_cast<const float2*>(&bias[colw]);
    }
    float4 ge = *reinterpret_cast<const float4*>(&ln_eg[4 * lane]);
    float4 gb = *reinterpret_cast<const float4*>(&ln_eb[4 * lane]);

    for (; t < ETILES; ) {
        const int e0 = t * 64;
        // preload this warp's 8 edges' indices (lanes 0-7 src, 8-15 dst)
        int sd = 0;
        if (lane < 16)
            sd = __ldg(((lane < 8) ? src : dst) + e0 + hw * 8 + (lane & 7));

        float acc[2][8][4];
        mma_tile64h(sm, xbuf, wm, wn, g, t4, acc);
        BARH(barid);             // all X reads done -> P may overwrite

        // Phase A: eproj + be -> P (warps wn<2)
        if (wn < 2) {
            #pragma unroll
            for (int i = 0; i < 2; i++) {
                int rlo = wm * 32 + i * 16 + g;
                int rhi = rlo + 8;
                #pragma unroll
                for (int j = 0; j < 8; j++) {
                    int colw = (wn & 1) * 64 + j * 8 + t2;
                    P[rlo * 128 + colw]     = acc[i][j][0] + bb[j].x;
                    P[rlo * 128 + colw + 1] = acc[i][j][1] + bb[j].y;
                    P[rhi * 128 + colw]     = acc[i][j][2] + bb[j].x;
                    P[rhi * 128 + colw + 1] = acc[i][j][3] + bb[j].y;
                }
            }
        }
        BARH(barid);

        // Phase B: 8 edges per warp; lane owns 4 consecutive cols
        {
            int s = __shfl_sync(FULL, sd, 0);
            int d = __shfl_sync(FULL, sd, 8);
            float4 q4 = __ldg(reinterpret_cast<const float4*>(&q[(size_t)s * 128 + 4 * lane]));
            float4 k4 = __ldg(reinterpret_cast<const float4*>(&k[(size_t)d * 128 + 4 * lane]));
            float4 v4 = __ldg(reinterpret_cast<const float4*>(&v[(size_t)s * 128 + 4 * lane]));

            #pragma unroll 1
            for (int it = 0; it < 8; it++) {
                int sn = 0, dn = 0;
                float4 qn, kn, vn;
                if (it < 7) {
                    sn = __shfl_sync(FULL, sd, it + 1);
                    dn = __shfl_sync(FULL, sd, it + 9);
                    qn = __ldg(reinterpret_cast<const float4*>(&q[(size_t)sn * 128 + 4 * lane]));
                    kn = __ldg(reinterpret_cast<const float4*>(&k[(size_t)dn * 128 + 4 * lane]));
                    vn = __ldg(reinterpret_cast<const float4*>(&v[(size_t)sn * 128 + 4 * lane]));
                }

                int row = hw * 8 + it;
                float pd = q4.x * k4.x + q4.y * k4.y + q4.z * k4.z + q4.w * k4.w;
                pd += __shfl_xor_sync(FULL, pd, 1);
                pd += __shfl_xor_sync(FULL, pd, 2);
                pd += __shfl_xor_sync(FULL, pd, 4);

                float4 m4 = *reinterpret_cast<const float4*>(&P[row * 128 + 4 * lane]);
                m4.x = fmaf(pd, INV_SCALE, m4.x);
                m4.y = fmaf(pd, INV_SCALE, m4.y);
                m4.z = fmaf(pd, INV_SCALE, m4.z);
                m4.w = fmaf(pd, INV_SCALE, m4.w);

                // softmax over 4 heads: partners at lane^8, lane^16
                float4 mx = m4;
                #pragma unroll
                for (int off = 8; off <= 16; off <<= 1) {
                    mx.x = fmaxf(mx.x, __shfl_xor_sync(FULL, mx.x, off));
                    mx.y = fmaxf(mx.y, __shfl_xor_sync(FULL, mx.y, off));
                    mx.z = fmaxf(mx.z, __shfl_xor_sync(FULL, mx.z, off));
                    mx.w = fmaxf(mx.w, __shfl_xor_sync(FULL, mx.w, off));
                }
                float4 ex;
                ex.x = __expf(m4.x - mx.x); ex.y = __expf(m4.y - mx.y);
                ex.z = __expf(m4.z - mx.z); ex.w = __expf(m4.w - mx.w);
                float4 sx = ex;
                #pragma unroll
                for (int off = 8; off <= 16; off <<= 1) {
                    sx.x += __shfl_xor_sync(FULL, sx.x, off);
                    sx.y += __shfl_xor_sync(FULL, sx.y, off);
                    sx.z += __shfl_xor_sync(FULL, sx.z, off);
                    sx.w += __shfl_xor_sync(FULL, sx.w, off);
                }
                float4 msg;
                msg.x = v4.x * ex.x / sx.x;
                msg.y = v4.y * ex.y / sx.y;
                msg.z = v4.z * ex.z / sx.z;
                msg.w = v4.w * ex.w / sx.w;
                float* ap = &agg[(size_t)d * 128 + 4 * lane];
                asm volatile("red.global.add.v4.f32 [%0], {%1, %2, %3, %4};"
                             :: "l"(ap), "f"(msg.x), "f"(msg.y), "f"(msg.z), "f"(msg.w)
                             : "memory");

                // layernorm over 128 cols
                float ls = m4.x + m4.y + m4.z + m4.w;
                float lq = m4.x * m4.x + m4.y * m4.y + m4.z * m4.z + m4.w * m4.w;
                #pragma unroll
                for (int off = 16; off > 0; off >>= 1) {
                    ls += __shfl_xor_sync(FULL, ls, off);
                    lq += __shfl_xor_sync(FULL, lq, off);
                }
                float mu = ls * (1.0f / 128.0f);
                float var = lq * (1.0f / 128.0f) - mu * mu;
                float rs = rsqrtf(var + LN_EPS);

                float t0 = fmaf((m4.x - mu) * rs, ge.x, gb.x);
                float t1 = fmaf((m4.y - mu) * rs, ge.y, gb.y);
                float t2f = fmaf((m4.z - mu) * rs, ge.z, gb.z);
                float t3 = fmaf((m4.w - mu) * rs, ge.w, gb.w);
                float4 sil;
                sil.x = t0 / (1.0f + __expf(-t0));
                sil.y = t1 / (1.0f + __expf(-t1));
                sil.z = t2f / (1.0f + __expf(-t2f));
                sil.w = t3 / (1.0f + __expf(-t3));
                *reinterpret_cast<float4*>(&P[row * 128 + 4 * lane]) = sil;

                s = sn; d = dn; q4 = qn; k4 = kn; v4 = vn;
            }
        }
        BARH(barid);

        // Phase C: y = eres + bev + silu (warps wn>=2 hold the Wev product)
        if (wn >= 2) {
            #pragma unroll
            for (int i = 0; i < 2; i++) {
                int rlo = wm * 32 + i * 16 + g;
                int rhi = rlo + 8;
                #pragma unroll
                for (int j = 0; j < 8; j++) {
                    int colw = (wn & 1) * 64 + j * 8 + t2;
                    float2 o0, o1;
                    o0.x = acc[i][j][0] + bb[j].x + P[rlo * 128 + colw];
                    o0.y = acc[i][j][1] + bb[j].y + P[rlo * 128 + colw + 1];
                    o1.x = acc[i][j][2] + bb[j].x + P[rhi * 128 + colw];
                    o1.y = acc[i][j][3] + bb[j].y + P[rhi * 128 + colw + 1];
                    *reinterpret_cast<float2*>(&y_out[(size_t)(e0 + rlo) * 128 + colw]) = o0;
                    *reinterpret_cast<float2*>(&y_out[(size_t)(e0 + rhi) * 128 + colw]) = o1;
                }
            }
        }
        t += tstride;
        BARH(barid);             // P reads done -> buffer free for next convert

        if (t < ETILES) convert_x64(xbuf, edge_feats, t * 64, htid);
        BARH(barid);             // convert visible to all warps of the half
    }
}

// ---------------------------------------------------------------------------
// Node finalize: x = node_res + silu(LN_128(agg)), float4 lanes
// ---------------------------------------------------------------------------
__global__ __launch_bounds__(256) void node_kernel(
    const float* __restrict__ agg, const float* __restrict__ nres,
    const float* __restrict__ ln_ng, const float* __restrict__ ln_nb,
    float* __restrict__ x_out)
{
    int node = (blockIdx.x * blockDim.x + threadIdx.x) >> 5;
    int lane = threadIdx.x & 31;
    if (node >= NN) return;
    const unsigned FULL = 0xffffffffu;

    size_t base = (size_t)node * 128 + 4 * lane;
    float4 a = __ldg(reinterpret_cast<const float4*>(&agg[base]));

    float ls = a.x + a.y + a.z + a.w;
    float lq = a.x * a.x + a.y * a.y + a.z * a.z + a.w * a.w;
    #pragma unroll
    for (int off = 16; off > 0; off >>= 1) {
        ls += __shfl_xor_sync(FULL, ls, off);
        lq += __shfl_xor_sync(FULL, lq, off);
    }
    float mu  = ls * (1.0f / 128.0f);
    float var = lq * (1.0f / 128.0f) - mu * mu;
    float rs  = rsqrtf(var + LN_EPS);

    float4 g = __ldg(reinterpret_cast<const float4*>(&ln_ng[4 * lane]));
    float4 b = __ldg(reinterpret_cast<const float4*>(&ln_nb[4 * lane]));
    float4 r = __ldg(reinterpret_cast<const float4*>(&nres[base]));

    float t0 = fmaf((a.x - mu) * rs, g.x, b.x);
    float t1 = fmaf((a.y - mu) * rs, g.y, b.y);
    float t2 = fmaf((a.z - mu) * rs, g.z, b.z);
    float t3 = fmaf((a.w - mu) * rs, g.w, b.w);
    float4 o;
    o.x = t0 / (1.0f + __expf(-t0)) + r.x;
    o.y = t1 / (1.0f + __expf(-t1)) + r.y;
    o.z = t2 / (1.0f + __expf(-t2)) + r.z;
    o.w = t3 / (1.0f + __expf(-t3)) + r.w;
    *reinterpret_cast<float4*>(&x_out[base]) = o;
}

// ---------------------------------------------------------------------------
// Launch
// ---------------------------------------------------------------------------
extern "C" void kernel_launch(void* const* d_in, const int* in_sizes, int n_in,
                              void* d_out, int out_size)
{
    const float* node_feats = (const float*)d_in[0];
    const float* edge_feats = (const float*)d_in[1];
    const int*   src        = (const int*)d_in[2];
    const int*   dst        = (const int*)d_in[3];
    const float* Wq   = (const float*)d_in[4];
    const float* bq   = (const float*)d_in[5];
    const float* Wk   = (const float*)d_in[6];
    const float* bk   = (const float*)d_in[7];
    const float* Wv   = (const float*)d_in[8];
    const float* bv   = (const float*)d_in[9];
    const float* We   = (const float*)d_in[10];
    const float* be   = (const float*)d_in[11];
    const float* Wev  = (const float*)d_in[12];
    const float* bev  = (const float*)d_in[13];
    const float* Wout = (const float*)d_in[14];
    const float* bout = (const float*)d_in[15];
    const float* ln_ng = (const float*)d_in[16];
    const float* ln_nb = (const float*)d_in[17];
    const float* ln_eg = (const float*)d_in[18];
    const float* ln_eb = (const float*)d_in[19];

    float* scratch = nullptr;
    cudaGetSymbolAddress((void**)&scratch, g_scratch);
    float* q    = scratch;
    float* kk   = q    + (size_t)NN * 128;
    float* vv   = kk   + (size_t)NN * 128;
    float* nres = vv   + (size_t)NN * 128;
    float* agg  = nres + (size_t)NN * 128;

    float* x_out = (float*)d_out;
    float* y_out = x_out + (size_t)NN * 128;

    static bool attr_set = false;
    if (!attr_set) {
        cudaFuncSetAttribute(gemm_node, cudaFuncAttributeMaxDynamicSharedMemorySize, SMEM_GEMM);
        cudaFuncSetAttribute(edge_persist, cudaFuncAttributeMaxDynamicSharedMemorySize, SMEM_EDGE);
        attr_set = true;
    }

    int nsm = 148;
    cudaDeviceGetAttribute(&nsm, cudaDevAttrMultiProcessorCount, 0);

    // launch order: 0 prep_w, 1 zero, 2 gemm_node, 3 edge_persist, 4 node
    prep_w<<<6, 256>>>(Wq, Wk, Wv, Wout, We, Wev);
    zero_kernel<<<NN * 32 / 256, 256>>>(agg);
    gemm_node<<<2 * NBLK, 512, SMEM_GEMM>>>(
        node_feats, bq, bk, bv, bout, q, kk, vv, nres);
    edge_persist<<<nsm, 512, SMEM_EDGE>>>(
        edge_feats, be, bev, src, dst, q, kk, vv, ln_eg, ln_eb, agg, y_out);
    node_kernel<<<NN / 8, 256>>>(agg, nres, ln_ng, ln_nb, x_out);
}

// round 10
// speedup vs baseline: 1.4534x; 1.0363x over previous
#include <cuda_runtime.h>
#include <cuda_bf16.h>
#include <math.h>
#include <stdint.h>

#define NN 50000
#define EE 400000
#define NBLK 391            // ceil(NN/128) node tiles
#define ETILES 6250         // EE/64 edge tiles
#define INV_SCALE 0.17677669529663687f   // 1/sqrt(32)
#define LN_EPS 1e-5f

// Scratch: q, k, v, nres, agg (5*N*128 = 32M floats)
__device__ float g_scratch[32000000];
// bf16 hi/lo swizzled weight tiles: 6 weights x (32KB hi + 32KB lo)
__device__ __align__(256) unsigned char g_wbf[6 * 65536];

// ---- node gemm smem layout ----
#define SW1HI 0
#define SW2HI 65536
#define SXHI  131072
#define SMEM_GEMM 196608
// ---- edge persistent smem layout: W 128KB + per-half 32KB X/P buffer ----
#define EXB0  131072
#define SMEM_EDGE 196608

// Swizzled byte offset in a K-major bf16 tile (256B rows, 16B chunks,
// chunk ^= row&7 -> conflict-free for row-parallel and k-parallel access).
__device__ __forceinline__ int sw_off(int row, int col) {
    return row * 256 + ((((col >> 3) ^ (row & 7)) & 15) << 4) + (col & 7) * 2;
}

__device__ __forceinline__ uint32_t smem_u32(const void* p) {
    uint32_t a;
    asm("{ .reg .u64 t; cvta.to.shared.u64 t, %1; cvt.u32.u64 %0, t; }"
        : "=r"(a) : "l"(p));
    return a;
}

__device__ __forceinline__ void hmma(float* c, uint32_t a0, uint32_t a1,
                                     uint32_t a2, uint32_t a3,
                                     uint32_t b0, uint32_t b1) {
    asm("mma.sync.aligned.m16n8k16.row.col.f32.bf16.bf16.f32 "
        "{%0,%1,%2,%3}, {%4,%5,%6,%7}, {%8,%9}, {%0,%1,%2,%3};"
        : "+f"(c[0]), "+f"(c[1]), "+f"(c[2]), "+f"(c[3])
        : "r"(a0), "r"(a1), "r"(a2), "r"(a3), "r"(b0), "r"(b1));
}

#define LDSM_X4(r0, r1, r2, r3, addr) \
    asm volatile("ldmatrix.sync.aligned.m8n8.x4.shared.b16 {%0,%1,%2,%3}, [%4];" \
        : "=r"(r0), "=r"(r1), "=r"(r2), "=r"(r3) : "r"(addr))

__device__ __forceinline__ uint32_t pack_bf16x2(float a, float b) {
    uint32_t r;
    asm("cvt.rn.bf16x2.f32 %0, %1, %2;" : "=r"(r) : "f"(b), "f"(a));
    return r;
}

#define BARH(id) asm volatile("bar.sync %0, 256;" :: "r"(id) : "memory")

// ---------------------------------------------------------------------------
// Weight prep: split 6 weights into bf16 hi(trunc)/lo swizzled tiles.
// 48 blocks: weight = bx>>3, row strip = bx&7 (16 rows each).
// ---------------------------------------------------------------------------
__global__ void prep_w(const float* __restrict__ W0, const float* __restrict__ W1,
                       const float* __restrict__ W2, const float* __restrict__ W3,
                       const float* __restrict__ W4, const float* __restrict__ W5)
{
    const float* W;
    switch (blockIdx.x >> 3) {
        case 0: W = W0; break; case 1: W = W1; break; case 2: W = W2; break;
        case 3: W = W3; break; case 4: W = W4; break; default: W = W5; break;
    }
    unsigned char* out = g_wbf + (size_t)(blockIdx.x >> 3) * 65536;
    int base = (blockIdx.x & 7) * 2048;
    for (int ii = threadIdx.x; ii < 2048; ii += blockDim.x) {
        int idx = base + ii;
        int row = idx >> 7, col = idx & 127;
        float x = W[idx];
        uint32_t xu = __float_as_uint(x);
        uint32_t hi = xu & 0xffff0000u;
        float lo = x - __uint_as_float(hi);
        __nv_bfloat16 lb = __float2bfloat16(lo);
        int off = sw_off(row, col);
        *reinterpret_cast<uint16_t*>(out + off) = (uint16_t)(hi >> 16);
        *reinterpret_cast<__nv_bfloat16*>(out + 32768 + off) = lb;
    }
}

// ---------------------------------------------------------------------------
// Zero agg buffer
// ---------------------------------------------------------------------------
__global__ void zero_kernel(float* __restrict__ p)
{
    int i = blockIdx.x * blockDim.x + threadIdx.x;
    reinterpret_cast<float4*>(p)[i] = make_float4(0.f, 0.f, 0.f, 0.f);
}

// ---------------------------------------------------------------------------
// cp.async weight staging (no commit — caller commits)
// ---------------------------------------------------------------------------
__device__ __forceinline__ void copy_weights_async(char* sm, int w1idx, int w2idx) {
    uint32_t d1 = smem_u32(sm + SW1HI);
    uint32_t d2 = smem_u32(sm + SW2HI);
    const char* s1 = reinterpret_cast<const char*>(g_wbf + (size_t)w1idx * 65536);
    const char* s2 = reinterpret_cast<const char*>(g_wbf + (size_t)w2idx * 65536);
    int tid = threadIdx.x;
    #pragma unroll
    for (int i = 0; i < 8; i++) {
        int j = (tid + i * 512) * 16;
        asm volatile("cp.async.cg.shared.global [%0], [%1], 16;"
                     :: "r"(d1 + j), "l"(s1 + j));
        asm volatile("cp.async.cg.shared.global [%0], [%1], 16;"
                     :: "r"(d2 + j), "l"(s2 + j));
    }
}

// ---------------------------------------------------------------------------
// Node-side convert: 128-row tile of X fp32 -> swizzled hi/lo bf16 in smem
// (512 threads)
// ---------------------------------------------------------------------------
__device__ __forceinline__ void convert_x128(char* sm, const float* __restrict__ X,
                                             int m0, int M) {
    int tid = threadIdx.x;
    int r = tid >> 2;
    int ch = (tid & 3) * 32;
    bool valid = (m0 + r) < M;
    const float* xp = X + (size_t)(m0 + r) * 128 + ch;
    #pragma unroll
    for (int u = 0; u < 8; u++) {
        int c = ch + u * 4;
        float4 xv = make_float4(0.f, 0.f, 0.f, 0.f);
        if (valid) xv = __ldg(reinterpret_cast<const float4*>(xp + u * 4));
        uint32_t u0 = __float_as_uint(xv.x), u1 = __float_as_uint(xv.y);
        uint32_t u2 = __float_as_uint(xv.z), u3 = __float_as_uint(xv.w);
        uint32_t h01 = __byte_perm(u0, u1, 0x7632);
        uint32_t h23 = __byte_perm(u2, u3, 0x7632);
        float l0 = xv.x - __uint_as_float(u0 & 0xffff0000u);
        float l1 = xv.y - __uint_as_float(u1 & 0xffff0000u);
        float l2 = xv.z - __uint_as_float(u2 & 0xffff0000u);
        float l3 = xv.w - __uint_as_float(u3 & 0xffff0000u);
        int off = sw_off(r, c);
        *reinterpret_cast<uint2*>(sm + SXHI + off) = make_uint2(h01, h23);
        *reinterpret_cast<uint2*>(sm + SXHI + 32768 + off) =
            make_uint2(pack_bf16x2(l0, l1), pack_bf16x2(l2, l3));
    }
}

// Edge-side convert: 64-row tile into a half's 32KB buffer (256 threads/half)
__device__ __forceinline__ void convert_x64(char* xbuf, const float* __restrict__ X,
                                            int e0, int htid) {
    int r = htid >> 2;              // 0..63
    int ch = (htid & 3) * 32;
    const float* xp = X + (size_t)(e0 + r) * 128 + ch;
    #pragma unroll
    for (int u = 0; u < 8; u++) {
        int c = ch + u * 4;
        float4 xv = __ldg(reinterpret_cast<const float4*>(xp + u * 4));
        uint32_t u0 = __float_as_uint(xv.x), u1 = __float_as_uint(xv.y);
        uint32_t u2 = __float_as_uint(xv.z), u3 = __float_as_uint(xv.w);
        uint32_t h01 = __byte_perm(u0, u1, 0x7632);
        uint32_t h23 = __byte_perm(u2, u3, 0x7632);
        float l0 = xv.x - __uint_as_float(u0 & 0xffff0000u);
        float l1 = xv.y - __uint_as_float(u1 & 0xffff0000u);
        float l2 = xv.z - __uint_as_float(u2 & 0xffff0000u);
        float l3 = xv.w - __uint_as_float(u3 & 0xffff0000u);
        int off = sw_off(r, c);     // < 16384 for r < 64
        *reinterpret_cast<uint2*>(xbuf + off) = make_uint2(h01, h23);
        *reinterpret_cast<uint2*>(xbuf + 16384 + off) =
            make_uint2(pack_bf16x2(l0, l1), pack_bf16x2(l2, l3));
    }
}

// ---------------------------------------------------------------------------
// Node MMA (16 warps, M=128): LDS.32 version (unchanged, proven)
// ---------------------------------------------------------------------------
__device__ __forceinline__ void mma_tile128(const char* sm, float acc[2][8][4]) {
    const int lane = threadIdx.x & 31;
    const int wid  = threadIdx.x >> 5;
    const int wm = wid & 3, wn = wid >> 2;
    const int g  = lane >> 2;
    const int t4 = (lane & 3) * 4;

    const char* xhi = sm + SXHI;
    const char* xlo = sm + SXHI + 32768;
    const char* wh = sm + ((wn >= 2) ? SW2HI : SW1HI);
    const char* wl = wh + 32768;

    const int arow = (wm * 32 + g) * 256 + t4;
    const int brow = ((wn & 1) * 64 + g) * 256 + t4;

    #pragma unroll
    for (int i = 0; i < 2; i++)
        #pragma unroll
        for (int j = 0; j < 8; j++)
            #pragma unroll
            for (int r = 0; r < 4; r++) acc[i][j][r] = 0.f;

    #pragma unroll
    for (int ks = 0; ks < 8; ks++) {
        const int cx0 = (((2 * ks) ^ g) << 4);
        const int cx1 = (((2 * ks + 1) ^ g) << 4);
        uint32_t ah[2][4], al[2][4];
        #pragma unroll
        for (int i = 0; i < 2; i++) {
            int r0 = arow + i * 16 * 256;
            int r8 = r0 + 8 * 256;
            ah[i][0] = *reinterpret_cast<const uint32_t*>(xhi + r0 + cx0);
            ah[i][1] = *reinterpret_cast<const uint32_t*>(xhi + r8 + cx0);
            ah[i][2] = *reinterpret_cast<const uint32_t*>(xhi + r0 + cx1);
            ah[i][3] = *reinterpret_cast<const uint32_t*>(xhi + r8 + cx1);
            al[i][0] = *reinterpret_cast<const uint32_t*>(xlo + r0 + cx0);
            al[i][1] = *reinterpret_cast<const uint32_t*>(xlo + r8 + cx0);
            al[i][2] = *reinterpret_cast<const uint32_t*>(xlo + r0 + cx1);
            al[i][3] = *reinterpret_cast<const uint32_t*>(xlo + r8 + cx1);
        }
        #pragma unroll
        for (int j = 0; j < 8; j++) {
            int rb = brow + j * 8 * 256;
            uint32_t bh0 = *reinterpret_cast<const uint32_t*>(wh + rb + cx0);
            uint32_t bh1 = *reinterpret_cast<const uint32_t*>(wh + rb + cx1);
            uint32_t bl0 = *reinterpret_cast<const uint32_t*>(wl + rb + cx0);
            uint32_t bl1 = *reinterpret_cast<const uint32_t*>(wl + rb + cx1);
            #pragma unroll
            for (int i = 0; i < 2; i++) {
                hmma(acc[i][j], ah[i][0], ah[i][1], ah[i][2], ah[i][3], bh0, bh1);
                hmma(acc[i][j], al[i][0], al[i][1], al[i][2], al[i][3], bh0, bh1);
                hmma(acc[i][j], ah[i][0], ah[i][1], ah[i][2], ah[i][3], bl0, bl1);
            }
        }
    }
}

// ---------------------------------------------------------------------------
// Edge half-MMA via ldmatrix (8 warps/half, M=64):
// wm = hw&1 (32 rows), wn = hw>>1 (64 of 256 combined cols).
// All row bases are multiples of 8 -> row&7 == lane&7 for the row a lane
// addresses, so the swizzle XOR term is lane-uniform per chunk.
// ---------------------------------------------------------------------------
__device__ __forceinline__ void mma_tile64h(uint32_t smb, uint32_t xbuf,
                                            int wm, int wn, int lane,
                                            float acc[2][8][4]) {
    const int mi = lane >> 3;          // matrix slot this lane addresses
    const int r  = lane & 7;           // row within 8x8 matrix
    const uint32_t xh = xbuf;
    const uint32_t xl = xbuf + 16384;
    const uint32_t wh = smb + ((wn >= 2) ? SW2HI : SW1HI);
    const uint32_t wl = wh + 32768;

    // A: matrices (mi&1 -> +8 rows, mi>>1 -> +1 chunk)
    const uint32_t aro0 = (uint32_t)((wm * 32 + (mi & 1) * 8 + r) * 256);
    const uint32_t aro1 = aro0 + 16 * 256;
    const int axc = mi >> 1;
    // B: matrices (mi>>1 -> +1 n-block, mi&1 -> +1 chunk)
    const int bxc = mi & 1;
    uint32_t bro[4];
    #pragma unroll
    for (int jp = 0; jp < 4; jp++)
        bro[jp] = (uint32_t)((((wn & 1) * 64) + (jp * 2 + (mi >> 1)) * 8 + r) * 256);

    #pragma unroll
    for (int i = 0; i < 2; i++)
        #pragma unroll
        for (int j = 0; j < 8; j++)
            #pragma unroll
            for (int rr = 0; rr < 4; rr++) acc[i][j][rr] = 0.f;

    #pragma unroll
    for (int ks = 0; ks < 8; ks++) {
        const uint32_t xA = (uint32_t)(((2 * ks + axc) ^ r) << 4);
        const uint32_t xB = (uint32_t)(((2 * ks + bxc) ^ r) << 4);
        uint32_t ah[8], al[8];
        LDSM_X4(ah[0], ah[1], ah[2], ah[3], xh + aro0 + xA);
        LDSM_X4(ah[4], ah[5], ah[6], ah[7], xh + aro1 + xA);
        LDSM_X4(al[0], al[1], al[2], al[3], xl + aro0 + xA);
        LDSM_X4(al[4], al[5], al[6], al[7], xl + aro1 + xA);
        #pragma unroll
        for (int jp = 0; jp < 4; jp++) {
            uint32_t bh[4], bl[4];
            LDSM_X4(bh[0], bh[1], bh[2], bh[3], wh + bro[jp] + xB);
            LDSM_X4(bl[0], bl[1], bl[2], bl[3], wl + bro[jp] + xB);
            const int j0 = jp * 2, j1 = jp * 2 + 1;
            hmma(acc[0][j0], ah[0], ah[1], ah[2], ah[3], bh[0], bh[1]);
            hmma(acc[0][j0], al[0], al[1], al[2], al[3], bh[0], bh[1]);
            hmma(acc[0][j0], ah[0], ah[1], ah[2], ah[3], bl[0], bl[1]);
            hmma(acc[0][j1], ah[0], ah[1], ah[2], ah[3], bh[2], bh[3]);
            hmma(acc[0][j1], al[0], al[1], al[2], al[3], bh[2], bh[3]);
            hmma(acc[0][j1], ah[0], ah[1], ah[2], ah[3], bl[2], bl[3]);
            hmma(acc[1][j0], ah[4], ah[5], ah[6], ah[7], bh[0], bh[1]);
            hmma(acc[1][j0], al[4], al[5], al[6], al[7], bh[0], bh[1]);
            hmma(acc[1][j0], ah[4], ah[5], ah[6], ah[7], bl[0], bl[1]);
            hmma(acc[1][j1], ah[4], ah[5], ah[6], ah[7], bh[2], bh[3]);
            hmma(acc[1][j1], al[4], al[5], al[6], al[7], bh[2], bh[3]);
            hmma(acc[1][j1], ah[4], ah[5], ah[6], ah[7], bl[2], bl[3]);
        }
    }
}

// ---------------------------------------------------------------------------
// Node GEMMs merged: half 0 -> (Wq,Wk)->(q,k), half 1 -> (Wv,Wout)->(v,nres)
// ---------------------------------------------------------------------------
__global__ __launch_bounds__(512, 1) void gemm_node(
    const float* __restrict__ X,
    const float* __restrict__ bq, const float* __restrict__ bk,
    const float* __restrict__ bv, const float* __restrict__ bout,
    float* __restrict__ q, float* __restrict__ kk,
    float* __restrict__ vv, float* __restrict__ nres)
{
    extern __shared__ char sm[];
    const int half = blockIdx.x / NBLK;
    const int tile = blockIdx.x % NBLK;
    const int m0 = tile * 128;
    const float* b1 = half ? bv : bq;
    const float* b2 = half ? bout : bk;
    float* Y1 = half ? vv : q;
    float* Y2 = half ? nres : kk;

    copy_weights_async(sm, half * 2, half * 2 + 1);
    asm volatile("cp.async.commit_group;");
    convert_x128(sm, X, m0, NN);
    asm volatile("cp.async.wait_group 0;");
    __syncthreads();

    float acc[2][8][4];
    mma_tile128(sm, acc);

    const int lane = threadIdx.x & 31;
    const int wid  = threadIdx.x >> 5;
    const int wm = wid & 3, wn = wid >> 2;
    const int g = lane >> 2, t2 = (lane & 3) * 2;

    const float* bias = (wn >= 2) ? b2 : b1;
    float* Y = (wn >= 2) ? Y2 : Y1;
    float2 bb[8];
    #pragma unroll
    for (int j = 0; j < 8; j++) {
        int colw = (wn & 1) * 64 + j * 8 + t2;
        bb[j] = *reinterpret_cast<const float2*>(&bias[colw]);
    }
    #pragma unroll
    for (int i = 0; i < 2; i++) {
        int rlo = m0 + wm * 32 + i * 16 + g;
        int rhi = rlo + 8;
        #pragma unroll
        for (int j = 0; j < 8; j++) {
            int colw = (wn & 1) * 64 + j * 8 + t2;
            if (rlo < NN) {
                float2 o = make_float2(acc[i][j][0] + bb[j].x, acc[i][j][1] + bb[j].y);
                *reinterpret_cast<float2*>(&Y[(size_t)rlo * 128 + colw]) = o;
            }
            if (rhi < NN) {
                float2 o = make_float2(acc[i][j][2] + bb[j].x, acc[i][j][3] + bb[j].y);
                *reinterpret_cast<float2*>(&Y[(size_t)rhi * 128 + colw]) = o;
            }
        }
    }
}

// ---------------------------------------------------------------------------
// Persistent edge kernel: two independent 256-thread halves per CTA.
// ---------------------------------------------------------------------------
__global__ __launch_bounds__(512, 1) void edge_persist(
    const float* __restrict__ edge_feats,
    const float* __restrict__ be, const float* __restrict__ bev,
    const int* __restrict__ src, const int* __restrict__ dst,
    const float* __restrict__ q, const float* __restrict__ k,
    const float* __restrict__ v,
    const float* __restrict__ ln_eg, const float* __restrict__ ln_eb,
    float* __restrict__ agg, float* __restrict__ y_out)
{
    extern __shared__ char sm[];
    const uint32_t smb = smem_u32(sm);
    const int tid  = threadIdx.x;
    const int lane = tid & 31;
    const int wid  = tid >> 5;
    const int h    = wid >> 3;          // half 0/1
    const int hw   = wid & 7;           // warp within half
    const int htid = tid & 255;
    const int wm = hw & 1, wn = hw >> 1;
    const int g = lane >> 2, t2 = (lane & 3) * 2;
    const int barid = 1 + h;
    const unsigned FULL = 0xffffffffu;

    char* xbuf = sm + EXB0 + h * 32768;
    const uint32_t xbuf_u = smb + EXB0 + h * 32768;
    float* P = reinterpret_cast<float*>(xbuf);   // [64][128], aliases X

    const int tstride = gridDim.x * 2;
    int t = blockIdx.x * 2 + h;

    // prologue: weights via cp.async + first tile converted directly
    copy_weights_async(sm, 4, 5);
    asm volatile("cp.async.commit_group;");
    if (t < ETILES) convert_x64(xbuf, edge_feats, t * 64, htid);
    asm volatile("cp.async.wait_group 0;");
    __syncthreads();

    // loop-invariant params
    const float* bias = (wn >= 2) ? bev : be;
    float2 bb[8];
    #pragma unroll
    for (int j = 0; j < 8; j++) {
        int colw = (wn & 1) * 64 + j * 8 + t2;
        bb[j] = *reinterpret_cast<const float2*>(&bias[colw]);
    }
    float4 ge = *reinterpret_cast<const float4*>(&ln_eg[4 * lane]);
    float4 gb = *reinterpret_cast<const float4*>(&ln_eb[4 * lane]);

    for (; t < ETILES; ) {
        const int e0 = t * 64;
        // preload this warp's 8 edges' indices (lanes 0-7 src, 8-15 dst)
        int sd = 0;
        if (lane < 16)
            sd = __ldg(((lane < 8) ? src : dst) + e0 + hw * 8 + (lane & 7));

        float acc[2][8][4];
        mma_tile64h(smb, xbuf_u, wm, wn, lane, acc);
        BARH(barid);             // all X reads done -> P may overwrite

        // Phase A: eproj + be -> P (warps wn<2)
        if (wn < 2) {
            #pragma unroll
            for (int i = 0; i < 2; i++) {
                int rlo = wm * 32 + i * 16 + g;
                int rhi = rlo + 8;
                #pragma unroll
                for (int j = 0; j < 8; j++) {
                    int colw = (wn & 1) * 64 + j * 8 + t2;
                    P[rlo * 128 + colw]     = acc[i][j][0] + bb[j].x;
                    P[rlo * 128 + colw + 1] = acc[i][j][1] + bb[j].y;
                    P[rhi * 128 + colw]     = acc[i][j][2] + bb[j].x;
                    P[rhi * 128 + colw + 1] = acc[i][j][3] + bb[j].y;
                }
            }
        }
        BARH(barid);

        // Phase B: 8 edges per warp; lane owns 4 consecutive cols.
        // No max-subtraction in softmax (|m| small by construction);
        // divisions via fast reciprocal.
        {
            int s = __shfl_sync(FULL, sd, 0);
            int d = __shfl_sync(FULL, sd, 8);
            float4 q4 = __ldg(reinterpret_cast<const float4*>(&q[(size_t)s * 128 + 4 * lane]));
            float4 k4 = __ldg(reinterpret_cast<const float4*>(&k[(size_t)d * 128 + 4 * lane]));
            float4 v4 = __ldg(reinterpret_cast<const float4*>(&v[(size_t)s * 128 + 4 * lane]));

            #pragma unroll 1
            for (int it = 0; it < 8; it++) {
                int sn = 0, dn = 0;
                float4 qn, kn, vn;
                if (it < 7) {
                    sn = __shfl_sync(FULL, sd, it + 1);
                    dn = __shfl_sync(FULL, sd, it + 9);
                    qn = __ldg(reinterpret_cast<const float4*>(&q[(size_t)sn * 128 + 4 * lane]));
                    kn = __ldg(reinterpret_cast<const float4*>(&k[(size_t)dn * 128 + 4 * lane]));
                    vn = __ldg(reinterpret_cast<const float4*>(&v[(size_t)sn * 128 + 4 * lane]));
                }

                int row = hw * 8 + it;
                float pd = q4.x * k4.x + q4.y * k4.y + q4.z * k4.z + q4.w * k4.w;
                pd += __shfl_xor_sync(FULL, pd, 1);
                pd += __shfl_xor_sync(FULL, pd, 2);
                pd += __shfl_xor_sync(FULL, pd, 4);

                float4 m4 = *reinterpret_cast<const float4*>(&P[row * 128 + 4 * lane]);
                m4.x = fmaf(pd, INV_SCALE, m4.x);
                m4.y = fmaf(pd, INV_SCALE, m4.y);
                m4.z = fmaf(pd, INV_SCALE, m4.z);
                m4.w = fmaf(pd, INV_SCALE, m4.w);

                // softmax over 4 heads (partners lane^8, lane^16), no max shift
                float4 ex;
                ex.x = __expf(m4.x); ex.y = __expf(m4.y);
                ex.z = __expf(m4.z); ex.w = __expf(m4.w);
                float4 sx = ex;
                #pragma unroll
                for (int off = 8; off <= 16; off <<= 1) {
                    sx.x += __shfl_xor_sync(FULL, sx.x, off);
                    sx.y += __shfl_xor_sync(FULL, sx.y, off);
                    sx.z += __shfl_xor_sync(FULL, sx.z, off);
                    sx.w += __shfl_xor_sync(FULL, sx.w, off);
                }
                float4 msg;
                msg.x = v4.x * ex.x * __fdividef(1.0f, sx.x);
                msg.y = v4.y * ex.y * __fdividef(1.0f, sx.y);
                msg.z = v4.z * ex.z * __fdividef(1.0f, sx.z);
                msg.w = v4.w * ex.w * __fdividef(1.0f, sx.w);
                float* ap = &agg[(size_t)d * 128 + 4 * lane];
                asm volatile("red.global.add.v4.f32 [%0], {%1, %2, %3, %4};"
                             :: "l"(ap), "f"(msg.x), "f"(msg.y), "f"(msg.z), "f"(msg.w)
                             : "memory");

                // layernorm over 128 cols
                float ls = m4.x + m4.y + m4.z + m4.w;
                float lq = m4.x * m4.x + m4.y * m4.y + m4.z * m4.z + m4.w * m4.w;
                #pragma unroll
                for (int off = 16; off > 0; off >>= 1) {
                    ls += __shfl_xor_sync(FULL, ls, off);
                    lq += __shfl_xor_sync(FULL, lq, off);
                }
                float mu = ls * (1.0f / 128.0f);
                float var = lq * (1.0f / 128.0f) - mu * mu;
                float rs = rsqrtf(var + LN_EPS);

                float t0 = fmaf((m4.x - mu) * rs, ge.x, gb.x);
                float t1 = fmaf((m4.y - mu) * rs, ge.y, gb.y);
                float t2f = fmaf((m4.z - mu) * rs, ge.z, gb.z);
                float t3 = fmaf((m4.w - mu) * rs, ge.w, gb.w);
                float4 sil;
                sil.x = t0 * __fdividef(1.0f, 1.0f + __expf(-t0));
                sil.y = t1 * __fdividef(1.0f, 1.0f + __expf(-t1));
                sil.z = t2f * __fdividef(1.0f, 1.0f + __expf(-t2f));
                sil.w = t3 * __fdividef(1.0f, 1.0f + __expf(-t3));
                *reinterpret_cast<float4*>(&P[row * 128 + 4 * lane]) = sil;

                s = sn; d = dn; q4 = qn; k4 = kn; v4 = vn;
            }
        }
        BARH(barid);

        // Phase C: y = eres + bev + silu (warps wn>=2 hold the Wev product)
        if (wn >= 2) {
            #pragma unroll
            for (int i = 0; i < 2; i++) {
                int rlo = wm * 32 + i * 16 + g;
                int rhi = rlo + 8;
                #pragma unroll
                for (int j = 0; j < 8; j++) {
                    int colw = (wn & 1) * 64 + j * 8 + t2;
                    float2 o0, o1;
                    o0.x = acc[i][j][0] + bb[j].x + P[rlo * 128 + colw];
                    o0.y = acc[i][j][1] + bb[j].y + P[rlo * 128 + colw + 1];
                    o1.x = acc[i][j][2] + bb[j].x + P[rhi * 128 + colw];
                    o1.y = acc[i][j][3] + bb[j].y + P[rhi * 128 + colw + 1];
                    *reinterpret_cast<float2*>(&y_out[(size_t)(e0 + rlo) * 128 + colw]) = o0;
                    *reinterpret_cast<float2*>(&y_out[(size_t)(e0 + rhi) * 128 + colw]) = o1;
                }
            }
        }
        t += tstride;
        BARH(barid);             // P reads done -> buffer free for next convert

        if (t < ETILES) convert_x64(xbuf, edge_feats, t * 64, htid);
        BARH(barid);             // convert visible to all warps of the half
    }
}

// ---------------------------------------------------------------------------
// Node finalize: x = node_res + silu(LN_128(agg)), float4 lanes
// ---------------------------------------------------------------------------
__global__ __launch_bounds__(256) void node_kernel(
    const float* __restrict__ agg, const float* __restrict__ nres,
    const float* __restrict__ ln_ng, const float* __restrict__ ln_nb,
    float* __restrict__ x_out)
{
    int node = (blockIdx.x * blockDim.x + threadIdx.x) >> 5;
    int lane = threadIdx.x & 31;
    if (node >= NN) return;
    const unsigned FULL = 0xffffffffu;

    size_t base = (size_t)node * 128 + 4 * lane;
    float4 a = __ldg(reinterpret_cast<const float4*>(&agg[base]));

    float ls = a.x + a.y + a.z + a.w;
    float lq = a.x * a.x + a.y * a.y + a.z * a.z + a.w * a.w;
    #pragma unroll
    for (int off = 16; off > 0; off >>= 1) {
        ls += __shfl_xor_sync(FULL, ls, off);
        lq += __shfl_xor_sync(FULL, lq, off);
    }
    float mu  = ls * (1.0f / 128.0f);
    float var = lq * (1.0f / 128.0f) - mu * mu;
    float rs  = rsqrtf(var + LN_EPS);

    float4 g = __ldg(reinterpret_cast<const float4*>(&ln_ng[4 * lane]));
    float4 b = __ldg(reinterpret_cast<const float4*>(&ln_nb[4 * lane]));
    float4 r = __ldg(reinterpret_cast<const float4*>(&nres[base]));

    float t0 = fmaf((a.x - mu) * rs, g.x, b.x);
    float t1 = fmaf((a.y - mu) * rs, g.y, b.y);
    float t2 = fmaf((a.z - mu) * rs, g.z, b.z);
    float t3 = fmaf((a.w - mu) * rs, g.w, b.w);
    float4 o;
    o.x = t0 * __fdividef(1.0f, 1.0f + __expf(-t0)) + r.x;
    o.y = t1 * __fdividef(1.0f, 1.0f + __expf(-t1)) + r.y;
    o.z = t2 * __fdividef(1.0f, 1.0f + __expf(-t2)) + r.z;
    o.w = t3 * __fdividef(1.0f, 1.0f + __expf(-t3)) + r.w;
    *reinterpret_cast<float4*>(&x_out[base]) = o;
}

// ---------------------------------------------------------------------------
// Launch
// ---------------------------------------------------------------------------
extern "C" void kernel_launch(void* const* d_in, const int* in_sizes, int n_in,
                              void* d_out, int out_size)
{
    const float* node_feats = (const float*)d_in[0];
    const float* edge_feats = (const float*)d_in[1];
    const int*   src        = (const int*)d_in[2];
    const int*   dst        = (const int*)d_in[3];
    const float* Wq   = (const float*)d_in[4];
    const float* bq   = (const float*)d_in[5];
    const float* Wk   = (const float*)d_in[6];
    const float* bk   = (const float*)d_in[7];
    const float* Wv   = (const float*)d_in[8];
    const float* bv   = (const float*)d_in[9];
    const float* We   = (const float*)d_in[10];
    const float* be   = (const float*)d_in[11];
    const float* Wev  = (const float*)d_in[12];
    const float* bev  = (const float*)d_in[13];
    const float* Wout = (const float*)d_in[14];
    const float* bout = (const float*)d_in[15];
    const float* ln_ng = (const float*)d_in[16];
    const float* ln_nb = (const float*)d_in[17];
    const float* ln_eg = (const float*)d_in[18];
    const float* ln_eb = (const float*)d_in[19];

    float* scratch = nullptr;
    cudaGetSymbolAddress((void**)&scratch, g_scratch);
    float* q    = scratch;
    float* kk   = q    + (size_t)NN * 128;
    float* vv   = kk   + (size_t)NN * 128;
    float* nres = vv   + (size_t)NN * 128;
    float* agg  = nres + (size_t)NN * 128;

    float* x_out = (float*)d_out;
    float* y_out = x_out + (size_t)NN * 128;

    static bool attr_set = false;
    if (!attr_set) {
        cudaFuncSetAttribute(gemm_node, cudaFuncAttributeMaxDynamicSharedMemorySize, SMEM_GEMM);
        cudaFuncSetAttribute(edge_persist, cudaFuncAttributeMaxDynamicSharedMemorySize, SMEM_EDGE);
        attr_set = true;
    }

    int nsm = 148;
    cudaDeviceGetAttribute(&nsm, cudaDevAttrMultiProcessorCount, 0);

    // launch order: 0 prep_w, 1 zero, 2 gemm_node, 3 edge_persist, 4 node
    prep_w<<<48, 256>>>(Wq, Wk, Wv, Wout, We, Wev);
    zero_kernel<<<NN * 32 / 256, 256>>>(agg);
    gemm_node<<<2 * NBLK, 512, SMEM_GEMM>>>(
        node_feats, bq, bk, bv, bout, q, kk, vv, nres);
    edge_persist<<<nsm, 512, SMEM_EDGE>>>(
        edge_feats, be, bev, src, dst, q, kk, vv, ln_eg, ln_eb, agg, y_out);
    node_kernel<<<NN / 8, 256>>>(agg, nres, ln_ng, ln_nb, x_out);
}

// round 11
// speedup vs baseline: 1.5143x; 1.0419x over previous
#include <cuda_runtime.h>
#include <cuda_bf16.h>
#include <math.h>
#include <stdint.h>

#define NN 50000
#define EE 400000
#define NBLK 391            // ceil(NN/128) node tiles
#define ETILES32 12500      // EE/32 edge tiles
#define INV_SCALE 0.17677669529663687f   // 1/sqrt(32)
#define LN_EPS 1e-5f

// Scratch: q, k, v, nres, agg (5*N*128 = 32M floats)
__device__ float g_scratch[32000000];
// bf16 hi/lo swizzled weight tiles: 6 weights x (32KB hi + 32KB lo)
__device__ __align__(256) unsigned char g_wbf[6 * 65536];

// ---- node gemm smem layout ----
#define SW1HI 0
#define SW2HI 65536
#define SXHI  131072
#define SMEM_GEMM 196608
// ---- edge persistent smem layout: W 128KB + per-group 16KB X/P buffer ----
#define EXB0  131072
#define SMEM_EDGE 196608

// Swizzled byte offset in a K-major bf16 tile (256B rows, 16B chunks,
// chunk ^= row&7 -> conflict-free for row-parallel and k-parallel access).
__device__ __forceinline__ int sw_off(int row, int col) {
    return row * 256 + ((((col >> 3) ^ (row & 7)) & 15) << 4) + (col & 7) * 2;
}

__device__ __forceinline__ uint32_t smem_u32(const void* p) {
    uint32_t a;
    asm("{ .reg .u64 t; cvta.to.shared.u64 t, %1; cvt.u32.u64 %0, t; }"
        : "=r"(a) : "l"(p));
    return a;
}

__device__ __forceinline__ void hmma(float* c, uint32_t a0, uint32_t a1,
                                     uint32_t a2, uint32_t a3,
                                     uint32_t b0, uint32_t b1) {
    asm("mma.sync.aligned.m16n8k16.row.col.f32.bf16.bf16.f32 "
        "{%0,%1,%2,%3}, {%4,%5,%6,%7}, {%8,%9}, {%0,%1,%2,%3};"
        : "+f"(c[0]), "+f"(c[1]), "+f"(c[2]), "+f"(c[3])
        : "r"(a0), "r"(a1), "r"(a2), "r"(a3), "r"(b0), "r"(b1));
}

#define LDSM_X4(r0, r1, r2, r3, addr) \
    asm volatile("ldmatrix.sync.aligned.m8n8.x4.shared.b16 {%0,%1,%2,%3}, [%4];" \
        : "=r"(r0), "=r"(r1), "=r"(r2), "=r"(r3) : "r"(addr))

__device__ __forceinline__ uint32_t pack_bf16x2(float a, float b) {
    uint32_t r;
    asm("cvt.rn.bf16x2.f32 %0, %1, %2;" : "=r"(r) : "f"(b), "f"(a));
    return r;
}

#define BARG(id) asm volatile("bar.sync %0, 128;" :: "r"(id) : "memory")

// ---------------------------------------------------------------------------
// Weight prep: split 6 weights into bf16 hi(trunc)/lo swizzled tiles.
// 48 blocks: weight = bx>>3, row strip = bx&7 (16 rows each).
// ---------------------------------------------------------------------------
__global__ void prep_w(const float* __restrict__ W0, const float* __restrict__ W1,
                       const float* __restrict__ W2, const float* __restrict__ W3,
                       const float* __restrict__ W4, const float* __restrict__ W5)
{
    const float* W;
    switch (blockIdx.x >> 3) {
        case 0: W = W0; break; case 1: W = W1; break; case 2: W = W2; break;
        case 3: W = W3; break; case 4: W = W4; break; default: W = W5; break;
    }
    unsigned char* out = g_wbf + (size_t)(blockIdx.x >> 3) * 65536;
    int base = (blockIdx.x & 7) * 2048;
    for (int ii = threadIdx.x; ii < 2048; ii += blockDim.x) {
        int idx = base + ii;
        int row = idx >> 7, col = idx & 127;
        float x = W[idx];
        uint32_t xu = __float_as_uint(x);
        uint32_t hi = xu & 0xffff0000u;
        float lo = x - __uint_as_float(hi);
        __nv_bfloat16 lb = __float2bfloat16(lo);
        int off = sw_off(row, col);
        *reinterpret_cast<uint16_t*>(out + off) = (uint16_t)(hi >> 16);
        *reinterpret_cast<__nv_bfloat16*>(out + 32768 + off) = lb;
    }
}

// ---------------------------------------------------------------------------
// Zero agg buffer
// ---------------------------------------------------------------------------
__global__ void zero_kernel(float* __restrict__ p)
{
    int i = blockIdx.x * blockDim.x + threadIdx.x;
    reinterpret_cast<float4*>(p)[i] = make_float4(0.f, 0.f, 0.f, 0.f);
}

// ---------------------------------------------------------------------------
// cp.async weight staging (no commit — caller commits)
// ---------------------------------------------------------------------------
__device__ __forceinline__ void copy_weights_async(char* sm, int w1idx, int w2idx) {
    uint32_t d1 = smem_u32(sm + SW1HI);
    uint32_t d2 = smem_u32(sm + SW2HI);
    const char* s1 = reinterpret_cast<const char*>(g_wbf + (size_t)w1idx * 65536);
    const char* s2 = reinterpret_cast<const char*>(g_wbf + (size_t)w2idx * 65536);
    int tid = threadIdx.x;
    #pragma unroll
    for (int i = 0; i < 8; i++) {
        int j = (tid + i * 512) * 16;
        asm volatile("cp.async.cg.shared.global [%0], [%1], 16;"
                     :: "r"(d1 + j), "l"(s1 + j));
        asm volatile("cp.async.cg.shared.global [%0], [%1], 16;"
                     :: "r"(d2 + j), "l"(s2 + j));
    }
}

// ---------------------------------------------------------------------------
// Node-side convert: 128-row tile of X fp32 -> swizzled hi/lo bf16 in smem
// (512 threads)
// ---------------------------------------------------------------------------
__device__ __forceinline__ void convert_x128(char* sm, const float* __restrict__ X,
                                             int m0, int M) {
    int tid = threadIdx.x;
    int r = tid >> 2;
    int ch = (tid & 3) * 32;
    bool valid = (m0 + r) < M;
    const float* xp = X + (size_t)(m0 + r) * 128 + ch;
    #pragma unroll
    for (int u = 0; u < 8; u++) {
        int c = ch + u * 4;
        float4 xv = make_float4(0.f, 0.f, 0.f, 0.f);
        if (valid) xv = __ldg(reinterpret_cast<const float4*>(xp + u * 4));
        uint32_t u0 = __float_as_uint(xv.x), u1 = __float_as_uint(xv.y);
        uint32_t u2 = __float_as_uint(xv.z), u3 = __float_as_uint(xv.w);
        uint32_t h01 = __byte_perm(u0, u1, 0x7632);
        uint32_t h23 = __byte_perm(u2, u3, 0x7632);
        float l0 = xv.x - __uint_as_float(u0 & 0xffff0000u);
        float l1 = xv.y - __uint_as_float(u1 & 0xffff0000u);
        float l2 = xv.z - __uint_as_float(u2 & 0xffff0000u);
        float l3 = xv.w - __uint_as_float(u3 & 0xffff0000u);
        int off = sw_off(r, c);
        *reinterpret_cast<uint2*>(sm + SXHI + off) = make_uint2(h01, h23);
        *reinterpret_cast<uint2*>(sm + SXHI + 32768 + off) =
            make_uint2(pack_bf16x2(l0, l1), pack_bf16x2(l2, l3));
    }
}

// Edge-side convert: 32-row tile into a group's 16KB buffer (128 threads/group)
__device__ __forceinline__ void convert_x32(char* xbuf, const float* __restrict__ X,
                                            int e0, int gtid) {
    int r = gtid >> 2;              // 0..31
    int ch = (gtid & 3) * 32;
    const float* xp = X + (size_t)(e0 + r) * 128 + ch;
    #pragma unroll
    for (int u = 0; u < 8; u++) {
        int c = ch + u * 4;
        float4 xv = __ldg(reinterpret_cast<const float4*>(xp + u * 4));
        uint32_t u0 = __float_as_uint(xv.x), u1 = __float_as_uint(xv.y);
        uint32_t u2 = __float_as_uint(xv.z), u3 = __float_as_uint(xv.w);
        uint32_t h01 = __byte_perm(u0, u1, 0x7632);
        uint32_t h23 = __byte_perm(u2, u3, 0x7632);
        float l0 = xv.x - __uint_as_float(u0 & 0xffff0000u);
        float l1 = xv.y - __uint_as_float(u1 & 0xffff0000u);
        float l2 = xv.z - __uint_as_float(u2 & 0xffff0000u);
        float l3 = xv.w - __uint_as_float(u3 & 0xffff0000u);
        int off = sw_off(r, c);     // < 8192 for r < 32
        *reinterpret_cast<uint2*>(xbuf + off) = make_uint2(h01, h23);
        *reinterpret_cast<uint2*>(xbuf + 8192 + off) =
            make_uint2(pack_bf16x2(l0, l1), pack_bf16x2(l2, l3));
    }
}

// ---------------------------------------------------------------------------
// Node MMA (16 warps, M=128): LDS.32 version (unchanged, proven)
// ---------------------------------------------------------------------------
__device__ __forceinline__ void mma_tile128(const char* sm, float acc[2][8][4]) {
    const int lane = threadIdx.x & 31;
    const int wid  = threadIdx.x >> 5;
    const int wm = wid & 3, wn = wid >> 2;
    const int g  = lane >> 2;
    const int t4 = (lane & 3) * 4;

    const char* xhi = sm + SXHI;
    const char* xlo = sm + SXHI + 32768;
    const char* wh = sm + ((wn >= 2) ? SW2HI : SW1HI);
    const char* wl = wh + 32768;

    const int arow = (wm * 32 + g) * 256 + t4;
    const int brow = ((wn & 1) * 64 + g) * 256 + t4;

    #pragma unroll
    for (int i = 0; i < 2; i++)
        #pragma unroll
        for (int j = 0; j < 8; j++)
            #pragma unroll
            for (int r = 0; r < 4; r++) acc[i][j][r] = 0.f;

    #pragma unroll
    for (int ks = 0; ks < 8; ks++) {
        const int cx0 = (((2 * ks) ^ g) << 4);
        const int cx1 = (((2 * ks + 1) ^ g) << 4);
        uint32_t ah[2][4], al[2][4];
        #pragma unroll
        for (int i = 0; i < 2; i++) {
            int r0 = arow + i * 16 * 256;
            int r8 = r0 + 8 * 256;
            ah[i][0] = *reinterpret_cast<const uint32_t*>(xhi + r0 + cx0);
            ah[i][1] = *reinterpret_cast<const uint32_t*>(xhi + r8 + cx0);
            ah[i][2] = *reinterpret_cast<const uint32_t*>(xhi + r0 + cx1);
            ah[i][3] = *reinterpret_cast<const uint32_t*>(xhi + r8 + cx1);
            al[i][0] = *reinterpret_cast<const uint32_t*>(xlo + r0 + cx0);
            al[i][1] = *reinterpret_cast<const uint32_t*>(xlo + r8 + cx0);
            al[i][2] = *reinterpret_cast<const uint32_t*>(xlo + r0 + cx1);
            al[i][3] = *reinterpret_cast<const uint32_t*>(xlo + r8 + cx1);
        }
        #pragma unroll
        for (int j = 0; j < 8; j++) {
            int rb = brow + j * 8 * 256;
            uint32_t bh0 = *reinterpret_cast<const uint32_t*>(wh + rb + cx0);
            uint32_t bh1 = *reinterpret_cast<const uint32_t*>(wh + rb + cx1);
            uint32_t bl0 = *reinterpret_cast<const uint32_t*>(wl + rb + cx0);
            uint32_t bl1 = *reinterpret_cast<const uint32_t*>(wl + rb + cx1);
            #pragma unroll
            for (int i = 0; i < 2; i++) {
                hmma(acc[i][j], ah[i][0], ah[i][1], ah[i][2], ah[i][3], bh0, bh1);
                hmma(acc[i][j], al[i][0], al[i][1], al[i][2], al[i][3], bh0, bh1);
                hmma(acc[i][j], ah[i][0], ah[i][1], ah[i][2], ah[i][3], bl0, bl1);
            }
        }
    }
}

// ---------------------------------------------------------------------------
// Group MMA via ldmatrix: M=32 tile, warp covers all rows, N=64 of 256
// combined cols (gw selects weight + col block). Row bases are multiples of
// 8 so the swizzle XOR term is lane-uniform per chunk.
// ---------------------------------------------------------------------------
__device__ __forceinline__ void mma_tile32g(uint32_t smb, uint32_t xbuf,
                                            int gw, int lane,
                                            float acc[2][8][4]) {
    const int mi = lane >> 3;          // matrix slot this lane addresses
    const int r  = lane & 7;           // row within 8x8 matrix
    const uint32_t xh = xbuf;
    const uint32_t xl = xbuf + 8192;
    const uint32_t wh = smb + ((gw >= 2) ? SW2HI : SW1HI);
    const uint32_t wl = wh + 32768;

    // A: frag i covers rows i*16..i*16+15; matrices (mi&1 -> +8 rows,
    // mi>>1 -> +1 k-chunk)
    const uint32_t aro0 = (uint32_t)(((mi & 1) * 8 + r) * 256);
    const uint32_t aro1 = aro0 + 16 * 256;
    const int axc = mi >> 1;
    // B: matrices (mi>>1 -> +1 n-block, mi&1 -> +1 k-chunk)
    const int bxc = mi & 1;
    uint32_t bro[4];
    #pragma unroll
    for (int jp = 0; jp < 4; jp++)
        bro[jp] = (uint32_t)((((gw & 1) * 64) + (jp * 2 + (mi >> 1)) * 8 + r) * 256);

    #pragma unroll
    for (int i = 0; i < 2; i++)
        #pragma unroll
        for (int j = 0; j < 8; j++)
            #pragma unroll
            for (int rr = 0; rr < 4; rr++) acc[i][j][rr] = 0.f;

    #pragma unroll
    for (int ks = 0; ks < 8; ks++) {
        const uint32_t xA = (uint32_t)(((2 * ks + axc) ^ r) << 4);
        const uint32_t xB = (uint32_t)(((2 * ks + bxc) ^ r) << 4);
        uint32_t ah[8], al[8];
        LDSM_X4(ah[0], ah[1], ah[2], ah[3], xh + aro0 + xA);
        LDSM_X4(ah[4], ah[5], ah[6], ah[7], xh + aro1 + xA);
        LDSM_X4(al[0], al[1], al[2], al[3], xl + aro0 + xA);
        LDSM_X4(al[4], al[5], al[6], al[7], xl + aro1 + xA);
        #pragma unroll
        for (int jp = 0; jp < 4; jp++) {
            uint32_t bh[4], bl[4];
            LDSM_X4(bh[0], bh[1], bh[2], bh[3], wh + bro[jp] + xB);
            LDSM_X4(bl[0], bl[1], bl[2], bl[3], wl + bro[jp] + xB);
            const int j0 = jp * 2, j1 = jp * 2 + 1;
            hmma(acc[0][j0], ah[0], ah[1], ah[2], ah[3], bh[0], bh[1]);
            hmma(acc[0][j0], al[0], al[1], al[2], al[3], bh[0], bh[1]);
            hmma(acc[0][j0], ah[0], ah[1], ah[2], ah[3], bl[0], bl[1]);
            hmma(acc[0][j1], ah[0], ah[1], ah[2], ah[3], bh[2], bh[3]);
            hmma(acc[0][j1], al[0], al[1], al[2], al[3], bh[2], bh[3]);
            hmma(acc[0][j1], ah[0], ah[1], ah[2], ah[3], bl[2], bl[3]);
            hmma(acc[1][j0], ah[4], ah[5], ah[6], ah[7], bh[0], bh[1]);
            hmma(acc[1][j0], al[4], al[5], al[6], al[7], bh[0], bh[1]);
            hmma(acc[1][j0], ah[4], ah[5], ah[6], ah[7], bl[0], bl[1]);
            hmma(acc[1][j1], ah[4], ah[5], ah[6], ah[7], bh[2], bh[3]);
            hmma(acc[1][j1], al[4], al[5], al[6], al[7], bh[2], bh[3]);
            hmma(acc[1][j1], ah[4], ah[5], ah[6], ah[7], bl[2], bl[3]);
        }
    }
}

// ---------------------------------------------------------------------------
// Node GEMMs merged: half 0 -> (Wq,Wk)->(q,k), half 1 -> (Wv,Wout)->(v,nres)
// ---------------------------------------------------------------------------
__global__ __launch_bounds__(512, 1) void gemm_node(
    const float* __restrict__ X,
    const float* __restrict__ bq, const float* __restrict__ bk,
    const float* __restrict__ bv, const float* __restrict__ bout,
    float* __restrict__ q, float* __restrict__ kk,
    float* __restrict__ vv, float* __restrict__ nres)
{
    extern __shared__ char sm[];
    const int half = blockIdx.x / NBLK;
    const int tile = blockIdx.x % NBLK;
    const int m0 = tile * 128;
    const float* b1 = half ? bv : bq;
    const float* b2 = half ? bout : bk;
    float* Y1 = half ? vv : q;
    float* Y2 = half ? nres : kk;

    copy_weights_async(sm, half * 2, half * 2 + 1);
    asm volatile("cp.async.commit_group;");
    convert_x128(sm, X, m0, NN);
    asm volatile("cp.async.wait_group 0;");
    __syncthreads();

    float acc[2][8][4];
    mma_tile128(sm, acc);

    const int lane = threadIdx.x & 31;
    const int wid  = threadIdx.x >> 5;
    const int wm = wid & 3, wn = wid >> 2;
    const int g = lane >> 2, t2 = (lane & 3) * 2;

    const float* bias = (wn >= 2) ? b2 : b1;
    float* Y = (wn >= 2) ? Y2 : Y1;
    float2 bb[8];
    #pragma unroll
    for (int j = 0; j < 8; j++) {
        int colw = (wn & 1) * 64 + j * 8 + t2;
        bb[j] = *reinterpret_cast<const float2*>(&bias[colw]);
    }
    #pragma unroll
    for (int i = 0; i < 2; i++) {
        int rlo = m0 + wm * 32 + i * 16 + g;
        int rhi = rlo + 8;
        #pragma unroll
        for (int j = 0; j < 8; j++) {
            int colw = (wn & 1) * 64 + j * 8 + t2;
            if (rlo < NN) {
                float2 o = make_float2(acc[i][j][0] + bb[j].x, acc[i][j][1] + bb[j].y);
                *reinterpret_cast<float2*>(&Y[(size_t)rlo * 128 + colw]) = o;
            }
            if (rhi < NN) {
                float2 o = make_float2(acc[i][j][2] + bb[j].x, acc[i][j][3] + bb[j].y);
                *reinterpret_cast<float2*>(&Y[(size_t)rhi * 128 + colw]) = o;
            }
        }
    }
}

// ---------------------------------------------------------------------------
// Persistent edge kernel: FOUR independent 128-thread groups per CTA, each
// with one warp per SMSP, own 32-edge tiles, own named barrier. Weights
// resident. Per group: 16KB X buffer (hi 8K + lo 8K) aliased by P[32][128].
// ---------------------------------------------------------------------------
__global__ __launch_bounds__(512, 1) void edge_persist(
    const float* __restrict__ edge_feats,
    const float* __restrict__ be, const float* __restrict__ bev,
    const int* __restrict__ src, const int* __restrict__ dst,
    const float* __restrict__ q, const float* __restrict__ k,
    const float* __restrict__ v,
    const float* __restrict__ ln_eg, const float* __restrict__ ln_eb,
    float* __restrict__ agg, float* __restrict__ y_out)
{
    extern __shared__ char sm[];
    const uint32_t smb = smem_u32(sm);
    const int tid  = threadIdx.x;
    const int lane = tid & 31;
    const int wid  = tid >> 5;
    const int grp  = wid >> 2;          // group 0..3 (one warp per SMSP each)
    const int gw   = wid & 3;           // warp within group = wn role
    const int gtid = tid & 127;
    const int g = lane >> 2, t2 = (lane & 3) * 2;
    const int barid = 1 + grp;
    const unsigned FULL = 0xffffffffu;

    char* xbuf = sm + EXB0 + grp * 16384;
    const uint32_t xbuf_u = smb + EXB0 + grp * 16384;
    float* P = reinterpret_cast<float*>(xbuf);   // [32][128], aliases X

    const int tstride = gridDim.x * 4;
    int t = blockIdx.x * 4 + grp;

    // prologue: weights via cp.async + first tile converted directly
    copy_weights_async(sm, 4, 5);
    asm volatile("cp.async.commit_group;");
    if (t < ETILES32) convert_x32(xbuf, edge_feats, t * 32, gtid);
    asm volatile("cp.async.wait_group 0;");
    __syncthreads();

    // loop-invariant params
    const float* bias = (gw >= 2) ? bev : be;
    float2 bb[8];
    #pragma unroll
    for (int j = 0; j < 8; j++) {
        int colw = (gw & 1) * 64 + j * 8 + t2;
        bb[j] = *reinterpret_cast<const float2*>(&bias[colw]);
    }
    float4 ge = *reinterpret_cast<const float4*>(&ln_eg[4 * lane]);
    float4 gb = *reinterpret_cast<const float4*>(&ln_eb[4 * lane]);

    for (; t < ETILES32; ) {
        const int e0 = t * 32;
        // preload this warp's 8 edges' indices (lanes 0-7 src, 8-15 dst)
        int sd = 0;
        if (lane < 16)
            sd = __ldg(((lane < 8) ? src : dst) + e0 + gw * 8 + (lane & 7));

        float acc[2][8][4];
        mma_tile32g(smb, xbuf_u, gw, lane, acc);
        BARG(barid);             // all X reads done -> P may overwrite

        // Phase A: eproj + be -> P (warps gw<2)
        if (gw < 2) {
            #pragma unroll
            for (int i = 0; i < 2; i++) {
                int rlo = i * 16 + g;
                int rhi = rlo + 8;
                #pragma unroll
                for (int j = 0; j < 8; j++) {
                    int colw = (gw & 1) * 64 + j * 8 + t2;
                    P[rlo * 128 + colw]     = acc[i][j][0] + bb[j].x;
                    P[rlo * 128 + colw + 1] = acc[i][j][1] + bb[j].y;
                    P[rhi * 128 + colw]     = acc[i][j][2] + bb[j].x;
                    P[rhi * 128 + colw + 1] = acc[i][j][3] + bb[j].y;
                }
            }
        }
        BARG(barid);

        // Phase B: 8 edges per warp (rows gw*8..gw*8+7); lane owns 4 cols.
        {
            int s = __shfl_sync(FULL, sd, 0);
            int d = __shfl_sync(FULL, sd, 8);
            float4 q4 = __ldg(reinterpret_cast<const float4*>(&q[(size_t)s * 128 + 4 * lane]));
            float4 k4 = __ldg(reinterpret_cast<const float4*>(&k[(size_t)d * 128 + 4 * lane]));
            float4 v4 = __ldg(reinterpret_cast<const float4*>(&v[(size_t)s * 128 + 4 * lane]));

            #pragma unroll 1
            for (int it = 0; it < 8; it++) {
                int sn = 0, dn = 0;
                float4 qn, kn, vn;
                if (it < 7) {
                    sn = __shfl_sync(FULL, sd, it + 1);
                    dn = __shfl_sync(FULL, sd, it + 9);
                    qn = __ldg(reinterpret_cast<const float4*>(&q[(size_t)sn * 128 + 4 * lane]));
                    kn = __ldg(reinterpret_cast<const float4*>(&k[(size_t)dn * 128 + 4 * lane]));
                    vn = __ldg(reinterpret_cast<const float4*>(&v[(size_t)sn * 128 + 4 * lane]));
                }

                int row = gw * 8 + it;
                float pd = q4.x * k4.x + q4.y * k4.y + q4.z * k4.z + q4.w * k4.w;
                pd += __shfl_xor_sync(FULL, pd, 1);
                pd += __shfl_xor_sync(FULL, pd, 2);
                pd += __shfl_xor_sync(FULL, pd, 4);

                float4 m4 = *reinterpret_cast<const float4*>(&P[row * 128 + 4 * lane]);
                m4.x = fmaf(pd, INV_SCALE, m4.x);
                m4.y = fmaf(pd, INV_SCALE, m4.y);
                m4.z = fmaf(pd, INV_SCALE, m4.z);
                m4.w = fmaf(pd, INV_SCALE, m4.w);

                // softmax over 4 heads (partners lane^8, lane^16), no max shift
                float4 ex;
                ex.x = __expf(m4.x); ex.y = __expf(m4.y);
                ex.z = __expf(m4.z); ex.w = __expf(m4.w);
                float4 sx = ex;
                #pragma unroll
                for (int off = 8; off <= 16; off <<= 1) {
                    sx.x += __shfl_xor_sync(FULL, sx.x, off);
                    sx.y += __shfl_xor_sync(FULL, sx.y, off);
                    sx.z += __shfl_xor_sync(FULL, sx.z, off);
                    sx.w += __shfl_xor_sync(FULL, sx.w, off);
                }
                float4 msg;
                msg.x = v4.x * ex.x * __fdividef(1.0f, sx.x);
                msg.y = v4.y * ex.y * __fdividef(1.0f, sx.y);
                msg.z = v4.z * ex.z * __fdividef(1.0f, sx.z);
                msg.w = v4.w * ex.w * __fdividef(1.0f, sx.w);
                float* ap = &agg[(size_t)d * 128 + 4 * lane];
                asm volatile("red.global.add.v4.f32 [%0], {%1, %2, %3, %4};"
                             :: "l"(ap), "f"(msg.x), "f"(msg.y), "f"(msg.z), "f"(msg.w)
                             : "memory");

                // layernorm over 128 cols
                float ls = m4.x + m4.y + m4.z + m4.w;
                float lq = m4.x * m4.x + m4.y * m4.y + m4.z * m4.z + m4.w * m4.w;
                #pragma unroll
                for (int off = 16; off > 0; off >>= 1) {
                    ls += __shfl_xor_sync(FULL, ls, off);
                    lq += __shfl_xor_sync(FULL, lq, off);
                }
                float mu = ls * (1.0f / 128.0f);
                float var = lq * (1.0f / 128.0f) - mu * mu;
                float rs = rsqrtf(var + LN_EPS);

                float t0 = fmaf((m4.x - mu) * rs, ge.x, gb.x);
                float t1 = fmaf((m4.y - mu) * rs, ge.y, gb.y);
                float t2f = fmaf((m4.z - mu) * rs, ge.z, gb.z);
                float t3 = fmaf((m4.w - mu) * rs, ge.w, gb.w);
                float4 sil;
                sil.x = t0 * __fdividef(1.0f, 1.0f + __expf(-t0));
                sil.y = t1 * __fdividef(1.0f, 1.0f + __expf(-t1));
                sil.z = t2f * __fdividef(1.0f, 1.0f + __expf(-t2f));
                sil.w = t3 * __fdividef(1.0f, 1.0f + __expf(-t3));
                *reinterpret_cast<float4*>(&P[row * 128 + 4 * lane]) = sil;

                s = sn; d = dn; q4 = qn; k4 = kn; v4 = vn;
            }
        }
        BARG(barid);

        // Phase C: y = eres + bev + silu (warps gw>=2 hold the Wev product)
        if (gw >= 2) {
            #pragma unroll
            for (int i = 0; i < 2; i++) {
                int rlo = i * 16 + g;
                int rhi = rlo + 8;
                #pragma unroll
                for (int j = 0; j < 8; j++) {
                    int colw = (gw & 1) * 64 + j * 8 + t2;
                    float2 o0, o1;
                    o0.x = acc[i][j][0] + bb[j].x + P[rlo * 128 + colw];
                    o0.y = acc[i][j][1] + bb[j].y + P[rlo * 128 + colw + 1];
                    o1.x = acc[i][j][2] + bb[j].x + P[rhi * 128 + colw];
                    o1.y = acc[i][j][3] + bb[j].y + P[rhi * 128 + colw + 1];
                    *reinterpret_cast<float2*>(&y_out[(size_t)(e0 + rlo) * 128 + colw]) = o0;
                    *reinterpret_cast<float2*>(&y_out[(size_t)(e0 + rhi) * 128 + colw]) = o1;
                }
            }
        }
        t += tstride;
        BARG(barid);             // P reads done -> buffer free for next convert

        if (t < ETILES32) convert_x32(xbuf, edge_feats, t * 32, gtid);
        BARG(barid);             // convert visible to all warps of the group
    }
}

// ---------------------------------------------------------------------------
// Node finalize: x = node_res + silu(LN_128(agg)), float4 lanes
// ---------------------------------------------------------------------------
__global__ __launch_bounds__(256) void node_kernel(
    const float* __restrict__ agg, const float* __restrict__ nres,
    const float* __restrict__ ln_ng, const float* __restrict__ ln_nb,
    float* __restrict__ x_out)
{
    int node = (blockIdx.x * blockDim.x + threadIdx.x) >> 5;
    int lane = threadIdx.x & 31;
    if (node >= NN) return;
    const unsigned FULL = 0xffffffffu;

    size_t base = (size_t)node * 128 + 4 * lane;
    float4 a = __ldg(reinterpret_cast<const float4*>(&agg[base]));

    float ls = a.x + a.y + a.z + a.w;
    float lq = a.x * a.x + a.y * a.y + a.z * a.z + a.w * a.w;
    #pragma unroll
    for (int off = 16; off > 0; off >>= 1) {
        ls += __shfl_xor_sync(FULL, ls, off);
        lq += __shfl_xor_sync(FULL, lq, off);
    }
    float mu  = ls * (1.0f / 128.0f);
    float var = lq * (1.0f / 128.0f) - mu * mu;
    float rs  = rsqrtf(var + LN_EPS);

    float4 g = __ldg(reinterpret_cast<const float4*>(&ln_ng[4 * lane]));
    float4 b = __ldg(reinterpret_cast<const float4*>(&ln_nb[4 * lane]));
    float4 r = __ldg(reinterpret_cast<const float4*>(&nres[base]));

    float t0 = fmaf((a.x - mu) * rs, g.x, b.x);
    float t1 = fmaf((a.y - mu) * rs, g.y, b.y);
    float t2 = fmaf((a.z - mu) * rs, g.z, b.z);
    float t3 = fmaf((a.w - mu) * rs, g.w, b.w);
    float4 o;
    o.x = t0 * __fdividef(1.0f, 1.0f + __expf(-t0)) + r.x;
    o.y = t1 * __fdividef(1.0f, 1.0f + __expf(-t1)) + r.y;
    o.z = t2 * __fdividef(1.0f, 1.0f + __expf(-t2)) + r.z;
    o.w = t3 * __fdividef(1.0f, 1.0f + __expf(-t3)) + r.w;
    *reinterpret_cast<float4*>(&x_out[base]) = o;
}

// ---------------------------------------------------------------------------
// Launch
// ---------------------------------------------------------------------------
extern "C" void kernel_launch(void* const* d_in, const int* in_sizes, int n_in,
                              void* d_out, int out_size)
{
    const float* node_feats = (const float*)d_in[0];
    const float* edge_feats = (const float*)d_in[1];
    const int*   src        = (const int*)d_in[2];
    const int*   dst        = (const int*)d_in[3];
    const float* Wq   = (const float*)d_in[4];
    const float* bq   = (const float*)d_in[5];
    const float* Wk   = (const float*)d_in[6];
    const float* bk   = (const float*)d_in[7];
    const float* Wv   = (const float*)d_in[8];
    const float* bv   = (const float*)d_in[9];
    const float* We   = (const float*)d_in[10];
    const float* be   = (const float*)d_in[11];
    const float* Wev  = (const float*)d_in[12];
    const float* bev  = (const float*)d_in[13];
    const float* Wout = (const float*)d_in[14];
    const float* bout = (const float*)d_in[15];
    const float* ln_ng = (const float*)d_in[16];
    const float* ln_nb = (const float*)d_in[17];
    const float* ln_eg = (const float*)d_in[18];
    const float* ln_eb = (const float*)d_in[19];

    float* scratch = nullptr;
    cudaGetSymbolAddress((void**)&scratch, g_scratch);
    float* q    = scratch;
    float* kk   = q    + (size_t)NN * 128;
    float* vv   = kk   + (size_t)NN * 128;
    float* nres = vv   + (size_t)NN * 128;
    float* agg  = nres + (size_t)NN * 128;

    float* x_out = (float*)d_out;
    float* y_out = x_out + (size_t)NN * 128;

    static bool attr_set = false;
    if (!attr_set) {
        cudaFuncSetAttribute(gemm_node, cudaFuncAttributeMaxDynamicSharedMemorySize, SMEM_GEMM);
        cudaFuncSetAttribute(edge_persist, cudaFuncAttributeMaxDynamicSharedMemorySize, SMEM_EDGE);
        attr_set = true;
    }

    int nsm = 148;
    cudaDeviceGetAttribute(&nsm, cudaDevAttrMultiProcessorCount, 0);

    // launch order: 0 prep_w, 1 zero, 2 gemm_node, 3 edge_persist, 4 node
    prep_w<<<48, 256>>>(Wq, Wk, Wv, Wout, We, Wev);
    zero_kernel<<<NN * 32 / 256, 256>>>(agg);
    gemm_node<<<2 * NBLK, 512, SMEM_GEMM>>>(
        node_feats, bq, bk, bv, bout, q, kk, vv, nres);
    edge_persist<<<nsm, 512, SMEM_EDGE>>>(
        edge_feats, be, bev, src, dst, q, kk, vv, ln_eg, ln_eb, agg, y_out);
    node_kernel<<<NN / 8, 256>>>(agg, nres, ln_ng, ln_nb, x_out);
}

// round 12
// speedup vs baseline: 1.7182x; 1.1346x over previous
#include <cuda_runtime.h>
#include <cuda_bf16.h>
#include <math.h>
#include <stdint.h>

#define NN 50000
#define EE 400000
#define NBLK 391            // ceil(NN/128) node tiles
#define ETILES32 12500      // EE/32 edge tiles
#define INV_SCALE 0.17677669529663687f   // 1/sqrt(32)
#define LN_EPS 1e-5f

// Scratch: q, k, v, nres, agg (5*N*128 = 32M floats)
__device__ float g_scratch[32000000];
// bf16 hi/lo swizzled weight tiles: 6 weights x (32KB hi + 32KB lo)
__device__ __align__(256) unsigned char g_wbf[6 * 65536];

// ---- node gemm smem layout ----
#define SW1HI 0
#define SW2HI 65536
#define SXHI  131072
#define SMEM_GEMM 196608
// ---- edge warp-specialized smem: W 128KB + X ring 2x16KB + P ring 2x32KB ----
#define EXR0  131072            // X ring (16KB per stage: hi 8K + lo 8K)
#define EPR0  163840            // P ring (32KB per stage: eproj 16K + eres 16K)
#define SMEM_EDGE_WS 229376

// Swizzled byte offset in a K-major bf16 tile (256B rows, 16B chunks,
// chunk ^= row&7 -> conflict-free for row-parallel and k-parallel access).
__device__ __forceinline__ int sw_off(int row, int col) {
    return row * 256 + ((((col >> 3) ^ (row & 7)) & 15) << 4) + (col & 7) * 2;
}

__device__ __forceinline__ uint32_t smem_u32(const void* p) {
    uint32_t a;
    asm("{ .reg .u64 t; cvta.to.shared.u64 t, %1; cvt.u32.u64 %0, t; }"
        : "=r"(a) : "l"(p));
    return a;
}

__device__ __forceinline__ void hmma(float* c, uint32_t a0, uint32_t a1,
                                     uint32_t a2, uint32_t a3,
                                     uint32_t b0, uint32_t b1) {
    asm("mma.sync.aligned.m16n8k16.row.col.f32.bf16.bf16.f32 "
        "{%0,%1,%2,%3}, {%4,%5,%6,%7}, {%8,%9}, {%0,%1,%2,%3};"
        : "+f"(c[0]), "+f"(c[1]), "+f"(c[2]), "+f"(c[3])
        : "r"(a0), "r"(a1), "r"(a2), "r"(a3), "r"(b0), "r"(b1));
}

#define LDSM_X4(r0, r1, r2, r3, addr) \
    asm volatile("ldmatrix.sync.aligned.m8n8.x4.shared.b16 {%0,%1,%2,%3}, [%4];" \
        : "=r"(r0), "=r"(r1), "=r"(r2), "=r"(r3) : "r"(addr))

__device__ __forceinline__ uint32_t pack_bf16x2(float a, float b) {
    uint32_t r;
    asm("cvt.rn.bf16x2.f32 %0, %1, %2;" : "=r"(r) : "f"(b), "f"(a));
    return r;
}

#define BAR_SYNC(id, cnt)   asm volatile("bar.sync %0, %1;"   :: "r"(id), "r"(cnt) : "memory")
#define BAR_ARRIVE(id, cnt) asm volatile("bar.arrive %0, %1;" :: "r"(id), "r"(cnt) : "memory")

// ---------------------------------------------------------------------------
// Weight prep: split 6 weights into bf16 hi(trunc)/lo swizzled tiles.
// ---------------------------------------------------------------------------
__global__ void prep_w(const float* __restrict__ W0, const float* __restrict__ W1,
                       const float* __restrict__ W2, const float* __restrict__ W3,
                       const float* __restrict__ W4, const float* __restrict__ W5)
{
    const float* W;
    switch (blockIdx.x >> 3) {
        case 0: W = W0; break; case 1: W = W1; break; case 2: W = W2; break;
        case 3: W = W3; break; case 4: W = W4; break; default: W = W5; break;
    }
    unsigned char* out = g_wbf + (size_t)(blockIdx.x >> 3) * 65536;
    int base = (blockIdx.x & 7) * 2048;
    for (int ii = threadIdx.x; ii < 2048; ii += blockDim.x) {
        int idx = base + ii;
        int row = idx >> 7, col = idx & 127;
        float x = W[idx];
        uint32_t xu = __float_as_uint(x);
        uint32_t hi = xu & 0xffff0000u;
        float lo = x - __uint_as_float(hi);
        __nv_bfloat16 lb = __float2bfloat16(lo);
        int off = sw_off(row, col);
        *reinterpret_cast<uint16_t*>(out + off) = (uint16_t)(hi >> 16);
        *reinterpret_cast<__nv_bfloat16*>(out + 32768 + off) = lb;
    }
}

__global__ void zero_kernel(float* __restrict__ p)
{
    int i = blockIdx.x * blockDim.x + threadIdx.x;
    reinterpret_cast<float4*>(p)[i] = make_float4(0.f, 0.f, 0.f, 0.f);
}

__device__ __forceinline__ void copy_weights_async(char* sm, int w1idx, int w2idx) {
    uint32_t d1 = smem_u32(sm + SW1HI);
    uint32_t d2 = smem_u32(sm + SW2HI);
    const char* s1 = reinterpret_cast<const char*>(g_wbf + (size_t)w1idx * 65536);
    const char* s2 = reinterpret_cast<const char*>(g_wbf + (size_t)w2idx * 65536);
    int tid = threadIdx.x;
    #pragma unroll
    for (int i = 0; i < 8; i++) {
        int j = (tid + i * 512) * 16;
        asm volatile("cp.async.cg.shared.global [%0], [%1], 16;"
                     :: "r"(d1 + j), "l"(s1 + j));
        asm volatile("cp.async.cg.shared.global [%0], [%1], 16;"
                     :: "r"(d2 + j), "l"(s2 + j));
    }
}

// ---------------------------------------------------------------------------
// Node-side convert (512 threads)
// ---------------------------------------------------------------------------
__device__ __forceinline__ void convert_x128(char* sm, const float* __restrict__ X,
                                             int m0, int M) {
    int tid = threadIdx.x;
    int r = tid >> 2;
    int ch = (tid & 3) * 32;
    bool valid = (m0 + r) < M;
    const float* xp = X + (size_t)(m0 + r) * 128 + ch;
    #pragma unroll
    for (int u = 0; u < 8; u++) {
        int c = ch + u * 4;
        float4 xv = make_float4(0.f, 0.f, 0.f, 0.f);
        if (valid) xv = __ldg(reinterpret_cast<const float4*>(xp + u * 4));
        uint32_t u0 = __float_as_uint(xv.x), u1 = __float_as_uint(xv.y);
        uint32_t u2 = __float_as_uint(xv.z), u3 = __float_as_uint(xv.w);
        uint32_t h01 = __byte_perm(u0, u1, 0x7632);
        uint32_t h23 = __byte_perm(u2, u3, 0x7632);
        float l0 = xv.x - __uint_as_float(u0 & 0xffff0000u);
        float l1 = xv.y - __uint_as_float(u1 & 0xffff0000u);
        float l2 = xv.z - __uint_as_float(u2 & 0xffff0000u);
        float l3 = xv.w - __uint_as_float(u3 & 0xffff0000u);
        int off = sw_off(r, c);
        *reinterpret_cast<uint2*>(sm + SXHI + off) = make_uint2(h01, h23);
        *reinterpret_cast<uint2*>(sm + SXHI + 32768 + off) =
            make_uint2(pack_bf16x2(l0, l1), pack_bf16x2(l2, l3));
    }
}

// Edge-side convert: 32-row tile into a 16KB stage buffer (128 threads)
__device__ __forceinline__ void convert_x32(char* xbuf, const float* __restrict__ X,
                                            int e0, int gtid) {
    int r = gtid >> 2;              // 0..31
    int ch = (gtid & 3) * 32;
    const float* xp = X + (size_t)(e0 + r) * 128 + ch;
    #pragma unroll
    for (int u = 0; u < 8; u++) {
        int c = ch + u * 4;
        float4 xv = __ldg(reinterpret_cast<const float4*>(xp + u * 4));
        uint32_t u0 = __float_as_uint(xv.x), u1 = __float_as_uint(xv.y);
        uint32_t u2 = __float_as_uint(xv.z), u3 = __float_as_uint(xv.w);
        uint32_t h01 = __byte_perm(u0, u1, 0x7632);
        uint32_t h23 = __byte_perm(u2, u3, 0x7632);
        float l0 = xv.x - __uint_as_float(u0 & 0xffff0000u);
        float l1 = xv.y - __uint_as_float(u1 & 0xffff0000u);
        float l2 = xv.z - __uint_as_float(u2 & 0xffff0000u);
        float l3 = xv.w - __uint_as_float(u3 & 0xffff0000u);
        int off = sw_off(r, c);     // < 8192 for r < 32
        *reinterpret_cast<uint2*>(xbuf + off) = make_uint2(h01, h23);
        *reinterpret_cast<uint2*>(xbuf + 8192 + off) =
            make_uint2(pack_bf16x2(l0, l1), pack_bf16x2(l2, l3));
    }
}

// ---------------------------------------------------------------------------
// Node MMA (16 warps, M=128): LDS.32 version (proven)
// ---------------------------------------------------------------------------
__device__ __forceinline__ void mma_tile128(const char* sm, float acc[2][8][4]) {
    const int lane = threadIdx.x & 31;
    const int wid  = threadIdx.x >> 5;
    const int wm = wid & 3, wn = wid >> 2;
    const int g  = lane >> 2;
    const int t4 = (lane & 3) * 4;

    const char* xhi = sm + SXHI;
    const char* xlo = sm + SXHI + 32768;
    const char* wh = sm + ((wn >= 2) ? SW2HI : SW1HI);
    const char* wl = wh + 32768;

    const int arow = (wm * 32 + g) * 256 + t4;
    const int brow = ((wn & 1) * 64 + g) * 256 + t4;

    #pragma unroll
    for (int i = 0; i < 2; i++)
        #pragma unroll
        for (int j = 0; j < 8; j++)
            #pragma unroll
            for (int r = 0; r < 4; r++) acc[i][j][r] = 0.f;

    #pragma unroll
    for (int ks = 0; ks < 8; ks++) {
        const int cx0 = (((2 * ks) ^ g) << 4);
        const int cx1 = (((2 * ks + 1) ^ g) << 4);
        uint32_t ah[2][4], al[2][4];
        #pragma unroll
        for (int i = 0; i < 2; i++) {
            int r0 = arow + i * 16 * 256;
            int r8 = r0 + 8 * 256;
            ah[i][0] = *reinterpret_cast<const uint32_t*>(xhi + r0 + cx0);
            ah[i][1] = *reinterpret_cast<const uint32_t*>(xhi + r8 + cx0);
            ah[i][2] = *reinterpret_cast<const uint32_t*>(xhi + r0 + cx1);
            ah[i][3] = *reinterpret_cast<const uint32_t*>(xhi + r8 + cx1);
            al[i][0] = *reinterpret_cast<const uint32_t*>(xlo + r0 + cx0);
            al[i][1] = *reinterpret_cast<const uint32_t*>(xlo + r8 + cx0);
            al[i][2] = *reinterpret_cast<const uint32_t*>(xlo + r0 + cx1);
            al[i][3] = *reinterpret_cast<const uint32_t*>(xlo + r8 + cx1);
        }
        #pragma unroll
        for (int j = 0; j < 8; j++) {
            int rb = brow + j * 8 * 256;
            uint32_t bh0 = *reinterpret_cast<const uint32_t*>(wh + rb + cx0);
            uint32_t bh1 = *reinterpret_cast<const uint32_t*>(wh + rb + cx1);
            uint32_t bl0 = *reinterpret_cast<const uint32_t*>(wl + rb + cx0);
            uint32_t bl1 = *reinterpret_cast<const uint32_t*>(wl + rb + cx1);
            #pragma unroll
            for (int i = 0; i < 2; i++) {
                hmma(acc[i][j], ah[i][0], ah[i][1], ah[i][2], ah[i][3], bh0, bh1);
                hmma(acc[i][j], al[i][0], al[i][1], al[i][2], al[i][3], bh0, bh1);
                hmma(acc[i][j], ah[i][0], ah[i][1], ah[i][2], ah[i][3], bl0, bl1);
            }
        }
    }
}

// ---------------------------------------------------------------------------
// 32-row tile MMA via ldmatrix (proven in R11): warp covers all 32 rows,
// N=64 of 256 combined cols selected by gw.
// ---------------------------------------------------------------------------
__device__ __forceinline__ void mma_tile32g(uint32_t smb, uint32_t xbuf,
                                            int gw, int lane,
                                            float acc[2][8][4]) {
    const int mi = lane >> 3;
    const int r  = lane & 7;
    const uint32_t xh = xbuf;
    const uint32_t xl = xbuf + 8192;
    const uint32_t wh = smb + ((gw >= 2) ? SW2HI : SW1HI);
    const uint32_t wl = wh + 32768;

    const uint32_t aro0 = (uint32_t)(((mi & 1) * 8 + r) * 256);
    const uint32_t aro1 = aro0 + 16 * 256;
    const int axc = mi >> 1;
    const int bxc = mi & 1;
    uint32_t bro[4];
    #pragma unroll
    for (int jp = 0; jp < 4; jp++)
        bro[jp] = (uint32_t)((((gw & 1) * 64) + (jp * 2 + (mi >> 1)) * 8 + r) * 256);

    #pragma unroll
    for (int i = 0; i < 2; i++)
        #pragma unroll
        for (int j = 0; j < 8; j++)
            #pragma unroll
            for (int rr = 0; rr < 4; rr++) acc[i][j][rr] = 0.f;

    #pragma unroll
    for (int ks = 0; ks < 8; ks++) {
        const uint32_t xA = (uint32_t)(((2 * ks + axc) ^ r) << 4);
        const uint32_t xB = (uint32_t)(((2 * ks + bxc) ^ r) << 4);
        uint32_t ah[8], al[8];
        LDSM_X4(ah[0], ah[1], ah[2], ah[3], xh + aro0 + xA);
        LDSM_X4(ah[4], ah[5], ah[6], ah[7], xh + aro1 + xA);
        LDSM_X4(al[0], al[1], al[2], al[3], xl + aro0 + xA);
        LDSM_X4(al[4], al[5], al[6], al[7], xl + aro1 + xA);
        #pragma unroll
        for (int jp = 0; jp < 4; jp++) {
            uint32_t bh[4], bl[4];
            LDSM_X4(bh[0], bh[1], bh[2], bh[3], wh + bro[jp] + xB);
            LDSM_X4(bl[0], bl[1], bl[2], bl[3], wl + bro[jp] + xB);
            const int j0 = jp * 2, j1 = jp * 2 + 1;
            hmma(acc[0][j0], ah[0], ah[1], ah[2], ah[3], bh[0], bh[1]);
            hmma(acc[0][j0], al[0], al[1], al[2], al[3], bh[0], bh[1]);
            hmma(acc[0][j0], ah[0], ah[1], ah[2], ah[3], bl[0], bl[1]);
            hmma(acc[0][j1], ah[0], ah[1], ah[2], ah[3], bh[2], bh[3]);
            hmma(acc[0][j1], al[0], al[1], al[2], al[3], bh[2], bh[3]);
            hmma(acc[0][j1], ah[0], ah[1], ah[2], ah[3], bl[2], bl[3]);
            hmma(acc[1][j0], ah[4], ah[5], ah[6], ah[7], bh[0], bh[1]);
            hmma(acc[1][j0], al[4], al[5], al[6], al[7], bh[0], bh[1]);
            hmma(acc[1][j0], ah[4], ah[5], ah[6], ah[7], bl[0], bl[1]);
            hmma(acc[1][j1], ah[4], ah[5], ah[6], ah[7], bh[2], bh[3]);
            hmma(acc[1][j1], al[4], al[5], al[6], al[7], bh[2], bh[3]);
            hmma(acc[1][j1], ah[4], ah[5], ah[6], ah[7], bl[2], bl[3]);
        }
    }
}

// ---------------------------------------------------------------------------
// Node GEMMs merged (unchanged, proven)
// ---------------------------------------------------------------------------
__global__ __launch_bounds__(512, 1) void gemm_node(
    const float* __restrict__ X,
    const float* __restrict__ bq, const float* __restrict__ bk,
    const float* __restrict__ bv, const float* __restrict__ bout,
    float* __restrict__ q, float* __restrict__ kk,
    float* __restrict__ vv, float* __restrict__ nres)
{
    extern __shared__ char sm[];
    const int half = blockIdx.x / NBLK;
    const int tile = blockIdx.x % NBLK;
    const int m0 = tile * 128;
    const float* b1 = half ? bv : bq;
    const float* b2 = half ? bout : bk;
    float* Y1 = half ? vv : q;
    float* Y2 = half ? nres : kk;

    copy_weights_async(sm, half * 2, half * 2 + 1);
    asm volatile("cp.async.commit_group;");
    convert_x128(sm, X, m0, NN);
    asm volatile("cp.async.wait_group 0;");
    __syncthreads();

    float acc[2][8][4];
    mma_tile128(sm, acc);

    const int lane = threadIdx.x & 31;
    const int wid  = threadIdx.x >> 5;
    const int wm = wid & 3, wn = wid >> 2;
    const int g = lane >> 2, t2 = (lane & 3) * 2;

    const float* bias = (wn >= 2) ? b2 : b1;
    float* Y = (wn >= 2) ? Y2 : Y1;
    float2 bb[8];
    #pragma unroll
    for (int j = 0; j < 8; j++) {
        int colw = (wn & 1) * 64 + j * 8 + t2;
        bb[j] = *reinterpret_cast<const float2*>(&bias[colw]);
    }
    #pragma unroll
    for (int i = 0; i < 2; i++) {
        int rlo = m0 + wm * 32 + i * 16 + g;
        int rhi = rlo + 8;
        #pragma unroll
        for (int j = 0; j < 8; j++) {
            int colw = (wn & 1) * 64 + j * 8 + t2;
            if (rlo < NN) {
                float2 o = make_float2(acc[i][j][0] + bb[j].x, acc[i][j][1] + bb[j].y);
                *reinterpret_cast<float2*>(&Y[(size_t)rlo * 128 + colw]) = o;
            }
            if (rhi < NN) {
                float2 o = make_float2(acc[i][j][2] + bb[j].x, acc[i][j][3] + bb[j].y);
                *reinterpret_cast<float2*>(&Y[(size_t)rhi * 128 + colw]) = o;
            }
        }
    }
}

// ---------------------------------------------------------------------------
// Warp-specialized persistent edge kernel.
//   wid 0-3   : MMA warps (one per SMSP). LDSM+HMMA+P-store only.
//   wid 4-11  : edge-math warps (4 edges each per 32-edge tile) + y store.
//   wid 12-15 : convert warps (X fp32 -> bf16 hi/lo staging).
// Rings: X 2x16KB (EXR0), P 2x32KB (EPR0: eproj 16K | eres 16K), biases folded.
// Barriers: XFULL s -> id 1+s (cnt 256), XEMPTY s -> 3+s (256),
//           PFULL s -> 5+s (384), PEMPTY s -> 7+s (384).
// ---------------------------------------------------------------------------
__global__ __launch_bounds__(512, 1) void edge_ws(
    const float* __restrict__ edge_feats,
    const float* __restrict__ be, const float* __restrict__ bev,
    const int* __restrict__ src, const int* __restrict__ dst,
    const float* __restrict__ q, const float* __restrict__ k,
    const float* __restrict__ v,
    const float* __restrict__ ln_eg, const float* __restrict__ ln_eb,
    float* __restrict__ agg, float* __restrict__ y_out)
{
    extern __shared__ char sm[];
    const uint32_t smb = smem_u32(sm);
    const int tid  = threadIdx.x;
    const int lane = tid & 31;
    const int wid  = tid >> 5;
    const unsigned FULL = 0xffffffffu;

    copy_weights_async(sm, 4, 5);      // We, Wev
    asm volatile("cp.async.commit_group;");
    asm volatile("cp.async.wait_group 0;");
    __syncthreads();

    int it = 0;
    if (wid >= 12) {
        // ---------------- convert warps ----------------
        const int gtid = tid - 384;    // 0..127
        for (int t = blockIdx.x; t < ETILES32; t += gridDim.x, ++it) {
            const int s = it & 1;
            if (it >= 2) BAR_SYNC(3 + s, 256);
            convert_x32(sm + EXR0 + s * 16384, edge_feats, t * 32, gtid);
            BAR_ARRIVE(1 + s, 256);
        }
    } else if (wid < 4) {
        // ---------------- MMA warps ----------------
        const int gw = wid;
        const float* bias = (gw >= 2) ? bev : be;
        const int g = lane >> 2, t2 = (lane & 3) * 2;
        float2 bb[8];
        #pragma unroll
        for (int j = 0; j < 8; j++) {
            int colw = (gw & 1) * 64 + j * 8 + t2;
            bb[j] = *reinterpret_cast<const float2*>(&bias[colw]);
        }
        for (int t = blockIdx.x; t < ETILES32; t += gridDim.x, ++it) {
            const int s = it & 1;
            BAR_SYNC(1 + s, 256);
            float acc[2][8][4];
            mma_tile32g(smb, smb + EXR0 + s * 16384, gw, lane, acc);
            BAR_ARRIVE(3 + s, 256);
            if (it >= 2) BAR_SYNC(7 + s, 384);
            float* Pp = reinterpret_cast<float*>(
                sm + EPR0 + s * 32768 + ((gw >= 2) ? 16384 : 0));
            #pragma unroll
            for (int i = 0; i < 2; i++) {
                int rlo = i * 16 + g;
                int rhi = rlo + 8;
                #pragma unroll
                for (int j = 0; j < 8; j++) {
                    int colw = (gw & 1) * 64 + j * 8 + t2;
                    Pp[rlo * 128 + colw]     = acc[i][j][0] + bb[j].x;
                    Pp[rlo * 128 + colw + 1] = acc[i][j][1] + bb[j].y;
                    Pp[rhi * 128 + colw]     = acc[i][j][2] + bb[j].x;
                    Pp[rhi * 128 + colw + 1] = acc[i][j][3] + bb[j].y;
                }
            }
            BAR_ARRIVE(5 + s, 384);
        }
    } else {
        // ---------------- edge-math warps ----------------
        const int ew = wid - 4;        // 0..7
        const int rbase = ew * 4;
        float4 ge = *reinterpret_cast<const float4*>(&ln_eg[4 * lane]);
        float4 gb = *reinterpret_cast<const float4*>(&ln_eb[4 * lane]);
        for (int t = blockIdx.x; t < ETILES32; t += gridDim.x, ++it) {
            const int s = it & 1;
            const int e0 = t * 32;
            // preload 4 src (lanes 0-3) + 4 dst (lanes 4-7) indices
            int sd = 0;
            if (lane < 8)
                sd = __ldg(((lane < 4) ? src : dst) + e0 + rbase + (lane & 3));
            int se[4], de[4];
            #pragma unroll
            for (int e = 0; e < 4; e++) {
                se[e] = __shfl_sync(FULL, sd, e);
                de[e] = __shfl_sync(FULL, sd, e + 4);
            }
            // gather q/k/v for all 4 edges up front (MLP)
            float4 Q[4], K[4], V[4];
            #pragma unroll
            for (int e = 0; e < 4; e++) {
                Q[e] = __ldg(reinterpret_cast<const float4*>(&q[(size_t)se[e] * 128 + 4 * lane]));
                K[e] = __ldg(reinterpret_cast<const float4*>(&k[(size_t)de[e] * 128 + 4 * lane]));
                V[e] = __ldg(reinterpret_cast<const float4*>(&v[(size_t)se[e] * 128 + 4 * lane]));
            }
            BAR_SYNC(5 + s, 384);
            const float* Pe = reinterpret_cast<const float*>(sm + EPR0 + s * 32768);
            const float* Pr = Pe + 4096;   // eres plane (16KB / 4)
            #pragma unroll
            for (int e = 0; e < 4; e++) {
                int row = rbase + e;
                float pd = Q[e].x * K[e].x + Q[e].y * K[e].y
                         + Q[e].z * K[e].z + Q[e].w * K[e].w;
                pd += __shfl_xor_sync(FULL, pd, 1);
                pd += __shfl_xor_sync(FULL, pd, 2);
                pd += __shfl_xor_sync(FULL, pd, 4);

                float4 m4 = *reinterpret_cast<const float4*>(&Pe[row * 128 + 4 * lane]);
                m4.x = fmaf(pd, INV_SCALE, m4.x);
                m4.y = fmaf(pd, INV_SCALE, m4.y);
                m4.z = fmaf(pd, INV_SCALE, m4.z);
                m4.w = fmaf(pd, INV_SCALE, m4.w);

                // softmax over 4 heads (partners lane^8, lane^16); |m| small
                float4 ex;
                ex.x = __expf(m4.x); ex.y = __expf(m4.y);
                ex.z = __expf(m4.z); ex.w = __expf(m4.w);
                float4 sx = ex;
                #pragma unroll
                for (int off = 8; off <= 16; off <<= 1) {
                    sx.x += __shfl_xor_sync(FULL, sx.x, off);
                    sx.y += __shfl_xor_sync(FULL, sx.y, off);
                    sx.z += __shfl_xor_sync(FULL, sx.z, off);
                    sx.w += __shfl_xor_sync(FULL, sx.w, off);
                }
                float4 msg;
                msg.x = V[e].x * ex.x * __fdividef(1.0f, sx.x);
                msg.y = V[e].y * ex.y * __fdividef(1.0f, sx.y);
                msg.z = V[e].z * ex.z * __fdividef(1.0f, sx.z);
                msg.w = V[e].w * ex.w * __fdividef(1.0f, sx.w);
                float* ap = &agg[(size_t)de[e] * 128 + 4 * lane];
                asm volatile("red.global.add.v4.f32 [%0], {%1, %2, %3, %4};"
                             :: "l"(ap), "f"(msg.x), "f"(msg.y), "f"(msg.z), "f"(msg.w)
                             : "memory");

                // layernorm over 128 cols
                float ls = m4.x + m4.y + m4.z + m4.w;
                float lq = m4.x * m4.x + m4.y * m4.y + m4.z * m4.z + m4.w * m4.w;
                #pragma unroll
                for (int off = 16; off > 0; off >>= 1) {
                    ls += __shfl_xor_sync(FULL, ls, off);
                    lq += __shfl_xor_sync(FULL, lq, off);
                }
                float mu = ls * (1.0f / 128.0f);
                float var = lq * (1.0f / 128.0f) - mu * mu;
                float rs = rsqrtf(var + LN_EPS);

                float t0 = fmaf((m4.x - mu) * rs, ge.x, gb.x);
                float t1 = fmaf((m4.y - mu) * rs, ge.y, gb.y);
                float t2f = fmaf((m4.z - mu) * rs, ge.z, gb.z);
                float t3 = fmaf((m4.w - mu) * rs, ge.w, gb.w);
                float4 er = *reinterpret_cast<const float4*>(&Pr[row * 128 + 4 * lane]);
                float4 o;
                o.x = t0 * __fdividef(1.0f, 1.0f + __expf(-t0)) + er.x;
                o.y = t1 * __fdividef(1.0f, 1.0f + __expf(-t1)) + er.y;
                o.z = t2f * __fdividef(1.0f, 1.0f + __expf(-t2f)) + er.z;
                o.w = t3 * __fdividef(1.0f, 1.0f + __expf(-t3)) + er.w;
                *reinterpret_cast<float4*>(&y_out[(size_t)(e0 + row) * 128 + 4 * lane]) = o;
            }
            BAR_ARRIVE(7 + s, 384);
        }
    }
}

// ---------------------------------------------------------------------------
// Node finalize (unchanged)
// ---------------------------------------------------------------------------
__global__ __launch_bounds__(256) void node_kernel(
    const float* __restrict__ agg, const float* __restrict__ nres,
    const float* __restrict__ ln_ng, const float* __restrict__ ln_nb,
    float* __restrict__ x_out)
{
    int node = (blockIdx.x * blockDim.x + threadIdx.x) >> 5;
    int lane = threadIdx.x & 31;
    if (node >= NN) return;
    const unsigned FULL = 0xffffffffu;

    size_t base = (size_t)node * 128 + 4 * lane;
    float4 a = __ldg(reinterpret_cast<const float4*>(&agg[base]));

    float ls = a.x + a.y + a.z + a.w;
    float lq = a.x * a.x + a.y * a.y + a.z * a.z + a.w * a.w;
    #pragma unroll
    for (int off = 16; off > 0; off >>= 1) {
        ls += __shfl_xor_sync(FULL, ls, off);
        lq += __shfl_xor_sync(FULL, lq, off);
    }
    float mu  = ls * (1.0f / 128.0f);
    float var = lq * (1.0f / 128.0f) - mu * mu;
    float rs  = rsqrtf(var + LN_EPS);

    float4 g = __ldg(reinterpret_cast<const float4*>(&ln_ng[4 * lane]));
    float4 b = __ldg(reinterpret_cast<const float4*>(&ln_nb[4 * lane]));
    float4 r = __ldg(reinterpret_cast<const float4*>(&nres[base]));

    float t0 = fmaf((a.x - mu) * rs, g.x, b.x);
    float t1 = fmaf((a.y - mu) * rs, g.y, b.y);
    float t2 = fmaf((a.z - mu) * rs, g.z, b.z);
    float t3 = fmaf((a.w - mu) * rs, g.w, b.w);
    float4 o;
    o.x = t0 * __fdividef(1.0f, 1.0f + __expf(-t0)) + r.x;
    o.y = t1 * __fdividef(1.0f, 1.0f + __expf(-t1)) + r.y;
    o.z = t2 * __fdividef(1.0f, 1.0f + __expf(-t2)) + r.z;
    o.w = t3 * __fdividef(1.0f, 1.0f + __expf(-t3)) + r.w;
    *reinterpret_cast<float4*>(&x_out[base]) = o;
}

// ---------------------------------------------------------------------------
// Launch
// ---------------------------------------------------------------------------
extern "C" void kernel_launch(void* const* d_in, const int* in_sizes, int n_in,
                              void* d_out, int out_size)
{
    const float* node_feats = (const float*)d_in[0];
    const float* edge_feats = (const float*)d_in[1];
    const int*   src        = (const int*)d_in[2];
    const int*   dst        = (const int*)d_in[3];
    const float* Wq   = (const float*)d_in[4];
    const float* bq   = (const float*)d_in[5];
    const float* Wk   = (const float*)d_in[6];
    const float* bk   = (const float*)d_in[7];
    const float* Wv   = (const float*)d_in[8];
    const float* bv   = (const float*)d_in[9];
    const float* We   = (const float*)d_in[10];
    const float* be   = (const float*)d_in[11];
    const float* Wev  = (const float*)d_in[12];
    const float* bev  = (const float*)d_in[13];
    const float* Wout = (const float*)d_in[14];
    const float* bout = (const float*)d_in[15];
    const float* ln_ng = (const float*)d_in[16];
    const float* ln_nb = (const float*)d_in[17];
    const float* ln_eg = (const float*)d_in[18];
    const float* ln_eb = (const float*)d_in[19];

    float* scratch = nullptr;
    cudaGetSymbolAddress((void**)&scratch, g_scratch);
    float* q    = scratch;
    float* kk   = q    + (size_t)NN * 128;
    float* vv   = kk   + (size_t)NN * 128;
    float* nres = vv   + (size_t)NN * 128;
    float* agg  = nres + (size_t)NN * 128;

    float* x_out = (float*)d_out;
    float* y_out = x_out + (size_t)NN * 128;

    static bool attr_set = false;
    if (!attr_set) {
        cudaFuncSetAttribute(gemm_node, cudaFuncAttributeMaxDynamicSharedMemorySize, SMEM_GEMM);
        cudaFuncSetAttribute(edge_ws, cudaFuncAttributeMaxDynamicSharedMemorySize, SMEM_EDGE_WS);
        attr_set = true;
    }

    int nsm = 148;
    cudaDeviceGetAttribute(&nsm, cudaDevAttrMultiProcessorCount, 0);

    // launch order: 0 prep_w, 1 zero, 2 gemm_node, 3 edge_ws, 4 node
    prep_w<<<48, 256>>>(Wq, Wk, Wv, Wout, We, Wev);
    zero_kernel<<<NN * 32 / 256, 256>>>(agg);
    gemm_node<<<2 * NBLK, 512, SMEM_GEMM>>>(
        node_feats, bq, bk, bv, bout, q, kk, vv, nres);
    edge_ws<<<nsm, 512, SMEM_EDGE_WS>>>(
        edge_feats, be, bev, src, dst, q, kk, vv, ln_eg, ln_eb, agg, y_out);
    node_kernel<<<NN / 8, 256>>>(agg, nres, ln_ng, ln_nb, x_out);
}

// round 13
// speedup vs baseline: 1.9353x; 1.1264x over previous
#include <cuda_runtime.h>
#include <cuda_bf16.h>
#include <cuda_fp16.h>
#include <math.h>
#include <stdint.h>

#define NN 50000
#define EE 400000
#define NBLK 391            // ceil(NN/128) node tiles
#define ETILES32 12500      // EE/32 edge tiles
#define INV_SCALE 0.17677669529663687f   // 1/sqrt(32)
#define LN_EPS 1e-5f

// Scratch: q, k, v, nres, agg (5*N*128 = 32M floats)
__device__ float g_scratch[32000000];
// fp16 swizzled weight tiles: 6 weights x 32KB
__device__ __align__(256) unsigned char g_wbf[6 * 32768];

// ---- node gemm smem layout ----
#define SW1HI 0
#define SW2HI 32768
#define SXHI  65536              // X hi 32KB, lo at +32768
#define SMEM_GEMM 131072
// ---- edge warp-specialized smem: W 64KB + X ring 3x16KB + P ring 2x32KB ----
#define EXR0  65536              // X ring (16KB/stage: hi 8K + lo 8K)
#define EPR0  114688             // P ring (32KB/stage: eproj 16K + eres 16K)
#define SMEM_EDGE_WS 180224

// Swizzled byte offset in a K-major fp16 tile (256B rows, 16B chunks,
// chunk ^= row&7 -> conflict-free for row-parallel and k-parallel access).
__device__ __forceinline__ int sw_off(int row, int col) {
    return row * 256 + ((((col >> 3) ^ (row & 7)) & 15) << 4) + (col & 7) * 2;
}

__device__ __forceinline__ uint32_t smem_u32(const void* p) {
    uint32_t a;
    asm("{ .reg .u64 t; cvta.to.shared.u64 t, %1; cvt.u32.u64 %0, t; }"
        : "=r"(a) : "l"(p));
    return a;
}

__device__ __forceinline__ void hmma(float* c, uint32_t a0, uint32_t a1,
                                     uint32_t a2, uint32_t a3,
                                     uint32_t b0, uint32_t b1) {
    asm("mma.sync.aligned.m16n8k16.row.col.f32.f16.f16.f32 "
        "{%0,%1,%2,%3}, {%4,%5,%6,%7}, {%8,%9}, {%0,%1,%2,%3};"
        : "+f"(c[0]), "+f"(c[1]), "+f"(c[2]), "+f"(c[3])
        : "r"(a0), "r"(a1), "r"(a2), "r"(a3), "r"(b0), "r"(b1));
}

#define LDSM_X4(r0, r1, r2, r3, addr) \
    asm volatile("ldmatrix.sync.aligned.m8n8.x4.shared.b16 {%0,%1,%2,%3}, [%4];" \
        : "=r"(r0), "=r"(r1), "=r"(r2), "=r"(r3) : "r"(addr))

// pack two f32 -> f16x2 {low=a, high=b} (rn)
__device__ __forceinline__ uint32_t pack_f16x2(float a, float b) {
    uint32_t r;
    asm("cvt.rn.f16x2.f32 %0, %1, %2;" : "=r"(r) : "f"(b), "f"(a));
    return r;
}

#define BAR_SYNC(id, cnt)   asm volatile("bar.sync %0, %1;"   :: "r"(id), "r"(cnt) : "memory")
#define BAR_ARRIVE(id, cnt) asm volatile("bar.arrive %0, %1;" :: "r"(id), "r"(cnt) : "memory")

// ---------------------------------------------------------------------------
// Weight prep: fp16(rn) swizzled tiles. 48 blocks: weight = bx>>3.
// ---------------------------------------------------------------------------
__global__ void prep_w(const float* __restrict__ W0, const float* __restrict__ W1,
                       const float* __restrict__ W2, const float* __restrict__ W3,
                       const float* __restrict__ W4, const float* __restrict__ W5)
{
    const float* W;
    switch (blockIdx.x >> 3) {
        case 0: W = W0; break; case 1: W = W1; break; case 2: W = W2; break;
        case 3: W = W3; break; case 4: W = W4; break; default: W = W5; break;
    }
    unsigned char* out = g_wbf + (size_t)(blockIdx.x >> 3) * 32768;
    int base = (blockIdx.x & 7) * 2048;
    for (int ii = threadIdx.x; ii < 2048; ii += blockDim.x) {
        int idx = base + ii;
        int row = idx >> 7, col = idx & 127;
        __half h = __float2half_rn(W[idx]);
        *reinterpret_cast<uint16_t*>(out + sw_off(row, col)) = __half_as_ushort(h);
    }
}

__global__ void zero_kernel(float* __restrict__ p)
{
    int i = blockIdx.x * blockDim.x + threadIdx.x;
    reinterpret_cast<float4*>(p)[i] = make_float4(0.f, 0.f, 0.f, 0.f);
}

// 64KB weight staging (both weights), 512 threads
__device__ __forceinline__ void copy_weights_async(char* sm, int w1idx, int w2idx) {
    uint32_t d1 = smem_u32(sm + SW1HI);
    uint32_t d2 = smem_u32(sm + SW2HI);
    const char* s1 = reinterpret_cast<const char*>(g_wbf + (size_t)w1idx * 32768);
    const char* s2 = reinterpret_cast<const char*>(g_wbf + (size_t)w2idx * 32768);
    int tid = threadIdx.x;
    #pragma unroll
    for (int i = 0; i < 4; i++) {
        int j = (tid + i * 512) * 16;
        asm volatile("cp.async.cg.shared.global [%0], [%1], 16;"
                     :: "r"(d1 + j), "l"(s1 + j));
        asm volatile("cp.async.cg.shared.global [%0], [%1], 16;"
                     :: "r"(d2 + j), "l"(s2 + j));
    }
}

// ---------------------------------------------------------------------------
// Converts: fp32 -> fp16 hi + fp16 lo (lo = x - float(hi)), swizzled planes
// ---------------------------------------------------------------------------
__device__ __forceinline__ void cvt_split4(float4 xv, uint2& hi, uint2& lo) {
    __half h0 = __float2half_rn(xv.x), h1 = __float2half_rn(xv.y);
    __half h2 = __float2half_rn(xv.z), h3 = __float2half_rn(xv.w);
    uint32_t hp01, hp23;
    asm("mov.b32 %0, {%1, %2};" : "=r"(hp01)
        : "h"(__half_as_ushort(h0)), "h"(__half_as_ushort(h1)));
    asm("mov.b32 %0, {%1, %2};" : "=r"(hp23)
        : "h"(__half_as_ushort(h2)), "h"(__half_as_ushort(h3)));
    float l0 = xv.x - __half2float(h0);
    float l1 = xv.y - __half2float(h1);
    float l2 = xv.z - __half2float(h2);
    float l3 = xv.w - __half2float(h3);
    hi = make_uint2(hp01, hp23);
    lo = make_uint2(pack_f16x2(l0, l1), pack_f16x2(l2, l3));
}

// Node-side: 128-row tile (512 threads)
__device__ __forceinline__ void convert_x128(char* sm, const float* __restrict__ X,
                                             int m0, int M) {
    int tid = threadIdx.x;
    int r = tid >> 2;
    int ch = (tid & 3) * 32;
    bool valid = (m0 + r) < M;
    const float* xp = X + (size_t)(m0 + r) * 128 + ch;
    #pragma unroll
    for (int u = 0; u < 8; u++) {
        int c = ch + u * 4;
        float4 xv = make_float4(0.f, 0.f, 0.f, 0.f);
        if (valid) xv = __ldg(reinterpret_cast<const float4*>(xp + u * 4));
        uint2 hi, lo;
        cvt_split4(xv, hi, lo);
        int off = sw_off(r, c);
        *reinterpret_cast<uint2*>(sm + SXHI + off) = hi;
        *reinterpret_cast<uint2*>(sm + SXHI + 32768 + off) = lo;
    }
}

// Edge-side: 32-row tile into a 16KB stage (128 threads)
__device__ __forceinline__ void convert_x32(char* xbuf, const float* __restrict__ X,
                                            int e0, int gtid) {
    int r = gtid >> 2;              // 0..31
    int ch = (gtid & 3) * 32;
    const float* xp = X + (size_t)(e0 + r) * 128 + ch;
    #pragma unroll
    for (int u = 0; u < 8; u++) {
        int c = ch + u * 4;
        float4 xv = __ldg(reinterpret_cast<const float4*>(xp + u * 4));
        uint2 hi, lo;
        cvt_split4(xv, hi, lo);
        int off = sw_off(r, c);     // < 8192 for r < 32
        *reinterpret_cast<uint2*>(xbuf + off) = hi;
        *reinterpret_cast<uint2*>(xbuf + 8192 + off) = lo;
    }
}

// ---------------------------------------------------------------------------
// Node MMA (16 warps, M=128), fp16 2-term
// ---------------------------------------------------------------------------
__device__ __forceinline__ void mma_tile128(const char* sm, float acc[2][8][4]) {
    const int lane = threadIdx.x & 31;
    const int wid  = threadIdx.x >> 5;
    const int wm = wid & 3, wn = wid >> 2;
    const int g  = lane >> 2;
    const int t4 = (lane & 3) * 4;

    const char* xhi = sm + SXHI;
    const char* xlo = sm + SXHI + 32768;
    const char* wh = sm + ((wn >= 2) ? SW2HI : SW1HI);

    const int arow = (wm * 32 + g) * 256 + t4;
    const int brow = ((wn & 1) * 64 + g) * 256 + t4;

    #pragma unroll
    for (int i = 0; i < 2; i++)
        #pragma unroll
        for (int j = 0; j < 8; j++)
            #pragma unroll
            for (int r = 0; r < 4; r++) acc[i][j][r] = 0.f;

    #pragma unroll
    for (int ks = 0; ks < 8; ks++) {
        const int cx0 = (((2 * ks) ^ g) << 4);
        const int cx1 = (((2 * ks + 1) ^ g) << 4);
        uint32_t ah[2][4], al[2][4];
        #pragma unroll
        for (int i = 0; i < 2; i++) {
            int r0 = arow + i * 16 * 256;
            int r8 = r0 + 8 * 256;
            ah[i][0] = *reinterpret_cast<const uint32_t*>(xhi + r0 + cx0);
            ah[i][1] = *reinterpret_cast<const uint32_t*>(xhi + r8 + cx0);
            ah[i][2] = *reinterpret_cast<const uint32_t*>(xhi + r0 + cx1);
            ah[i][3] = *reinterpret_cast<const uint32_t*>(xhi + r8 + cx1);
            al[i][0] = *reinterpret_cast<const uint32_t*>(xlo + r0 + cx0);
            al[i][1] = *reinterpret_cast<const uint32_t*>(xlo + r8 + cx0);
            al[i][2] = *reinterpret_cast<const uint32_t*>(xlo + r0 + cx1);
            al[i][3] = *reinterpret_cast<const uint32_t*>(xlo + r8 + cx1);
        }
        #pragma unroll
        for (int j = 0; j < 8; j++) {
            int rb = brow + j * 8 * 256;
            uint32_t bh0 = *reinterpret_cast<const uint32_t*>(wh + rb + cx0);
            uint32_t bh1 = *reinterpret_cast<const uint32_t*>(wh + rb + cx1);
            #pragma unroll
            for (int i = 0; i < 2; i++) {
                hmma(acc[i][j], ah[i][0], ah[i][1], ah[i][2], ah[i][3], bh0, bh1);
                hmma(acc[i][j], al[i][0], al[i][1], al[i][2], al[i][3], bh0, bh1);
            }
        }
    }
}

// ---------------------------------------------------------------------------
// 32-row tile MMA via ldmatrix, fp16 2-term (layout proven in R11/12)
// ---------------------------------------------------------------------------
__device__ __forceinline__ void mma_tile32g(uint32_t smb, uint32_t xbuf,
                                            int gw, int lane,
                                            float acc[2][8][4]) {
    const int mi = lane >> 3;
    const int r  = lane & 7;
    const uint32_t xh = xbuf;
    const uint32_t xl = xbuf + 8192;
    const uint32_t wh = smb + ((gw >= 2) ? SW2HI : SW1HI);

    const uint32_t aro0 = (uint32_t)(((mi & 1) * 8 + r) * 256);
    const uint32_t aro1 = aro0 + 16 * 256;
    const int axc = mi >> 1;
    const int bxc = mi & 1;
    uint32_t bro[4];
    #pragma unroll
    for (int jp = 0; jp < 4; jp++)
        bro[jp] = (uint32_t)((((gw & 1) * 64) + (jp * 2 + (mi >> 1)) * 8 + r) * 256);

    #pragma unroll
    for (int i = 0; i < 2; i++)
        #pragma unroll
        for (int j = 0; j < 8; j++)
            #pragma unroll
            for (int rr = 0; rr < 4; rr++) acc[i][j][rr] = 0.f;

    #pragma unroll
    for (int ks = 0; ks < 8; ks++) {
        const uint32_t xA = (uint32_t)(((2 * ks + axc) ^ r) << 4);
        const uint32_t xB = (uint32_t)(((2 * ks + bxc) ^ r) << 4);
        uint32_t ah[8], al[8];
        LDSM_X4(ah[0], ah[1], ah[2], ah[3], xh + aro0 + xA);
        LDSM_X4(ah[4], ah[5], ah[6], ah[7], xh + aro1 + xA);
        LDSM_X4(al[0], al[1], al[2], al[3], xl + aro0 + xA);
        LDSM_X4(al[4], al[5], al[6], al[7], xl + aro1 + xA);
        #pragma unroll
        for (int jp = 0; jp < 4; jp++) {
            uint32_t bh[4];
            LDSM_X4(bh[0], bh[1], bh[2], bh[3], wh + bro[jp] + xB);
            const int j0 = jp * 2, j1 = jp * 2 + 1;
            hmma(acc[0][j0], ah[0], ah[1], ah[2], ah[3], bh[0], bh[1]);
            hmma(acc[0][j0], al[0], al[1], al[2], al[3], bh[0], bh[1]);
            hmma(acc[0][j1], ah[0], ah[1], ah[2], ah[3], bh[2], bh[3]);
            hmma(acc[0][j1], al[0], al[1], al[2], al[3], bh[2], bh[3]);
            hmma(acc[1][j0], ah[4], ah[5], ah[6], ah[7], bh[0], bh[1]);
            hmma(acc[1][j0], al[4], al[5], al[6], al[7], bh[0], bh[1]);
            hmma(acc[1][j1], ah[4], ah[5], ah[6], ah[7], bh[2], bh[3]);
            hmma(acc[1][j1], al[4], al[5], al[6], al[7], bh[2], bh[3]);
        }
    }
}

// ---------------------------------------------------------------------------
// Node GEMMs merged
// ---------------------------------------------------------------------------
__global__ __launch_bounds__(512, 1) void gemm_node(
    const float* __restrict__ X,
    const float* __restrict__ bq, const float* __restrict__ bk,
    const float* __restrict__ bv, const float* __restrict__ bout,
    float* __restrict__ q, float* __restrict__ kk,
    float* __restrict__ vv, float* __restrict__ nres)
{
    extern __shared__ char sm[];
    const int half = blockIdx.x / NBLK;
    const int tile = blockIdx.x % NBLK;
    const int m0 = tile * 128;
    const float* b1 = half ? bv : bq;
    const float* b2 = half ? bout : bk;
    float* Y1 = half ? vv : q;
    float* Y2 = half ? nres : kk;

    copy_weights_async(sm, half * 2, half * 2 + 1);
    asm volatile("cp.async.commit_group;");
    convert_x128(sm, X, m0, NN);
    asm volatile("cp.async.wait_group 0;");
    __syncthreads();

    float acc[2][8][4];
    mma_tile128(sm, acc);

    const int lane = threadIdx.x & 31;
    const int wid  = threadIdx.x >> 5;
    const int wm = wid & 3, wn = wid >> 2;
    const int g = lane >> 2, t2 = (lane & 3) * 2;

    const float* bias = (wn >= 2) ? b2 : b1;
    float* Y = (wn >= 2) ? Y2 : Y1;
    float2 bb[8];
    #pragma unroll
    for (int j = 0; j < 8; j++) {
        int colw = (wn & 1) * 64 + j * 8 + t2;
        bb[j] = *reinterpret_cast<const float2*>(&bias[colw]);
    }
    #pragma unroll
    for (int i = 0; i < 2; i++) {
        int rlo = m0 + wm * 32 + i * 16 + g;
        int rhi = rlo + 8;
        #pragma unroll
        for (int j = 0; j < 8; j++) {
            int colw = (wn & 1) * 64 + j * 8 + t2;
            if (rlo < NN) {
                float2 o = make_float2(acc[i][j][0] + bb[j].x, acc[i][j][1] + bb[j].y);
                *reinterpret_cast<float2*>(&Y[(size_t)rlo * 128 + colw]) = o;
            }
            if (rhi < NN) {
                float2 o = make_float2(acc[i][j][2] + bb[j].x, acc[i][j][3] + bb[j].y);
                *reinterpret_cast<float2*>(&Y[(size_t)rhi * 128 + colw]) = o;
            }
        }
    }
}

// ---------------------------------------------------------------------------
// Warp-specialized persistent edge kernel (structure proven in R12).
//   wid 0-3: MMA warps; wid 4-11: edge-math warps; wid 12-15: convert warps.
// X ring 3 stages (16KB), P ring 2 stages (32KB: eproj 16K | eres 16K).
// Barriers: XFULL s->1+s (256), XEMPTY s->4+s (256),
//           PFULL p->7+p (384), PEMPTY p->9+p (384).
// ---------------------------------------------------------------------------
__global__ __launch_bounds__(512, 1) void edge_ws(
    const float* __restrict__ edge_feats,
    const float* __restrict__ be, const float* __restrict__ bev,
    const int* __restrict__ src, const int* __restrict__ dst,
    const float* __restrict__ q, const float* __restrict__ k,
    const float* __restrict__ v,
    const float* __restrict__ ln_eg, const float* __restrict__ ln_eb,
    float* __restrict__ agg, float* __restrict__ y_out)
{
    extern __shared__ char sm[];
    const uint32_t smb = smem_u32(sm);
    const int tid  = threadIdx.x;
    const int lane = tid & 31;
    const int wid  = tid >> 5;
    const unsigned FULL = 0xffffffffu;

    copy_weights_async(sm, 4, 5);      // We, Wev
    asm volatile("cp.async.commit_group;");
    asm volatile("cp.async.wait_group 0;");
    __syncthreads();

    int it = 0;
    if (wid >= 12) {
        // ---------------- convert warps ----------------
        const int gtid = tid - 384;    // 0..127
        for (int t = blockIdx.x; t < ETILES32; t += gridDim.x, ++it) {
            const int s = it % 3;
            if (it >= 3) BAR_SYNC(4 + s, 256);
            convert_x32(sm + EXR0 + s * 16384, edge_feats, t * 32, gtid);
            BAR_ARRIVE(1 + s, 256);
        }
    } else if (wid < 4) {
        // ---------------- MMA warps ----------------
        const int gw = wid;
        const float* bias = (gw >= 2) ? bev : be;
        const int g = lane >> 2, t2 = (lane & 3) * 2;
        float2 bb[8];
        #pragma unroll
        for (int j = 0; j < 8; j++) {
            int colw = (gw & 1) * 64 + j * 8 + t2;
            bb[j] = *reinterpret_cast<const float2*>(&bias[colw]);
        }
        for (int t = blockIdx.x; t < ETILES32; t += gridDim.x, ++it) {
            const int s = it % 3;
            const int p = it & 1;
            BAR_SYNC(1 + s, 256);
            float acc[2][8][4];
            mma_tile32g(smb, smb + EXR0 + s * 16384, gw, lane, acc);
            BAR_ARRIVE(4 + s, 256);
            if (it >= 2) BAR_SYNC(9 + p, 384);
            float* Pp = reinterpret_cast<float*>(
                sm + EPR0 + p * 32768 + ((gw >= 2) ? 16384 : 0));
            #pragma unroll
            for (int i = 0; i < 2; i++) {
                int rlo = i * 16 + g;
                int rhi = rlo + 8;
                #pragma unroll
                for (int j = 0; j < 8; j++) {
                    int colw = (gw & 1) * 64 + j * 8 + t2;
                    Pp[rlo * 128 + colw]     = acc[i][j][0] + bb[j].x;
                    Pp[rlo * 128 + colw + 1] = acc[i][j][1] + bb[j].y;
                    Pp[rhi * 128 + colw]     = acc[i][j][2] + bb[j].x;
                    Pp[rhi * 128 + colw + 1] = acc[i][j][3] + bb[j].y;
                }
            }
            BAR_ARRIVE(7 + p, 384);
        }
    } else {
        // ---------------- edge-math warps ----------------
        const int ew = wid - 4;        // 0..7
        const int rbase = ew * 4;
        float4 ge = *reinterpret_cast<const float4*>(&ln_eg[4 * lane]);
        float4 gb = *reinterpret_cast<const float4*>(&ln_eb[4 * lane]);
        for (int t = blockIdx.x; t < ETILES32; t += gridDim.x, ++it) {
            const int p = it & 1;
            const int e0 = t * 32;
            int sd = 0;
            if (lane < 8)
                sd = __ldg(((lane < 4) ? src : dst) + e0 + rbase + (lane & 3));
            int se[4], de[4];
            #pragma unroll
            for (int e = 0; e < 4; e++) {
                se[e] = __shfl_sync(FULL, sd, e);
                de[e] = __shfl_sync(FULL, sd, e + 4);
            }
            float4 Q[4], K[4], V[4];
            #pragma unroll
            for (int e = 0; e < 4; e++) {
                Q[e] = __ldg(reinterpret_cast<const float4*>(&q[(size_t)se[e] * 128 + 4 * lane]));
                K[e] = __ldg(reinterpret_cast<const float4*>(&k[(size_t)de[e] * 128 + 4 * lane]));
                V[e] = __ldg(reinterpret_cast<const float4*>(&v[(size_t)se[e] * 128 + 4 * lane]));
            }
            BAR_SYNC(7 + p, 384);
            const float* Pe = reinterpret_cast<const float*>(sm + EPR0 + p * 32768);
            const float* Pr = Pe + 4096;   // eres plane
            #pragma unroll
            for (int e = 0; e < 4; e++) {
                int row = rbase + e;
                float pd = Q[e].x * K[e].x + Q[e].y * K[e].y
                         + Q[e].z * K[e].z + Q[e].w * K[e].w;
                pd += __shfl_xor_sync(FULL, pd, 1);
                pd += __shfl_xor_sync(FULL, pd, 2);
                pd += __shfl_xor_sync(FULL, pd, 4);

                float4 m4 = *reinterpret_cast<const float4*>(&Pe[row * 128 + 4 * lane]);
                m4.x = fmaf(pd, INV_SCALE, m4.x);
                m4.y = fmaf(pd, INV_SCALE, m4.y);
                m4.z = fmaf(pd, INV_SCALE, m4.z);
                m4.w = fmaf(pd, INV_SCALE, m4.w);

                float4 ex;
                ex.x = __expf(m4.x); ex.y = __expf(m4.y);
                ex.z = __expf(m4.z); ex.w = __expf(m4.w);
                float4 sx = ex;
                #pragma unroll
                for (int off = 8; off <= 16; off <<= 1) {
                    sx.x += __shfl_xor_sync(FULL, sx.x, off);
                    sx.y += __shfl_xor_sync(FULL, sx.y, off);
                    sx.z += __shfl_xor_sync(FULL, sx.z, off);
                    sx.w += __shfl_xor_sync(FULL, sx.w, off);
                }
                float4 msg;
                msg.x = V[e].x * ex.x * __fdividef(1.0f, sx.x);
                msg.y = V[e].y * ex.y * __fdividef(1.0f, sx.y);
                msg.z = V[e].z * ex.z * __fdividef(1.0f, sx.z);
                msg.w = V[e].w * ex.w * __fdividef(1.0f, sx.w);
                float* ap = &agg[(size_t)de[e] * 128 + 4 * lane];
                asm volatile("red.global.add.v4.f32 [%0], {%1, %2, %3, %4};"
                             :: "l"(ap), "f"(msg.x), "f"(msg.y), "f"(msg.z), "f"(msg.w)
                             : "memory");

                float ls = m4.x + m4.y + m4.z + m4.w;
                float lq = m4.x * m4.x + m4.y * m4.y + m4.z * m4.z + m4.w * m4.w;
                #pragma unroll
                for (int off = 16; off > 0; off >>= 1) {
                    ls += __shfl_xor_sync(FULL, ls, off);
                    lq += __shfl_xor_sync(FULL, lq, off);
                }
                float mu = ls * (1.0f / 128.0f);
                float var = lq * (1.0f / 128.0f) - mu * mu;
                float rs = rsqrtf(var + LN_EPS);

                float t0 = fmaf((m4.x - mu) * rs, ge.x, gb.x);
                float t1 = fmaf((m4.y - mu) * rs, ge.y, gb.y);
                float t2f = fmaf((m4.z - mu) * rs, ge.z, gb.z);
                float t3 = fmaf((m4.w - mu) * rs, ge.w, gb.w);
                float4 er = *reinterpret_cast<const float4*>(&Pr[row * 128 + 4 * lane]);
                float4 o;
                o.x = t0 * __fdividef(1.0f, 1.0f + __expf(-t0)) + er.x;
                o.y = t1 * __fdividef(1.0f, 1.0f + __expf(-t1)) + er.y;
                o.z = t2f * __fdividef(1.0f, 1.0f + __expf(-t2f)) + er.z;
                o.w = t3 * __fdividef(1.0f, 1.0f + __expf(-t3)) + er.w;
                *reinterpret_cast<float4*>(&y_out[(size_t)(e0 + row) * 128 + 4 * lane]) = o;
            }
            BAR_ARRIVE(9 + p, 384);
        }
    }
}

// ---------------------------------------------------------------------------
// Node finalize
// ---------------------------------------------------------------------------
__global__ __launch_bounds__(256) void node_kernel(
    const float* __restrict__ agg, const float* __restrict__ nres,
    const float* __restrict__ ln_ng, const float* __restrict__ ln_nb,
    float* __restrict__ x_out)
{
    int node = (blockIdx.x * blockDim.x + threadIdx.x) >> 5;
    int lane = threadIdx.x & 31;
    if (node >= NN) return;
    const unsigned FULL = 0xffffffffu;

    size_t base = (size_t)node * 128 + 4 * lane;
    float4 a = __ldg(reinterpret_cast<const float4*>(&agg[base]));

    float ls = a.x + a.y + a.z + a.w;
    float lq = a.x * a.x + a.y * a.y + a.z * a.z + a.w * a.w;
    #pragma unroll
    for (int off = 16; off > 0; off >>= 1) {
        ls += __shfl_xor_sync(FULL, ls, off);
        lq += __shfl_xor_sync(FULL, lq, off);
    }
    float mu  = ls * (1.0f / 128.0f);
    float var = lq * (1.0f / 128.0f) - mu * mu;
    float rs  = rsqrtf(var + LN_EPS);

    float4 g = __ldg(reinterpret_cast<const float4*>(&ln_ng[4 * lane]));
    float4 b = __ldg(reinterpret_cast<const float4*>(&ln_nb[4 * lane]));
    float4 r = __ldg(reinterpret_cast<const float4*>(&nres[base]));

    float t0 = fmaf((a.x - mu) * rs, g.x, b.x);
    float t1 = fmaf((a.y - mu) * rs, g.y, b.y);
    float t2 = fmaf((a.z - mu) * rs, g.z, b.z);
    float t3 = fmaf((a.w - mu) * rs, g.w, b.w);
    float4 o;
    o.x = t0 * __fdividef(1.0f, 1.0f + __expf(-t0)) + r.x;
    o.y = t1 * __fdividef(1.0f, 1.0f + __expf(-t1)) + r.y;
    o.z = t2 * __fdividef(1.0f, 1.0f + __expf(-t2)) + r.z;
    o.w = t3 * __fdividef(1.0f, 1.0f + __expf(-t3)) + r.w;
    *reinterpret_cast<float4*>(&x_out[base]) = o;
}

// ---------------------------------------------------------------------------
// Launch
// ---------------------------------------------------------------------------
extern "C" void kernel_launch(void* const* d_in, const int* in_sizes, int n_in,
                              void* d_out, int out_size)
{
    const float* node_feats = (const float*)d_in[0];
    const float* edge_feats = (const float*)d_in[1];
    const int*   src        = (const int*)d_in[2];
    const int*   dst        = (const int*)d_in[3];
    const float* Wq   = (const float*)d_in[4];
    const float* bq   = (const float*)d_in[5];
    const float* Wk   = (const float*)d_in[6];
    const float* bk   = (const float*)d_in[7];
    const float* Wv   = (const float*)d_in[8];
    const float* bv   = (const float*)d_in[9];
    const float* We   = (const float*)d_in[10];
    const float* be   = (const float*)d_in[11];
    const float* Wev  = (const float*)d_in[12];
    const float* bev  = (const float*)d_in[13];
    const float* Wout = (const float*)d_in[14];
    const float* bout = (const float*)d_in[15];
    const float* ln_ng = (const float*)d_in[16];
    const float* ln_nb = (const float*)d_in[17];
    const float* ln_eg = (const float*)d_in[18];
    const float* ln_eb = (const float*)d_in[19];

    float* scratch = nullptr;
    cudaGetSymbolAddress((void**)&scratch, g_scratch);
    float* q    = scratch;
    float* kk   = q    + (size_t)NN * 128;
    float* vv   = kk   + (size_t)NN * 128;
    float* nres = vv   + (size_t)NN * 128;
    float* agg  = nres + (size_t)NN * 128;

    float* x_out = (float*)d_out;
    float* y_out = x_out + (size_t)NN * 128;

    static bool attr_set = false;
    if (!attr_set) {
        cudaFuncSetAttribute(gemm_node, cudaFuncAttributeMaxDynamicSharedMemorySize, SMEM_GEMM);
        cudaFuncSetAttribute(edge_ws, cudaFuncAttributeMaxDynamicSharedMemorySize, SMEM_EDGE_WS);
        attr_set = true;
    }

    int nsm = 148;
    cudaDeviceGetAttribute(&nsm, cudaDevAttrMultiProcessorCount, 0);

    // launch order: 0 prep_w, 1 zero, 2 gemm_node, 3 edge_ws, 4 node
    prep_w<<<48, 256>>>(Wq, Wk, Wv, Wout, We, Wev);
    zero_kernel<<<NN * 32 / 256, 256>>>(agg);
    gemm_node<<<2 * NBLK, 512, SMEM_GEMM>>>(
        node_feats, bq, bk, bv, bout, q, kk, vv, nres);
    edge_ws<<<nsm, 512, SMEM_EDGE_WS>>>(
        edge_feats, be, bev, src, dst, q, kk, vv, ln_eg, ln_eb, agg, y_out);
    node_kernel<<<NN / 8, 256>>>(agg, nres, ln_ng, ln_nb, x_out);
}

// round 15
// speedup vs baseline: 2.1466x; 1.1091x over previous
#include <cuda_runtime.h>
#include <cuda_bf16.h>
#include <cuda_fp16.h>
#include <math.h>
#include <stdint.h>

#define NN 50000
#define EE 400000
#define NBLK 391            // ceil(NN/128) node tiles
#define ETILES32 12500      // EE/32 edge tiles
#define INV_SCALE 0.17677669529663687f   // 1/sqrt(32)
#define LN_EPS 1e-5f

// Scratch: q, k, v, nres, agg (5*N*128 = 32M floats)
__device__ float g_scratch[32000000];
// fp16 swizzled weight tiles: 6 weights x 32KB
__device__ __align__(256) unsigned char g_wbf[6 * 32768];

// ---- node gemm smem layout ----
#define SW1HI 0
#define SW2HI 32768
#define SXHI  65536              // X hi 32KB, lo at +32768
#define SMEM_GEMM 131072
// ---- edge warp-specialized smem: W 64KB + X ring 3x16KB + P ring 2x33792 ----
#define EXR0  65536              // X ring (16KB/stage: hi 8K + lo 8K)
#define EPR0  114688             // P ring (33792/stage: eproj 16896 + eres 16896)
#define PROW  132                // padded row stride (floats) -> kills 8-way conflicts
#define PSTAGE 33792
#define PHALF  4224              // floats: offset of eres plane
#define SMEM_EDGE_WS (114688 + 2 * PSTAGE)   // 182272

// Swizzled byte offset in a K-major fp16 tile (256B rows, 16B chunks,
// chunk ^= row&7 -> conflict-free for row-parallel and k-parallel access).
__device__ __forceinline__ int sw_off(int row, int col) {
    return row * 256 + ((((col >> 3) ^ (row & 7)) & 15) << 4) + (col & 7) * 2;
}

__device__ __forceinline__ uint32_t smem_u32(const void* p) {
    uint32_t a;
    asm("{ .reg .u64 t; cvta.to.shared.u64 t, %1; cvt.u32.u64 %0, t; }"
        : "=r"(a) : "l"(p));
    return a;
}

__device__ __forceinline__ void hmma(float* c, uint32_t a0, uint32_t a1,
                                     uint32_t a2, uint32_t a3,
                                     uint32_t b0, uint32_t b1) {
    asm("mma.sync.aligned.m16n8k16.row.col.f32.f16.f16.f32 "
        "{%0,%1,%2,%3}, {%4,%5,%6,%7}, {%8,%9}, {%0,%1,%2,%3};"
        : "+f"(c[0]), "+f"(c[1]), "+f"(c[2]), "+f"(c[3])
        : "r"(a0), "r"(a1), "r"(a2), "r"(a3), "r"(b0), "r"(b1));
}

#define LDSM_X4(r0, r1, r2, r3, addr) \
    asm volatile("ldmatrix.sync.aligned.m8n8.x4.shared.b16 {%0,%1,%2,%3}, [%4];" \
        : "=r"(r0), "=r"(r1), "=r"(r2), "=r"(r3) : "r"(addr))

// streaming 32B global load (evict-first in L2): protect q/k/v residency
__device__ __forceinline__ void ldg_stream8(const float* p, float4& a, float4& b) {
    asm("ld.global.nc.L2::evict_first.v8.b32 {%0,%1,%2,%3,%4,%5,%6,%7}, [%8];"
        : "=f"(a.x), "=f"(a.y), "=f"(a.z), "=f"(a.w),
          "=f"(b.x), "=f"(b.y), "=f"(b.z), "=f"(b.w) : "l"(p));
}
__device__ __forceinline__ void stg_stream4(float* p, float4 v) {
    asm volatile("st.global.cs.v4.f32 [%0], {%1,%2,%3,%4};"
                 :: "l"(p), "f"(v.x), "f"(v.y), "f"(v.z), "f"(v.w) : "memory");
}

// pack two f32 -> f16x2 {low=a, high=b} (rn)
__device__ __forceinline__ uint32_t pack_f16x2(float a, float b) {
    uint32_t r;
    asm("cvt.rn.f16x2.f32 %0, %1, %2;" : "=r"(r) : "f"(b), "f"(a));
    return r;
}

#define BAR_SYNC(id, cnt)   asm volatile("bar.sync %0, %1;"   :: "r"(id), "r"(cnt) : "memory")
#define BAR_ARRIVE(id, cnt) asm volatile("bar.arrive %0, %1;" :: "r"(id), "r"(cnt) : "memory")

// ---------------------------------------------------------------------------
// Weight prep: fp16(rn) swizzled tiles. 48 blocks: weight = bx>>3.
// ---------------------------------------------------------------------------
__global__ void prep_w(const float* __restrict__ W0, const float* __restrict__ W1,
                       const float* __restrict__ W2, const float* __restrict__ W3,
                       const float* __restrict__ W4, const float* __restrict__ W5)
{
    const float* W;
    switch (blockIdx.x >> 3) {
        case 0: W = W0; break; case 1: W = W1; break; case 2: W = W2; break;
        case 3: W = W3; break; case 4: W = W4; break; default: W = W5; break;
    }
    unsigned char* out = g_wbf + (size_t)(blockIdx.x >> 3) * 32768;
    int base = (blockIdx.x & 7) * 2048;
    for (int ii = threadIdx.x; ii < 2048; ii += blockDim.x) {
        int idx = base + ii;
        int row = idx >> 7, col = idx & 127;
        __half h = __float2half_rn(W[idx]);
        *reinterpret_cast<uint16_t*>(out + sw_off(row, col)) = __half_as_ushort(h);
    }
}

__global__ void zero_kernel(float* __restrict__ p)
{
    int i = blockIdx.x * blockDim.x + threadIdx.x;
    reinterpret_cast<float4*>(p)[i] = make_float4(0.f, 0.f, 0.f, 0.f);
}

// 64KB weight staging (both weights), 512 threads
__device__ __forceinline__ void copy_weights_async(char* sm, int w1idx, int w2idx) {
    uint32_t d1 = smem_u32(sm + SW1HI);
    uint32_t d2 = smem_u32(sm + SW2HI);
    const char* s1 = reinterpret_cast<const char*>(g_wbf + (size_t)w1idx * 32768);
    const char* s2 = reinterpret_cast<const char*>(g_wbf + (size_t)w2idx * 32768);
    int tid = threadIdx.x;
    #pragma unroll
    for (int i = 0; i < 4; i++) {
        int j = (tid + i * 512) * 16;
        asm volatile("cp.async.cg.shared.global [%0], [%1], 16;"
                     :: "r"(d1 + j), "l"(s1 + j));
        asm volatile("cp.async.cg.shared.global [%0], [%1], 16;"
                     :: "r"(d2 + j), "l"(s2 + j));
    }
}

// ---------------------------------------------------------------------------
// Converts: fp32 -> fp16 hi + fp16 lo (lo = x - float(hi)), swizzled planes
// ---------------------------------------------------------------------------
__device__ __forceinline__ void cvt_split4(float4 xv, uint2& hi, uint2& lo) {
    __half h0 = __float2half_rn(xv.x), h1 = __float2half_rn(xv.y);
    __half h2 = __float2half_rn(xv.z), h3 = __float2half_rn(xv.w);
    uint32_t hp01, hp23;
    asm("mov.b32 %0, {%1, %2};" : "=r"(hp01)
        : "h"(__half_as_ushort(h0)), "h"(__half_as_ushort(h1)));
    asm("mov.b32 %0, {%1, %2};" : "=r"(hp23)
        : "h"(__half_as_ushort(h2)), "h"(__half_as_ushort(h3)));
    float l0 = xv.x - __half2float(h0);
    float l1 = xv.y - __half2float(h1);
    float l2 = xv.z - __half2float(h2);
    float l3 = xv.w - __half2float(h3);
    hi = make_uint2(hp01, hp23);
    lo = make_uint2(pack_f16x2(l0, l1), pack_f16x2(l2, l3));
}

// Node-side: 128-row tile (512 threads)
__device__ __forceinline__ void convert_x128(char* sm, const float* __restrict__ X,
                                             int m0, int M) {
    int tid = threadIdx.x;
    int r = tid >> 2;
    int ch = (tid & 3) * 32;
    bool valid = (m0 + r) < M;
    const float* xp = X + (size_t)(m0 + r) * 128 + ch;
    #pragma unroll
    for (int u = 0; u < 8; u++) {
        int c = ch + u * 4;
        float4 xv = make_float4(0.f, 0.f, 0.f, 0.f);
        if (valid) xv = __ldg(reinterpret_cast<const float4*>(xp + u * 4));
        uint2 hi, lo;
        cvt_split4(xv, hi, lo);
        int off = sw_off(r, c);
        *reinterpret_cast<uint2*>(sm + SXHI + off) = hi;
        *reinterpret_cast<uint2*>(sm + SXHI + 32768 + off) = lo;
    }
}

// Edge-side: 32-row tile into a 16KB stage (128 threads), streaming 32B loads
__device__ __forceinline__ void convert_x32(char* xbuf, const float* __restrict__ X,
                                            int e0, int gtid) {
    int r = gtid >> 2;              // 0..31
    int ch = (gtid & 3) * 32;
    const float* xp = X + (size_t)(e0 + r) * 128 + ch;
    #pragma unroll
    for (int u = 0; u < 4; u++) {
        int c = ch + u * 8;
        float4 xa, xb;
        ldg_stream8(xp + u * 8, xa, xb);
        uint2 hi, lo;
        cvt_split4(xa, hi, lo);
        int off = sw_off(r, c);     // < 8192 for r < 32
        *reinterpret_cast<uint2*>(xbuf + off) = hi;
        *reinterpret_cast<uint2*>(xbuf + 8192 + off) = lo;
        cvt_split4(xb, hi, lo);
        off = sw_off(r, c + 4);
        *reinterpret_cast<uint2*>(xbuf + off) = hi;
        *reinterpret_cast<uint2*>(xbuf + 8192 + off) = lo;
    }
}

// ---------------------------------------------------------------------------
// Node MMA (16 warps, M=128), fp16 2-term
// ---------------------------------------------------------------------------
__device__ __forceinline__ void mma_tile128(const char* sm, float acc[2][8][4]) {
    const int lane = threadIdx.x & 31;
    const int wid  = threadIdx.x >> 5;
    const int wm = wid & 3, wn = wid >> 2;
    const int g  = lane >> 2;
    const int t4 = (lane & 3) * 4;

    const char* xhi = sm + SXHI;
    const char* xlo = sm + SXHI + 32768;
    const char* wh = sm + ((wn >= 2) ? SW2HI : SW1HI);

    const int arow = (wm * 32 + g) * 256 + t4;
    const int brow = ((wn & 1) * 64 + g) * 256 + t4;

    #pragma unroll
    for (int i = 0; i < 2; i++)
        #pragma unroll
        for (int j = 0; j < 8; j++)
            #pragma unroll
            for (int r = 0; r < 4; r++) acc[i][j][r] = 0.f;

    #pragma unroll
    for (int ks = 0; ks < 8; ks++) {
        const int cx0 = (((2 * ks) ^ g) << 4);
        const int cx1 = (((2 * ks + 1) ^ g) << 4);
        uint32_t ah[2][4], al[2][4];
        #pragma unroll
        for (int i = 0; i < 2; i++) {
            int r0 = arow + i * 16 * 256;
            int r8 = r0 + 8 * 256;
            ah[i][0] = *reinterpret_cast<const uint32_t*>(xhi + r0 + cx0);
            ah[i][1] = *reinterpret_cast<const uint32_t*>(xhi + r8 + cx0);
            ah[i][2] = *reinterpret_cast<const uint32_t*>(xhi + r0 + cx1);
            ah[i][3] = *reinterpret_cast<const uint32_t*>(xhi + r8 + cx1);
            al[i][0] = *reinterpret_cast<const uint32_t*>(xlo + r0 + cx0);
            al[i][1] = *reinterpret_cast<const uint32_t*>(xlo + r8 + cx0);
            al[i][2] = *reinterpret_cast<const uint32_t*>(xlo + r0 + cx1);
            al[i][3] = *reinterpret_cast<const uint32_t*>(xlo + r8 + cx1);
        }
        #pragma unroll
        for (int j = 0; j < 8; j++) {
            int rb = brow + j * 8 * 256;
            uint32_t bh0 = *reinterpret_cast<const uint32_t*>(wh + rb + cx0);
            uint32_t bh1 = *reinterpret_cast<const uint32_t*>(wh + rb + cx1);
            #pragma unroll
            for (int i = 0; i < 2; i++) {
                hmma(acc[i][j], ah[i][0], ah[i][1], ah[i][2], ah[i][3], bh0, bh1);
                hmma(acc[i][j], al[i][0], al[i][1], al[i][2], al[i][3], bh0, bh1);
            }
        }
    }
}

// ---------------------------------------------------------------------------
// 32-row tile MMA via ldmatrix, fp16 2-term (layout proven R11-13)
// ---------------------------------------------------------------------------
__device__ __forceinline__ void mma_tile32g(uint32_t smb, uint32_t xbuf,
                                            int gw, int lane,
                                            float acc[2][8][4]) {
    const int mi = lane >> 3;
    const int r  = lane & 7;
    const uint32_t xh = xbuf;
    const uint32_t xl = xbuf + 8192;
    const uint32_t wh = smb + ((gw >= 2) ? SW2HI : SW1HI);

    const uint32_t aro0 = (uint32_t)(((mi & 1) * 8 + r) * 256);
    const uint32_t aro1 = aro0 + 16 * 256;
    const int axc = mi >> 1;
    const int bxc = mi & 1;
    uint32_t bro[4];
    #pragma unroll
    for (int jp = 0; jp < 4; jp++)
        bro[jp] = (uint32_t)((((gw & 1) * 64) + (jp * 2 + (mi >> 1)) * 8 + r) * 256);

    #pragma unroll
    for (int i = 0; i < 2; i++)
        #pragma unroll
        for (int j = 0; j < 8; j++)
            #pragma unroll
            for (int rr = 0; rr < 4; rr++) acc[i][j][rr] = 0.f;

    #pragma unroll
    for (int ks = 0; ks < 8; ks++) {
        const uint32_t xA = (uint32_t)(((2 * ks + axc) ^ r) << 4);
        const uint32_t xB = (uint32_t)(((2 * ks + bxc) ^ r) << 4);
        uint32_t ah[8], al[8];
        LDSM_X4(ah[0], ah[1], ah[2], ah[3], xh + aro0 + xA);
        LDSM_X4(ah[4], ah[5], ah[6], ah[7], xh + aro1 + xA);
        LDSM_X4(al[0], al[1], al[2], al[3], xl + aro0 + xA);
        LDSM_X4(al[4], al[5], al[6], al[7], xl + aro1 + xA);
        #pragma unroll
        for (int jp = 0; jp < 4; jp++) {
            uint32_t bh[4];
            LDSM_X4(bh[0], bh[1], bh[2], bh[3], wh + bro[jp] + xB);
            const int j0 = jp * 2, j1 = jp * 2 + 1;
            hmma(acc[0][j0], ah[0], ah[1], ah[2], ah[3], bh[0], bh[1]);
            hmma(acc[0][j0], al[0], al[1], al[2], al[3], bh[0], bh[1]);
            hmma(acc[0][j1], ah[0], ah[1], ah[2], ah[3], bh[2], bh[3]);
            hmma(acc[0][j1], al[0], al[1], al[2], al[3], bh[2], bh[3]);
            hmma(acc[1][j0], ah[4], ah[5], ah[6], ah[7], bh[0], bh[1]);
            hmma(acc[1][j0], al[4], al[5], al[6], al[7], bh[0], bh[1]);
            hmma(acc[1][j1], ah[4], ah[5], ah[6], ah[7], bh[2], bh[3]);
            hmma(acc[1][j1], al[4], al[5], al[6], al[7], bh[2], bh[3]);
        }
    }
}

// ---------------------------------------------------------------------------
// Node GEMMs merged
// ---------------------------------------------------------------------------
__global__ __launch_bounds__(512, 1) void gemm_node(
    const float* __restrict__ X,
    const float* __restrict__ bq, const float* __restrict__ bk,
    const float* __restrict__ bv, const float* __restrict__ bout,
    float* __restrict__ q, float* __restrict__ kk,
    float* __restrict__ vv, float* __restrict__ nres)
{
    extern __shared__ char sm[];
    const int half = blockIdx.x / NBLK;
    const int tile = blockIdx.x % NBLK;
    const int m0 = tile * 128;
    const float* b1 = half ? bv : bq;
    const float* b2 = half ? bout : bk;
    float* Y1 = half ? vv : q;
    float* Y2 = half ? nres : kk;

    copy_weights_async(sm, half * 2, half * 2 + 1);
    asm volatile("cp.async.commit_group;");
    convert_x128(sm, X, m0, NN);
    asm volatile("cp.async.wait_group 0;");
    __syncthreads();

    float acc[2][8][4];
    mma_tile128(sm, acc);

    const int lane = threadIdx.x & 31;
    const int wid  = threadIdx.x >> 5;
    const int wm = wid & 3, wn = wid >> 2;
    const int g = lane >> 2, t2 = (lane & 3) * 2;

    const float* bias = (wn >= 2) ? b2 : b1;
    float* Y = (wn >= 2) ? Y2 : Y1;
    float2 bb[8];
    #pragma unroll
    for (int j = 0; j < 8; j++) {
        int colw = (wn & 1) * 64 + j * 8 + t2;
        bb[j] = *reinterpret_cast<const float2*>(&bias[colw]);
    }
    #pragma unroll
    for (int i = 0; i < 2; i++) {
        int rlo = m0 + wm * 32 + i * 16 + g;
        int rhi = rlo + 8;
        #pragma unroll
        for (int j = 0; j < 8; j++) {
            int colw = (wn & 1) * 64 + j * 8 + t2;
            if (rlo < NN) {
                float2 o = make_float2(acc[i][j][0] + bb[j].x, acc[i][j][1] + bb[j].y);
                *reinterpret_cast<float2*>(&Y[(size_t)rlo * 128 + colw]) = o;
            }
            if (rhi < NN) {
                float2 o = make_float2(acc[i][j][2] + bb[j].x, acc[i][j][3] + bb[j].y);
                *reinterpret_cast<float2*>(&Y[(size_t)rhi * 128 + colw]) = o;
            }
        }
    }
}

// ---------------------------------------------------------------------------
// Warp-specialized persistent edge kernel (R12/13 structure).
//   wid 0-3: MMA warps; wid 4-11: edge-math warps; wid 12-15: convert warps.
// X ring 3x16KB; P ring 2x33792 with 132-float padded rows.
// Barriers: XFULL s->1+s (256), XEMPTY s->4+s (256),
//           PFULL p->7+p (384), PEMPTY p->9+p (384).
// ---------------------------------------------------------------------------
__global__ __launch_bounds__(512, 1) void edge_ws(
    const float* __restrict__ edge_feats,
    const float* __restrict__ be, const float* __restrict__ bev,
    const int* __restrict__ src, const int* __restrict__ dst,
    const float* __restrict__ q, const float* __restrict__ k,
    const float* __restrict__ v,
    const float* __restrict__ ln_eg, const float* __restrict__ ln_eb,
    float* __restrict__ agg, float* __restrict__ y_out)
{
    extern __shared__ char sm[];
    const uint32_t smb = smem_u32(sm);
    const int tid  = threadIdx.x;
    const int lane = tid & 31;
    const int wid  = tid >> 5;
    const unsigned FULL = 0xffffffffu;

    copy_weights_async(sm, 4, 5);      // We, Wev
    asm volatile("cp.async.commit_group;");
    asm volatile("cp.async.wait_group 0;");
    __syncthreads();

    int it = 0;
    if (wid >= 12) {
        // ---------------- convert warps ----------------
        const int gtid = tid - 384;    // 0..127
        for (int t = blockIdx.x; t < ETILES32; t += gridDim.x, ++it) {
            const int s = it % 3;
            if (it >= 3) BAR_SYNC(4 + s, 256);
            convert_x32(sm + EXR0 + s * 16384, edge_feats, t * 32, gtid);
            BAR_ARRIVE(1 + s, 256);
        }
    } else if (wid < 4) {
        // ---------------- MMA warps ----------------
        const int gw = wid;
        const float* bias = (gw >= 2) ? bev : be;
        const int g = lane >> 2, t2 = (lane & 3) * 2;
        float2 bb[8];
        #pragma unroll
        for (int j = 0; j < 8; j++) {
            int colw = (gw & 1) * 64 + j * 8 + t2;
            bb[j] = *reinterpret_cast<const float2*>(&bias[colw]);
        }
        for (int t = blockIdx.x; t < ETILES32; t += gridDim.x, ++it) {
            const int s = it % 3;
            const int p = it & 1;
            BAR_SYNC(1 + s, 256);
            float acc[2][8][4];
            mma_tile32g(smb, smb + EXR0 + s * 16384, gw, lane, acc);
            BAR_ARRIVE(4 + s, 256);
            if (it >= 2) BAR_SYNC(9 + p, 384);
            float* Pp = reinterpret_cast<float*>(sm + EPR0 + p * PSTAGE)
                        + ((gw >= 2) ? PHALF : 0);
            #pragma unroll
            for (int i = 0; i < 2; i++) {
                int rlo = i * 16 + g;
                int rhi = rlo + 8;
                #pragma unroll
                for (int j = 0; j < 8; j++) {
                    int colw = (gw & 1) * 64 + j * 8 + t2;
                    Pp[rlo * PROW + colw]     = acc[i][j][0] + bb[j].x;
                    Pp[rlo * PROW + colw + 1] = acc[i][j][1] + bb[j].y;
                    Pp[rhi * PROW + colw]     = acc[i][j][2] + bb[j].x;
                    Pp[rhi * PROW + colw + 1] = acc[i][j][3] + bb[j].y;
                }
            }
            BAR_ARRIVE(7 + p, 384);
        }
    } else {
        // ---------------- edge-math warps ----------------
        const int ew = wid - 4;        // 0..7
        const int rbase = ew * 4;
        float4 ge = *reinterpret_cast<const float4*>(&ln_eg[4 * lane]);
        float4 gb = *reinterpret_cast<const float4*>(&ln_eb[4 * lane]);
        for (int t = blockIdx.x; t < ETILES32; t += gridDim.x, ++it) {
            const int p = it & 1;
            const int e0 = t * 32;
            int sd = 0;
            if (lane < 8)
                sd = __ldg(((lane < 4) ? src : dst) + e0 + rbase + (lane & 3));
            int se[4], de[4];
            #pragma unroll
            for (int e = 0; e < 4; e++) {
                se[e] = __shfl_sync(FULL, sd, e);
                de[e] = __shfl_sync(FULL, sd, e + 4);
            }
            float4 Q[4], K[4], V[4];
            #pragma unroll
            for (int e = 0; e < 4; e++) {
                Q[e] = __ldg(reinterpret_cast<const float4*>(&q[(size_t)se[e] * 128 + 4 * lane]));
                K[e] = __ldg(reinterpret_cast<const float4*>(&k[(size_t)de[e] * 128 + 4 * lane]));
                V[e] = __ldg(reinterpret_cast<const float4*>(&v[(size_t)se[e] * 128 + 4 * lane]));
            }
            BAR_SYNC(7 + p, 384);
            const float* Pe = reinterpret_cast<const float*>(sm + EPR0 + p * PSTAGE);
            const float* Pr = Pe + PHALF;   // eres plane
            #pragma unroll
            for (int e = 0; e < 4; e++) {
                int row = rbase + e;
                float pd = Q[e].x * K[e].x + Q[e].y * K[e].y
                         + Q[e].z * K[e].z + Q[e].w * K[e].w;
                pd += __shfl_xor_sync(FULL, pd, 1);
                pd += __shfl_xor_sync(FULL, pd, 2);
                pd += __shfl_xor_sync(FULL, pd, 4);

                float4 m4 = *reinterpret_cast<const float4*>(&Pe[row * PROW + 4 * lane]);
                m4.x = fmaf(pd, INV_SCALE, m4.x);
                m4.y = fmaf(pd, INV_SCALE, m4.y);
                m4.z = fmaf(pd, INV_SCALE, m4.z);
                m4.w = fmaf(pd, INV_SCALE, m4.w);

                float4 ex;
                ex.x = __expf(m4.x); ex.y = __expf(m4.y);
                ex.z = __expf(m4.z); ex.w = __expf(m4.w);
                float4 sx = ex;
                #pragma unroll
                for (int off = 8; off <= 16; off <<= 1) {
                    sx.x += __shfl_xor_sync(FULL, sx.x, off);
                    sx.y += __shfl_xor_sync(FULL, sx.y, off);
                    sx.z += __shfl_xor_sync(FULL, sx.z, off);
                    sx.w += __shfl_xor_sync(FULL, sx.w, off);
                }
                float4 msg;
                msg.x = V[e].x * ex.x * __fdividef(1.0f, sx.x);
                msg.y = V[e].y * ex.y * __fdividef(1.0f, sx.y);
                msg.z = V[e].z * ex.z * __fdividef(1.0f, sx.z);
                msg.w = V[e].w * ex.w * __fdividef(1.0f, sx.w);
                float* ap = &agg[(size_t)de[e] * 128 + 4 * lane];
                asm volatile("red.global.add.v4.f32 [%0], {%1, %2, %3, %4};"
                             :: "l"(ap), "f"(msg.x), "f"(msg.y), "f"(msg.z), "f"(msg.w)
                             : "memory");

                float ls = m4.x + m4.y + m4.z + m4.w;
                float lq = m4.x * m4.x + m4.y * m4.y + m4.z * m4.z + m4.w * m4.w;
                #pragma unroll
                for (int off = 16; off > 0; off >>= 1) {
                    ls += __shfl_xor_sync(FULL, ls, off);
                    lq += __shfl_xor_sync(FULL, lq, off);
                }
                float mu = ls * (1.0f / 128.0f);
                float var = lq * (1.0f / 128.0f) - mu * mu;
                float rs = rsqrtf(var + LN_EPS);

                float t0 = fmaf((m4.x - mu) * rs, ge.x, gb.x);
                float t1 = fmaf((m4.y - mu) * rs, ge.y, gb.y);
                float t2f = fmaf((m4.z - mu) * rs, ge.z, gb.z);
                float t3 = fmaf((m4.w - mu) * rs, ge.w, gb.w);
                float4 er = *reinterpret_cast<const float4*>(&Pr[row * PROW + 4 * lane]);
                float4 o;
                o.x = t0 * __fdividef(1.0f, 1.0f + __expf(-t0)) + er.x;
                o.y = t1 * __fdividef(1.0f, 1.0f + __expf(-t1)) + er.y;
                o.z = t2f * __fdividef(1.0f, 1.0f + __expf(-t2f)) + er.z;
                o.w = t3 * __fdividef(1.0f, 1.0f + __expf(-t3)) + er.w;
                stg_stream4(&y_out[(size_t)(e0 + row) * 128 + 4 * lane], o);
            }
            BAR_ARRIVE(9 + p, 384);
        }
    }
}

// ---------------------------------------------------------------------------
// Node finalize
// ---------------------------------------------------------------------------
__global__ __launch_bounds__(256) void node_kernel(
    const float* __restrict__ agg, const float* __restrict__ nres,
    const float* __restrict__ ln_ng, const float* __restrict__ ln_nb,
    float* __restrict__ x_out)
{
    int node = (blockIdx.x * blockDim.x + threadIdx.x) >> 5;
    int lane = threadIdx.x & 31;
    if (node >= NN) return;
    const unsigned FULL = 0xffffffffu;

    size_t base = (size_t)node * 128 + 4 * lane;
    float4 a = __ldg(reinterpret_cast<const float4*>(&agg[base]));

    float ls = a.x + a.y + a.z + a.w;
    float lq = a.x * a.x + a.y * a.y + a.z * a.z + a.w * a.w;
    #pragma unroll
    for (int off = 16; off > 0; off >>= 1) {
        ls += __shfl_xor_sync(FULL, ls, off);
        lq += __shfl_xor_sync(FULL, lq, off);
    }
    float mu  = ls * (1.0f / 128.0f);
    float var = lq * (1.0f / 128.0f) - mu * mu;
    float rs  = rsqrtf(var + LN_EPS);

    float4 g = __ldg(reinterpret_cast<const float4*>(&ln_ng[4 * lane]));
    float4 b = __ldg(reinterpret_cast<const float4*>(&ln_nb[4 * lane]));
    float4 r = __ldg(reinterpret_cast<const float4*>(&nres[base]));

    float t0 = fmaf((a.x - mu) * rs, g.x, b.x);
    float t1 = fmaf((a.y - mu) * rs, g.y, b.y);
    float t2 = fmaf((a.z - mu) * rs, g.z, b.z);
    float t3 = fmaf((a.w - mu) * rs, g.w, b.w);
    float4 o;
    o.x = t0 * __fdividef(1.0f, 1.0f + __expf(-t0)) + r.x;
    o.y = t1 * __fdividef(1.0f, 1.0f + __expf(-t1)) + r.y;
    o.z = t2 * __fdividef(1.0f, 1.0f + __expf(-t2)) + r.z;
    o.w = t3 * __fdividef(1.0f, 1.0f + __expf(-t3)) + r.w;
    *reinterpret_cast<float4*>(&x_out[base]) = o;
}

// ---------------------------------------------------------------------------
// Launch
// ---------------------------------------------------------------------------
extern "C" void kernel_launch(void* const* d_in, const int* in_sizes, int n_in,
                              void* d_out, int out_size)
{
    const float* node_feats = (const float*)d_in[0];
    const float* edge_feats = (const float*)d_in[1];
    const int*   src        = (const int*)d_in[2];
    const int*   dst        = (const int*)d_in[3];
    const float* Wq   = (const float*)d_in[4];
    const float* bq   = (const float*)d_in[5];
    const float* Wk   = (const float*)d_in[6];
    const float* bk   = (const float*)d_in[7];
    const float* Wv   = (const float*)d_in[8];
    const float* bv   = (const float*)d_in[9];
    const float* We   = (const float*)d_in[10];
    const float* be   = (const float*)d_in[11];
    const float* Wev  = (const float*)d_in[12];
    const float* bev  = (const float*)d_in[13];
    const float* Wout = (const float*)d_in[14];
    const float* bout = (const float*)d_in[15];
    const float* ln_ng = (const float*)d_in[16];
    const float* ln_nb = (const float*)d_in[17];
    const float* ln_eg = (const float*)d_in[18];
    const float* ln_eb = (const float*)d_in[19];

    float* scratch = nullptr;
    cudaGetSymbolAddress((void**)&scratch, g_scratch);
    float* q    = scratch;
    float* kk   = q    + (size_t)NN * 128;
    float* vv   = kk   + (size_t)NN * 128;
    float* nres = vv   + (size_t)NN * 128;
    float* agg  = nres + (size_t)NN * 128;

    float* x_out = (float*)d_out;
    float* y_out = x_out + (size_t)NN * 128;

    static bool attr_set = false;
    if (!attr_set) {
        cudaFuncSetAttribute(gemm_node, cudaFuncAttributeMaxDynamicSharedMemorySize, SMEM_GEMM);
        cudaFuncSetAttribute(edge_ws, cudaFuncAttributeMaxDynamicSharedMemorySize, SMEM_EDGE_WS);
        attr_set = true;
    }

    int nsm = 148;
    cudaDeviceGetAttribute(&nsm, cudaDevAttrMultiProcessorCount, 0);

    // launch order: 0 prep_w, 1 zero, 2 gemm_node, 3 edge_ws, 4 node
    prep_w<<<48, 256>>>(Wq, Wk, Wv, Wout, We, Wev);
    zero_kernel<<<NN * 32 / 256, 256>>>(agg);
    gemm_node<<<2 * NBLK, 512, SMEM_GEMM>>>(
        node_feats, bq, bk, bv, bout, q, kk, vv, nres);
    edge_ws<<<nsm, 512, SMEM_EDGE_WS>>>(
        edge_feats, be, bev, src, dst, q, kk, vv, ln_eg, ln_eb, agg, y_out);
    node_kernel<<<NN / 8, 256>>>(agg, nres, ln_ng, ln_nb, x_out);
}

// round 16
// speedup vs baseline: 2.3238x; 1.0826x over previous
#include <cuda_runtime.h>
#include <cuda_bf16.h>
#include <cuda_fp16.h>
#include <math.h>
#include <stdint.h>

#define NN 50000
#define EE 400000
#define NBLK 391            // ceil(NN/128) node tiles
#define ZBLK 391            // agg-zero blocks appended to gemm_node
#define ETILES32 12500      // EE/32 edge tiles
#define INV_SCALE 0.17677669529663687f   // 1/sqrt(32)
#define LN_EPS 1e-5f

// Scratch: q, k, v, nres, agg (5*N*128 = 32M floats)
__device__ float g_scratch[32000000];
// fp16 swizzled weight tiles: 6 weights x 32KB
__device__ __align__(256) unsigned char g_wbf[6 * 32768];

// ---- node gemm smem layout (single-plane X) ----
#define SW1HI 0
#define SW2HI 32768
#define SXHI  65536              // X 32KB (single fp16 plane)
#define SMEM_GEMM 98304
// ---- edge WS smem: W 64KB + X ring 3x8KB + P ring 2x33792 ----
#define EXR0  65536              // X ring (8KB/stage, single plane)
#define EPR0  90112              // P ring (33792/stage: eproj | eres)
#define PROW  132                // padded row stride (floats)
#define PSTAGE 33792
#define PHALF  4224              // floats: offset of eres plane
#define SMEM_EDGE_WS (90112 + 2 * PSTAGE)   // 157696

// Swizzled byte offset in a K-major fp16 tile (256B rows, 16B chunks,
// chunk ^= row&7 -> conflict-free for row-parallel and k-parallel access).
__device__ __forceinline__ int sw_off(int row, int col) {
    return row * 256 + ((((col >> 3) ^ (row & 7)) & 15) << 4) + (col & 7) * 2;
}

__device__ __forceinline__ uint32_t smem_u32(const void* p) {
    uint32_t a;
    asm("{ .reg .u64 t; cvta.to.shared.u64 t, %1; cvt.u32.u64 %0, t; }"
        : "=r"(a) : "l"(p));
    return a;
}

__device__ __forceinline__ void hmma(float* c, uint32_t a0, uint32_t a1,
                                     uint32_t a2, uint32_t a3,
                                     uint32_t b0, uint32_t b1) {
    asm("mma.sync.aligned.m16n8k16.row.col.f32.f16.f16.f32 "
        "{%0,%1,%2,%3}, {%4,%5,%6,%7}, {%8,%9}, {%0,%1,%2,%3};"
        : "+f"(c[0]), "+f"(c[1]), "+f"(c[2]), "+f"(c[3])
        : "r"(a0), "r"(a1), "r"(a2), "r"(a3), "r"(b0), "r"(b1));
}

#define LDSM_X4(r0, r1, r2, r3, addr) \
    asm volatile("ldmatrix.sync.aligned.m8n8.x4.shared.b16 {%0,%1,%2,%3}, [%4];" \
        : "=r"(r0), "=r"(r1), "=r"(r2), "=r"(r3) : "r"(addr))

// streaming 32B global load (evict-first in L2): protect q/k/v residency
__device__ __forceinline__ void ldg_stream8(const float* p, float4& a, float4& b) {
    asm("ld.global.nc.L2::evict_first.v8.b32 {%0,%1,%2,%3,%4,%5,%6,%7}, [%8];"
        : "=f"(a.x), "=f"(a.y), "=f"(a.z), "=f"(a.w),
          "=f"(b.x), "=f"(b.y), "=f"(b.z), "=f"(b.w) : "l"(p));
}
__device__ __forceinline__ void stg_stream4(float* p, float4 v) {
    asm volatile("st.global.cs.v4.f32 [%0], {%1,%2,%3,%4};"
                 :: "l"(p), "f"(v.x), "f"(v.y), "f"(v.z), "f"(v.w) : "memory");
}

#define BAR_SYNC(id, cnt)   asm volatile("bar.sync %0, %1;"   :: "r"(id), "r"(cnt) : "memory")
#define BAR_ARRIVE(id, cnt) asm volatile("bar.arrive %0, %1;" :: "r"(id), "r"(cnt) : "memory")

// ---------------------------------------------------------------------------
// Weight prep: fp16(rn) swizzled tiles. 48 blocks: weight = bx>>3.
// ---------------------------------------------------------------------------
__global__ void prep_w(const float* __restrict__ W0, const float* __restrict__ W1,
                       const float* __restrict__ W2, const float* __restrict__ W3,
                       const float* __restrict__ W4, const float* __restrict__ W5)
{
    const float* W;
    switch (blockIdx.x >> 3) {
        case 0: W = W0; break; case 1: W = W1; break; case 2: W = W2; break;
        case 3: W = W3; break; case 4: W = W4; break; default: W = W5; break;
    }
    unsigned char* out = g_wbf + (size_t)(blockIdx.x >> 3) * 32768;
    int base = (blockIdx.x & 7) * 2048;
    for (int ii = threadIdx.x; ii < 2048; ii += blockDim.x) {
        int idx = base + ii;
        int row = idx >> 7, col = idx & 127;
        __half h = __float2half_rn(W[idx]);
        *reinterpret_cast<uint16_t*>(out + sw_off(row, col)) = __half_as_ushort(h);
    }
}

// 64KB weight staging (both weights), 512 threads
__device__ __forceinline__ void copy_weights_async(char* sm, int w1idx, int w2idx) {
    uint32_t d1 = smem_u32(sm + SW1HI);
    uint32_t d2 = smem_u32(sm + SW2HI);
    const char* s1 = reinterpret_cast<const char*>(g_wbf + (size_t)w1idx * 32768);
    const char* s2 = reinterpret_cast<const char*>(g_wbf + (size_t)w2idx * 32768);
    int tid = threadIdx.x;
    #pragma unroll
    for (int i = 0; i < 4; i++) {
        int j = (tid + i * 512) * 16;
        asm volatile("cp.async.cg.shared.global [%0], [%1], 16;"
                     :: "r"(d1 + j), "l"(s1 + j));
        asm volatile("cp.async.cg.shared.global [%0], [%1], 16;"
                     :: "r"(d2 + j), "l"(s2 + j));
    }
}

// ---------------------------------------------------------------------------
// Converts: fp32 -> single fp16 plane, swizzled
// ---------------------------------------------------------------------------
__device__ __forceinline__ uint2 cvt4(float4 xv) {
    __half h0 = __float2half_rn(xv.x), h1 = __float2half_rn(xv.y);
    __half h2 = __float2half_rn(xv.z), h3 = __float2half_rn(xv.w);
    uint32_t hp01, hp23;
    asm("mov.b32 %0, {%1, %2};" : "=r"(hp01)
        : "h"(__half_as_ushort(h0)), "h"(__half_as_ushort(h1)));
    asm("mov.b32 %0, {%1, %2};" : "=r"(hp23)
        : "h"(__half_as_ushort(h2)), "h"(__half_as_ushort(h3)));
    return make_uint2(hp01, hp23);
}

// Node-side: 128-row tile (512 threads)
__device__ __forceinline__ void convert_x128(char* sm, const float* __restrict__ X,
                                             int m0, int M) {
    int tid = threadIdx.x;
    int r = tid >> 2;
    int ch = (tid & 3) * 32;
    bool valid = (m0 + r) < M;
    const float* xp = X + (size_t)(m0 + r) * 128 + ch;
    #pragma unroll
    for (int u = 0; u < 8; u++) {
        int c = ch + u * 4;
        float4 xv = make_float4(0.f, 0.f, 0.f, 0.f);
        if (valid) xv = __ldg(reinterpret_cast<const float4*>(xp + u * 4));
        *reinterpret_cast<uint2*>(sm + SXHI + sw_off(r, c)) = cvt4(xv);
    }
}

// Edge-side: 32-row tile into an 8KB stage (128 threads), streaming 32B loads
__device__ __forceinline__ void convert_x32(char* xbuf, const float* __restrict__ X,
                                            int e0, int gtid) {
    int r = gtid >> 2;              // 0..31
    int ch = (gtid & 3) * 32;
    const float* xp = X + (size_t)(e0 + r) * 128 + ch;
    #pragma unroll
    for (int u = 0; u < 4; u++) {
        int c = ch + u * 8;
        float4 xa, xb;
        ldg_stream8(xp + u * 8, xa, xb);
        *reinterpret_cast<uint2*>(xbuf + sw_off(r, c)) = cvt4(xa);
        *reinterpret_cast<uint2*>(xbuf + sw_off(r, c + 4)) = cvt4(xb);
    }
}

// ---------------------------------------------------------------------------
// Node MMA (16 warps, M=128), single fp16
// ---------------------------------------------------------------------------
__device__ __forceinline__ void mma_tile128(const char* sm, float acc[2][8][4]) {
    const int lane = threadIdx.x & 31;
    const int wid  = threadIdx.x >> 5;
    const int wm = wid & 3, wn = wid >> 2;
    const int g  = lane >> 2;
    const int t4 = (lane & 3) * 4;

    const char* xhi = sm + SXHI;
    const char* wh = sm + ((wn >= 2) ? SW2HI : SW1HI);

    const int arow = (wm * 32 + g) * 256 + t4;
    const int brow = ((wn & 1) * 64 + g) * 256 + t4;

    #pragma unroll
    for (int i = 0; i < 2; i++)
        #pragma unroll
        for (int j = 0; j < 8; j++)
            #pragma unroll
            for (int r = 0; r < 4; r++) acc[i][j][r] = 0.f;

    #pragma unroll
    for (int ks = 0; ks < 8; ks++) {
        const int cx0 = (((2 * ks) ^ g) << 4);
        const int cx1 = (((2 * ks + 1) ^ g) << 4);
        uint32_t ah[2][4];
        #pragma unroll
        for (int i = 0; i < 2; i++) {
            int r0 = arow + i * 16 * 256;
            int r8 = r0 + 8 * 256;
            ah[i][0] = *reinterpret_cast<const uint32_t*>(xhi + r0 + cx0);
            ah[i][1] = *reinterpret_cast<const uint32_t*>(xhi + r8 + cx0);
            ah[i][2] = *reinterpret_cast<const uint32_t*>(xhi + r0 + cx1);
            ah[i][3] = *reinterpret_cast<const uint32_t*>(xhi + r8 + cx1);
        }
        #pragma unroll
        for (int j = 0; j < 8; j++) {
            int rb = brow + j * 8 * 256;
            uint32_t bh0 = *reinterpret_cast<const uint32_t*>(wh + rb + cx0);
            uint32_t bh1 = *reinterpret_cast<const uint32_t*>(wh + rb + cx1);
            #pragma unroll
            for (int i = 0; i < 2; i++)
                hmma(acc[i][j], ah[i][0], ah[i][1], ah[i][2], ah[i][3], bh0, bh1);
        }
    }
}

// ---------------------------------------------------------------------------
// 32-row tile MMA via ldmatrix, single fp16 (layout proven R11-15)
// ---------------------------------------------------------------------------
__device__ __forceinline__ void mma_tile32g(uint32_t smb, uint32_t xbuf,
                                            int gw, int lane,
                                            float acc[2][8][4]) {
    const int mi = lane >> 3;
    const int r  = lane & 7;
    const uint32_t xh = xbuf;
    const uint32_t wh = smb + ((gw >= 2) ? SW2HI : SW1HI);

    const uint32_t aro0 = (uint32_t)(((mi & 1) * 8 + r) * 256);
    const uint32_t aro1 = aro0 + 16 * 256;
    const int axc = mi >> 1;
    const int bxc = mi & 1;
    uint32_t bro[4];
    #pragma unroll
    for (int jp = 0; jp < 4; jp++)
        bro[jp] = (uint32_t)((((gw & 1) * 64) + (jp * 2 + (mi >> 1)) * 8 + r) * 256);

    #pragma unroll
    for (int i = 0; i < 2; i++)
        #pragma unroll
        for (int j = 0; j < 8; j++)
            #pragma unroll
            for (int rr = 0; rr < 4; rr++) acc[i][j][rr] = 0.f;

    #pragma unroll
    for (int ks = 0; ks < 8; ks++) {
        const uint32_t xA = (uint32_t)(((2 * ks + axc) ^ r) << 4);
        const uint32_t xB = (uint32_t)(((2 * ks + bxc) ^ r) << 4);
        uint32_t ah[8];
        LDSM_X4(ah[0], ah[1], ah[2], ah[3], xh + aro0 + xA);
        LDSM_X4(ah[4], ah[5], ah[6], ah[7], xh + aro1 + xA);
        #pragma unroll
        for (int jp = 0; jp < 4; jp++) {
            uint32_t bh[4];
            LDSM_X4(bh[0], bh[1], bh[2], bh[3], wh + bro[jp] + xB);
            const int j0 = jp * 2, j1 = jp * 2 + 1;
            hmma(acc[0][j0], ah[0], ah[1], ah[2], ah[3], bh[0], bh[1]);
            hmma(acc[0][j1], ah[0], ah[1], ah[2], ah[3], bh[2], bh[3]);
            hmma(acc[1][j0], ah[4], ah[5], ah[6], ah[7], bh[0], bh[1]);
            hmma(acc[1][j1], ah[4], ah[5], ah[6], ah[7], bh[2], bh[3]);
        }
    }
}

// ---------------------------------------------------------------------------
// Node GEMMs merged; trailing ZBLK blocks zero agg
// ---------------------------------------------------------------------------
__global__ __launch_bounds__(512, 1) void gemm_node(
    const float* __restrict__ X,
    const float* __restrict__ bq, const float* __restrict__ bk,
    const float* __restrict__ bv, const float* __restrict__ bout,
    float* __restrict__ q, float* __restrict__ kk,
    float* __restrict__ vv, float* __restrict__ nres,
    float* __restrict__ agg)
{
    if (blockIdx.x >= 2 * NBLK) {
        int idx = (blockIdx.x - 2 * NBLK) * 512 + threadIdx.x;
        const int stride = ZBLK * 512;
        float4 z = make_float4(0.f, 0.f, 0.f, 0.f);
        for (int i = idx; i < NN * 32; i += stride)
            reinterpret_cast<float4*>(agg)[i] = z;
        return;
    }

    extern __shared__ char sm[];
    const int half = blockIdx.x / NBLK;
    const int tile = blockIdx.x % NBLK;
    const int m0 = tile * 128;
    const float* b1 = half ? bv : bq;
    const float* b2 = half ? bout : bk;
    float* Y1 = half ? vv : q;
    float* Y2 = half ? nres : kk;

    copy_weights_async(sm, half * 2, half * 2 + 1);
    asm volatile("cp.async.commit_group;");
    convert_x128(sm, X, m0, NN);
    asm volatile("cp.async.wait_group 0;");
    __syncthreads();

    float acc[2][8][4];
    mma_tile128(sm, acc);

    const int lane = threadIdx.x & 31;
    const int wid  = threadIdx.x >> 5;
    const int wm = wid & 3, wn = wid >> 2;
    const int g = lane >> 2, t2 = (lane & 3) * 2;

    const float* bias = (wn >= 2) ? b2 : b1;
    float* Y = (wn >= 2) ? Y2 : Y1;
    float2 bb[8];
    #pragma unroll
    for (int j = 0; j < 8; j++) {
        int colw = (wn & 1) * 64 + j * 8 + t2;
        bb[j] = *reinterpret_cast<const float2*>(&bias[colw]);
    }
    #pragma unroll
    for (int i = 0; i < 2; i++) {
        int rlo = m0 + wm * 32 + i * 16 + g;
        int rhi = rlo + 8;
        #pragma unroll
        for (int j = 0; j < 8; j++) {
            int colw = (wn & 1) * 64 + j * 8 + t2;
            if (rlo < NN) {
                float2 o = make_float2(acc[i][j][0] + bb[j].x, acc[i][j][1] + bb[j].y);
                *reinterpret_cast<float2*>(&Y[(size_t)rlo * 128 + colw]) = o;
            }
            if (rhi < NN) {
                float2 o = make_float2(acc[i][j][2] + bb[j].x, acc[i][j][3] + bb[j].y);
                *reinterpret_cast<float2*>(&Y[(size_t)rhi * 128 + colw]) = o;
            }
        }
    }
}

// ---------------------------------------------------------------------------
// Warp-specialized persistent edge kernel (R12-15 structure, single-plane X).
//   wid 0-3: MMA warps; wid 4-11: edge-math warps; wid 12-15: convert warps.
// X ring 3x8KB; P ring 2x33792 with 132-float padded rows.
// Barriers: XFULL s->1+s (256), XEMPTY s->4+s (256),
//           PFULL p->7+p (384), PEMPTY p->9+p (384).
// ---------------------------------------------------------------------------
__global__ __launch_bounds__(512, 1) void edge_ws(
    const float* __restrict__ edge_feats,
    const float* __restrict__ be, const float* __restrict__ bev,
    const int* __restrict__ src, const int* __restrict__ dst,
    const float* __restrict__ q, const float* __restrict__ k,
    const float* __restrict__ v,
    const float* __restrict__ ln_eg, const float* __restrict__ ln_eb,
    float* __restrict__ agg, float* __restrict__ y_out)
{
    extern __shared__ char sm[];
    const uint32_t smb = smem_u32(sm);
    const int tid  = threadIdx.x;
    const int lane = tid & 31;
    const int wid  = tid >> 5;
    const unsigned FULL = 0xffffffffu;

    copy_weights_async(sm, 4, 5);      // We, Wev
    asm volatile("cp.async.commit_group;");
    asm volatile("cp.async.wait_group 0;");
    __syncthreads();

    int it = 0;
    if (wid >= 12) {
        // ---------------- convert warps ----------------
        const int gtid = tid - 384;    // 0..127
        for (int t = blockIdx.x; t < ETILES32; t += gridDim.x, ++it) {
            const int s = it % 3;
            if (it >= 3) BAR_SYNC(4 + s, 256);
            convert_x32(sm + EXR0 + s * 8192, edge_feats, t * 32, gtid);
            BAR_ARRIVE(1 + s, 256);
        }
    } else if (wid < 4) {
        // ---------------- MMA warps ----------------
        const int gw = wid;
        const float* bias = (gw >= 2) ? bev : be;
        const int g = lane >> 2, t2 = (lane & 3) * 2;
        float2 bb[8];
        #pragma unroll
        for (int j = 0; j < 8; j++) {
            int colw = (gw & 1) * 64 + j * 8 + t2;
            bb[j] = *reinterpret_cast<const float2*>(&bias[colw]);
        }
        for (int t = blockIdx.x; t < ETILES32; t += gridDim.x, ++it) {
            const int s = it % 3;
            const int p = it & 1;
            BAR_SYNC(1 + s, 256);
            float acc[2][8][4];
            mma_tile32g(smb, smb + EXR0 + s * 8192, gw, lane, acc);
            BAR_ARRIVE(4 + s, 256);
            if (it >= 2) BAR_SYNC(9 + p, 384);
            float* Pp = reinterpret_cast<float*>(sm + EPR0 + p * PSTAGE)
                        + ((gw >= 2) ? PHALF : 0);
            #pragma unroll
            for (int i = 0; i < 2; i++) {
                int rlo = i * 16 + g;
                int rhi = rlo + 8;
                #pragma unroll
                for (int j = 0; j < 8; j++) {
                    int colw = (gw & 1) * 64 + j * 8 + t2;
                    Pp[rlo * PROW + colw]     = acc[i][j][0] + bb[j].x;
                    Pp[rlo * PROW + colw + 1] = acc[i][j][1] + bb[j].y;
                    Pp[rhi * PROW + colw]     = acc[i][j][2] + bb[j].x;
                    Pp[rhi * PROW + colw + 1] = acc[i][j][3] + bb[j].y;
                }
            }
            BAR_ARRIVE(7 + p, 384);
        }
    } else {
        // ---------------- edge-math warps ----------------
        const int ew = wid - 4;        // 0..7
        const int rbase = ew * 4;
        float4 ge = *reinterpret_cast<const float4*>(&ln_eg[4 * lane]);
        float4 gb = *reinterpret_cast<const float4*>(&ln_eb[4 * lane]);
        for (int t = blockIdx.x; t < ETILES32; t += gridDim.x, ++it) {
            const int p = it & 1;
            const int e0 = t * 32;
            int sd = 0;
            if (lane < 8)
                sd = __ldg(((lane < 4) ? src : dst) + e0 + rbase + (lane & 3));
            int se[4], de[4];
            #pragma unroll
            for (int e = 0; e < 4; e++) {
                se[e] = __shfl_sync(FULL, sd, e);
                de[e] = __shfl_sync(FULL, sd, e + 4);
            }
            float4 Q[4], K[4], V[4];
            #pragma unroll
            for (int e = 0; e < 4; e++) {
                Q[e] = __ldg(reinterpret_cast<const float4*>(&q[(size_t)se[e] * 128 + 4 * lane]));
                K[e] = __ldg(reinterpret_cast<const float4*>(&k[(size_t)de[e] * 128 + 4 * lane]));
                V[e] = __ldg(reinterpret_cast<const float4*>(&v[(size_t)se[e] * 128 + 4 * lane]));
            }
            BAR_SYNC(7 + p, 384);
            const float* Pe = reinterpret_cast<const float*>(sm + EPR0 + p * PSTAGE);
            const float* Pr = Pe + PHALF;   // eres plane
            #pragma unroll
            for (int e = 0; e < 4; e++) {
                int row = rbase + e;
                float pd = Q[e].x * K[e].x + Q[e].y * K[e].y
                         + Q[e].z * K[e].z + Q[e].w * K[e].w;
                pd += __shfl_xor_sync(FULL, pd, 1);
                pd += __shfl_xor_sync(FULL, pd, 2);
                pd += __shfl_xor_sync(FULL, pd, 4);

                float4 m4 = *reinterpret_cast<const float4*>(&Pe[row * PROW + 4 * lane]);
                m4.x = fmaf(pd, INV_SCALE, m4.x);
                m4.y = fmaf(pd, INV_SCALE, m4.y);
                m4.z = fmaf(pd, INV_SCALE, m4.z);
                m4.w = fmaf(pd, INV_SCALE, m4.w);

                float4 ex;
                ex.x = __expf(m4.x); ex.y = __expf(m4.y);
                ex.z = __expf(m4.z); ex.w = __expf(m4.w);
                float4 sx = ex;
                #pragma unroll
                for (int off = 8; off <= 16; off <<= 1) {
                    sx.x += __shfl_xor_sync(FULL, sx.x, off);
                    sx.y += __shfl_xor_sync(FULL, sx.y, off);
                    sx.z += __shfl_xor_sync(FULL, sx.z, off);
                    sx.w += __shfl_xor_sync(FULL, sx.w, off);
                }
                float4 msg;
                msg.x = V[e].x * ex.x * __fdividef(1.0f, sx.x);
                msg.y = V[e].y * ex.y * __fdividef(1.0f, sx.y);
                msg.z = V[e].z * ex.z * __fdividef(1.0f, sx.z);
                msg.w = V[e].w * ex.w * __fdividef(1.0f, sx.w);
                float* ap = &agg[(size_t)de[e] * 128 + 4 * lane];
                asm volatile("red.global.add.v4.f32 [%0], {%1, %2, %3, %4};"
                             :: "l"(ap), "f"(msg.x), "f"(msg.y), "f"(msg.z), "f"(msg.w)
                             : "memory");

                float ls = m4.x + m4.y + m4.z + m4.w;
                float lq = m4.x * m4.x + m4.y * m4.y + m4.z * m4.z + m4.w * m4.w;
                #pragma unroll
                for (int off = 16; off > 0; off >>= 1) {
                    ls += __shfl_xor_sync(FULL, ls, off);
                    lq += __shfl_xor_sync(FULL, lq, off);
                }
                float mu = ls * (1.0f / 128.0f);
                float var = lq * (1.0f / 128.0f) - mu * mu;
                float rs = rsqrtf(var + LN_EPS);

                float t0 = fmaf((m4.x - mu) * rs, ge.x, gb.x);
                float t1 = fmaf((m4.y - mu) * rs, ge.y, gb.y);
                float t2f = fmaf((m4.z - mu) * rs, ge.z, gb.z);
                float t3 = fmaf((m4.w - mu) * rs, ge.w, gb.w);
                float4 er = *reinterpret_cast<const float4*>(&Pr[row * PROW + 4 * lane]);
                float4 o;
                o.x = t0 * __fdividef(1.0f, 1.0f + __expf(-t0)) + er.x;
                o.y = t1 * __fdividef(1.0f, 1.0f + __expf(-t1)) + er.y;
                o.z = t2f * __fdividef(1.0f, 1.0f + __expf(-t2f)) + er.z;
                o.w = t3 * __fdividef(1.0f, 1.0f + __expf(-t3)) + er.w;
                stg_stream4(&y_out[(size_t)(e0 + row) * 128 + 4 * lane], o);
            }
            BAR_ARRIVE(9 + p, 384);
        }
    }
}

// ---------------------------------------------------------------------------
// Node finalize
// ---------------------------------------------------------------------------
__global__ __launch_bounds__(256) void node_kernel(
    const float* __restrict__ agg, const float* __restrict__ nres,
    const float* __restrict__ ln_ng, const float* __restrict__ ln_nb,
    float* __restrict__ x_out)
{
    int node = (blockIdx.x * blockDim.x + threadIdx.x) >> 5;
    int lane = threadIdx.x & 31;
    if (node >= NN) return;
    const unsigned FULL = 0xffffffffu;

    size_t base = (size_t)node * 128 + 4 * lane;
    float4 a = __ldg(reinterpret_cast<const float4*>(&agg[base]));

    float ls = a.x + a.y + a.z + a.w;
    float lq = a.x * a.x + a.y * a.y + a.z * a.z + a.w * a.w;
    #pragma unroll
    for (int off = 16; off > 0; off >>= 1) {
        ls += __shfl_xor_sync(FULL, ls, off);
        lq += __shfl_xor_sync(FULL, lq, off);
    }
    float mu  = ls * (1.0f / 128.0f);
    float var = lq * (1.0f / 128.0f) - mu * mu;
    float rs  = rsqrtf(var + LN_EPS);

    float4 g = __ldg(reinterpret_cast<const float4*>(&ln_ng[4 * lane]));
    float4 b = __ldg(reinterpret_cast<const float4*>(&ln_nb[4 * lane]));
    float4 r = __ldg(reinterpret_cast<const float4*>(&nres[base]));

    float t0 = fmaf((a.x - mu) * rs, g.x, b.x);
    float t1 = fmaf((a.y - mu) * rs, g.y, b.y);
    float t2 = fmaf((a.z - mu) * rs, g.z, b.z);
    float t3 = fmaf((a.w - mu) * rs, g.w, b.w);
    float4 o;
    o.x = t0 * __fdividef(1.0f, 1.0f + __expf(-t0)) + r.x;
    o.y = t1 * __fdividef(1.0f, 1.0f + __expf(-t1)) + r.y;
    o.z = t2 * __fdividef(1.0f, 1.0f + __expf(-t2)) + r.z;
    o.w = t3 * __fdividef(1.0f, 1.0f + __expf(-t3)) + r.w;
    *reinterpret_cast<float4*>(&x_out[base]) = o;
}

// ---------------------------------------------------------------------------
// Launch
// ---------------------------------------------------------------------------
extern "C" void kernel_launch(void* const* d_in, const int* in_sizes, int n_in,
                              void* d_out, int out_size)
{
    const float* node_feats = (const float*)d_in[0];
    const float* edge_feats = (const float*)d_in[1];
    const int*   src        = (const int*)d_in[2];
    const int*   dst        = (const int*)d_in[3];
    const float* Wq   = (const float*)d_in[4];
    const float* bq   = (const float*)d_in[5];
    const float* Wk   = (const float*)d_in[6];
    const float* bk   = (const float*)d_in[7];
    const float* Wv   = (const float*)d_in[8];
    const float* bv   = (const float*)d_in[9];
    const float* We   = (const float*)d_in[10];
    const float* be   = (const float*)d_in[11];
    const float* Wev  = (const float*)d_in[12];
    const float* bev  = (const float*)d_in[13];
    const float* Wout = (const float*)d_in[14];
    const float* bout = (const float*)d_in[15];
    const float* ln_ng = (const float*)d_in[16];
    const float* ln_nb = (const float*)d_in[17];
    const float* ln_eg = (const float*)d_in[18];
    const float* ln_eb = (const float*)d_in[19];

    float* scratch = nullptr;
    cudaGetSymbolAddress((void**)&scratch, g_scratch);
    float* q    = scratch;
    float* kk   = q    + (size_t)NN * 128;
    float* vv   = kk   + (size_t)NN * 128;
    float* nres = vv   + (size_t)NN * 128;
    float* agg  = nres + (size_t)NN * 128;

    float* x_out = (float*)d_out;
    float* y_out = x_out + (size_t)NN * 128;

    static bool attr_set = false;
    if (!attr_set) {
        cudaFuncSetAttribute(gemm_node, cudaFuncAttributeMaxDynamicSharedMemorySize, SMEM_GEMM);
        cudaFuncSetAttribute(edge_ws, cudaFuncAttributeMaxDynamicSharedMemorySize, SMEM_EDGE_WS);
        attr_set = true;
    }

    int nsm = 148;
    cudaDeviceGetAttribute(&nsm, cudaDevAttrMultiProcessorCount, 0);

    // launch order: 0 prep_w, 1 gemm_node(+zero), 2 edge_ws, 3 node
    prep_w<<<48, 256>>>(Wq, Wk, Wv, Wout, We, Wev);
    gemm_node<<<2 * NBLK + ZBLK, 512, SMEM_GEMM>>>(
        node_feats, bq, bk, bv, bout, q, kk, vv, nres, agg);
    edge_ws<<<nsm, 512, SMEM_EDGE_WS>>>(
        edge_feats, be, bev, src, dst, q, kk, vv, ln_eg, ln_eb, agg, y_out);
    node_kernel<<<NN / 8, 256>>>(agg, nres, ln_ng, ln_nb, x_out);
}

// round 17
// speedup vs baseline: 2.4101x; 1.0371x over previous
#include <cuda_runtime.h>
#include <cuda_bf16.h>
#include <cuda_fp16.h>
#include <math.h>
#include <stdint.h>

#define NN 50000
#define EE 400000
#define NBLK 391            // ceil(NN/128) node tiles
#define ZBLK 391            // agg-zero blocks appended to gemm_node
#define ETILES32 12500      // EE/32 edge tiles
#define INV_SCALE 0.17677669529663687f   // 1/sqrt(32)
#define LN_EPS 1e-5f

// Scratch (float units): qh/kh/vh fp16 (NN*64 floats each), nres, agg fp32
__device__ float g_scratch[32000000];
// fp16 swizzled weight tiles: 6 weights x 32KB
__device__ __align__(256) unsigned char g_wbf[6 * 32768];

// ---- node gemm smem layout (single-plane X) ----
#define SW1HI 0
#define SW2HI 32768
#define SXHI  65536              // X 32KB (single fp16 plane)
#define SMEM_GEMM 98304
// ---- edge WS smem: W 64KB + X ring 3x8KB + P ring 2x33792 ----
#define EXR0  65536              // X ring (8KB/stage, single plane)
#define EPR0  90112              // P ring (33792/stage: eproj | eres)
#define PROW  132                // padded row stride (floats)
#define PSTAGE 33792
#define PHALF  4224              // floats: offset of eres plane
#define SMEM_EDGE_WS (90112 + 2 * PSTAGE)   // 157696

// Swizzled byte offset in a K-major fp16 tile (256B rows, 16B chunks,
// chunk ^= row&7 -> conflict-free for row-parallel and k-parallel access).
__device__ __forceinline__ int sw_off(int row, int col) {
    return row * 256 + ((((col >> 3) ^ (row & 7)) & 15) << 4) + (col & 7) * 2;
}

__device__ __forceinline__ uint32_t smem_u32(const void* p) {
    uint32_t a;
    asm("{ .reg .u64 t; cvta.to.shared.u64 t, %1; cvt.u32.u64 %0, t; }"
        : "=r"(a) : "l"(p));
    return a;
}

__device__ __forceinline__ void hmma(float* c, uint32_t a0, uint32_t a1,
                                     uint32_t a2, uint32_t a3,
                                     uint32_t b0, uint32_t b1) {
    asm("mma.sync.aligned.m16n8k16.row.col.f32.f16.f16.f32 "
        "{%0,%1,%2,%3}, {%4,%5,%6,%7}, {%8,%9}, {%0,%1,%2,%3};"
        : "+f"(c[0]), "+f"(c[1]), "+f"(c[2]), "+f"(c[3])
        : "r"(a0), "r"(a1), "r"(a2), "r"(a3), "r"(b0), "r"(b1));
}

#define LDSM_X4(r0, r1, r2, r3, addr) \
    asm volatile("ldmatrix.sync.aligned.m8n8.x4.shared.b16 {%0,%1,%2,%3}, [%4];" \
        : "=r"(r0), "=r"(r1), "=r"(r2), "=r"(r3) : "r"(addr))

// streaming 32B global load (evict-first in L2): protect q/k/v residency
__device__ __forceinline__ void ldg_stream8(const float* p, float4& a, float4& b) {
    asm("ld.global.nc.L2::evict_first.v8.b32 {%0,%1,%2,%3,%4,%5,%6,%7}, [%8];"
        : "=f"(a.x), "=f"(a.y), "=f"(a.z), "=f"(a.w),
          "=f"(b.x), "=f"(b.y), "=f"(b.z), "=f"(b.w) : "l"(p));
}
__device__ __forceinline__ void stg_stream4(float* p, float4 v) {
    asm volatile("st.global.cs.v4.f32 [%0], {%1,%2,%3,%4};"
                 :: "l"(p), "f"(v.x), "f"(v.y), "f"(v.z), "f"(v.w) : "memory");
}

#define BAR_SYNC(id, cnt)   asm volatile("bar.sync %0, %1;"   :: "r"(id), "r"(cnt) : "memory")
#define BAR_ARRIVE(id, cnt) asm volatile("bar.arrive %0, %1;" :: "r"(id), "r"(cnt) : "memory")

// ---------------------------------------------------------------------------
// Weight prep: fp16(rn) swizzled tiles. 48 blocks: weight = bx>>3.
// ---------------------------------------------------------------------------
__global__ void prep_w(const float* __restrict__ W0, const float* __restrict__ W1,
                       const float* __restrict__ W2, const float* __restrict__ W3,
                       const float* __restrict__ W4, const float* __restrict__ W5)
{
    const float* W;
    switch (blockIdx.x >> 3) {
        case 0: W = W0; break; case 1: W = W1; break; case 2: W = W2; break;
        case 3: W = W3; break; case 4: W = W4; break; default: W = W5; break;
    }
    unsigned char* out = g_wbf + (size_t)(blockIdx.x >> 3) * 32768;
    int base = (blockIdx.x & 7) * 2048;
    for (int ii = threadIdx.x; ii < 2048; ii += blockDim.x) {
        int idx = base + ii;
        int row = idx >> 7, col = idx & 127;
        __half h = __float2half_rn(W[idx]);
        *reinterpret_cast<uint16_t*>(out + sw_off(row, col)) = __half_as_ushort(h);
    }
}

// 64KB weight staging (both weights), 512 threads
__device__ __forceinline__ void copy_weights_async(char* sm, int w1idx, int w2idx) {
    uint32_t d1 = smem_u32(sm + SW1HI);
    uint32_t d2 = smem_u32(sm + SW2HI);
    const char* s1 = reinterpret_cast<const char*>(g_wbf + (size_t)w1idx * 32768);
    const char* s2 = reinterpret_cast<const char*>(g_wbf + (size_t)w2idx * 32768);
    int tid = threadIdx.x;
    #pragma unroll
    for (int i = 0; i < 4; i++) {
        int j = (tid + i * 512) * 16;
        asm volatile("cp.async.cg.shared.global [%0], [%1], 16;"
                     :: "r"(d1 + j), "l"(s1 + j));
        asm volatile("cp.async.cg.shared.global [%0], [%1], 16;"
                     :: "r"(d2 + j), "l"(s2 + j));
    }
}

// ---------------------------------------------------------------------------
// Converts: fp32 -> single fp16 plane, swizzled
// ---------------------------------------------------------------------------
__device__ __forceinline__ uint2 cvt4(float4 xv) {
    __half h0 = __float2half_rn(xv.x), h1 = __float2half_rn(xv.y);
    __half h2 = __float2half_rn(xv.z), h3 = __float2half_rn(xv.w);
    uint32_t hp01, hp23;
    asm("mov.b32 %0, {%1, %2};" : "=r"(hp01)
        : "h"(__half_as_ushort(h0)), "h"(__half_as_ushort(h1)));
    asm("mov.b32 %0, {%1, %2};" : "=r"(hp23)
        : "h"(__half_as_ushort(h2)), "h"(__half_as_ushort(h3)));
    return make_uint2(hp01, hp23);
}

// Node-side: 128-row tile (512 threads)
__device__ __forceinline__ void convert_x128(char* sm, const float* __restrict__ X,
                                             int m0, int M) {
    int tid = threadIdx.x;
    int r = tid >> 2;
    int ch = (tid & 3) * 32;
    bool valid = (m0 + r) < M;
    const float* xp = X + (size_t)(m0 + r) * 128 + ch;
    #pragma unroll
    for (int u = 0; u < 8; u++) {
        int c = ch + u * 4;
        float4 xv = make_float4(0.f, 0.f, 0.f, 0.f);
        if (valid) xv = __ldg(reinterpret_cast<const float4*>(xp + u * 4));
        *reinterpret_cast<uint2*>(sm + SXHI + sw_off(r, c)) = cvt4(xv);
    }
}

// Edge-side: 32-row tile into an 8KB stage (128 threads), streaming 32B loads
__device__ __forceinline__ void convert_x32(char* xbuf, const float* __restrict__ X,
                                            int e0, int gtid) {
    int r = gtid >> 2;              // 0..31
    int ch = (gtid & 3) * 32;
    const float* xp = X + (size_t)(e0 + r) * 128 + ch;
    #pragma unroll
    for (int u = 0; u < 4; u++) {
        int c = ch + u * 8;
        float4 xa, xb;
        ldg_stream8(xp + u * 8, xa, xb);
        *reinterpret_cast<uint2*>(xbuf + sw_off(r, c)) = cvt4(xa);
        *reinterpret_cast<uint2*>(xbuf + sw_off(r, c + 4)) = cvt4(xb);
    }
}

// ---------------------------------------------------------------------------
// Node MMA (16 warps, M=128), single fp16
// ---------------------------------------------------------------------------
__device__ __forceinline__ void mma_tile128(const char* sm, float acc[2][8][4]) {
    const int lane = threadIdx.x & 31;
    const int wid  = threadIdx.x >> 5;
    const int wm = wid & 3, wn = wid >> 2;
    const int g  = lane >> 2;
    const int t4 = (lane & 3) * 4;

    const char* xhi = sm + SXHI;
    const char* wh = sm + ((wn >= 2) ? SW2HI : SW1HI);

    const int arow = (wm * 32 + g) * 256 + t4;
    const int brow = ((wn & 1) * 64 + g) * 256 + t4;

    #pragma unroll
    for (int i = 0; i < 2; i++)
        #pragma unroll
        for (int j = 0; j < 8; j++)
            #pragma unroll
            for (int r = 0; r < 4; r++) acc[i][j][r] = 0.f;

    #pragma unroll
    for (int ks = 0; ks < 8; ks++) {
        const int cx0 = (((2 * ks) ^ g) << 4);
        const int cx1 = (((2 * ks + 1) ^ g) << 4);
        uint32_t ah[2][4];
        #pragma unroll
        for (int i = 0; i < 2; i++) {
            int r0 = arow + i * 16 * 256;
            int r8 = r0 + 8 * 256;
            ah[i][0] = *reinterpret_cast<const uint32_t*>(xhi + r0 + cx0);
            ah[i][1] = *reinterpret_cast<const uint32_t*>(xhi + r8 + cx0);
            ah[i][2] = *reinterpret_cast<const uint32_t*>(xhi + r0 + cx1);
            ah[i][3] = *reinterpret_cast<const uint32_t*>(xhi + r8 + cx1);
        }
        #pragma unroll
        for (int j = 0; j < 8; j++) {
            int rb = brow + j * 8 * 256;
            uint32_t bh0 = *reinterpret_cast<const uint32_t*>(wh + rb + cx0);
            uint32_t bh1 = *reinterpret_cast<const uint32_t*>(wh + rb + cx1);
            #pragma unroll
            for (int i = 0; i < 2; i++)
                hmma(acc[i][j], ah[i][0], ah[i][1], ah[i][2], ah[i][3], bh0, bh1);
        }
    }
}

// ---------------------------------------------------------------------------
// 32-row tile MMA via ldmatrix, single fp16 (layout proven R11-16)
// ---------------------------------------------------------------------------
__device__ __forceinline__ void mma_tile32g(uint32_t smb, uint32_t xbuf,
                                            int gw, int lane,
                                            float acc[2][8][4]) {
    const int mi = lane >> 3;
    const int r  = lane & 7;
    const uint32_t xh = xbuf;
    const uint32_t wh = smb + ((gw >= 2) ? SW2HI : SW1HI);

    const uint32_t aro0 = (uint32_t)(((mi & 1) * 8 + r) * 256);
    const uint32_t aro1 = aro0 + 16 * 256;
    const int axc = mi >> 1;
    const int bxc = mi & 1;
    uint32_t bro[4];
    #pragma unroll
    for (int jp = 0; jp < 4; jp++)
        bro[jp] = (uint32_t)((((gw & 1) * 64) + (jp * 2 + (mi >> 1)) * 8 + r) * 256);

    #pragma unroll
    for (int i = 0; i < 2; i++)
        #pragma unroll
        for (int j = 0; j < 8; j++)
            #pragma unroll
            for (int rr = 0; rr < 4; rr++) acc[i][j][rr] = 0.f;

    #pragma unroll
    for (int ks = 0; ks < 8; ks++) {
        const uint32_t xA = (uint32_t)(((2 * ks + axc) ^ r) << 4);
        const uint32_t xB = (uint32_t)(((2 * ks + bxc) ^ r) << 4);
        uint32_t ah[8];
        LDSM_X4(ah[0], ah[1], ah[2], ah[3], xh + aro0 + xA);
        LDSM_X4(ah[4], ah[5], ah[6], ah[7], xh + aro1 + xA);
        #pragma unroll
        for (int jp = 0; jp < 4; jp++) {
            uint32_t bh[4];
            LDSM_X4(bh[0], bh[1], bh[2], bh[3], wh + bro[jp] + xB);
            const int j0 = jp * 2, j1 = jp * 2 + 1;
            hmma(acc[0][j0], ah[0], ah[1], ah[2], ah[3], bh[0], bh[1]);
            hmma(acc[0][j1], ah[0], ah[1], ah[2], ah[3], bh[2], bh[3]);
            hmma(acc[1][j0], ah[4], ah[5], ah[6], ah[7], bh[0], bh[1]);
            hmma(acc[1][j1], ah[4], ah[5], ah[6], ah[7], bh[2], bh[3]);
        }
    }
}

// ---------------------------------------------------------------------------
// Node GEMMs merged; q/k/v outputs stored as fp16, nres fp32.
// Trailing ZBLK blocks zero agg.
// ---------------------------------------------------------------------------
__global__ __launch_bounds__(512, 1) void gemm_node(
    const float* __restrict__ X,
    const float* __restrict__ bq, const float* __restrict__ bk,
    const float* __restrict__ bv, const float* __restrict__ bout,
    __half* __restrict__ qh, __half* __restrict__ kh,
    __half* __restrict__ vh, float* __restrict__ nres,
    float* __restrict__ agg)
{
    if (blockIdx.x >= 2 * NBLK) {
        int idx = (blockIdx.x - 2 * NBLK) * 512 + threadIdx.x;
        const int stride = ZBLK * 512;
        float4 z = make_float4(0.f, 0.f, 0.f, 0.f);
        for (int i = idx; i < NN * 32; i += stride)
            reinterpret_cast<float4*>(agg)[i] = z;
        return;
    }

    extern __shared__ char sm[];
    const int half = blockIdx.x / NBLK;
    const int tile = blockIdx.x % NBLK;
    const int m0 = tile * 128;
    const float* b1 = half ? bv : bq;
    const float* b2 = half ? bout : bk;

    copy_weights_async(sm, half * 2, half * 2 + 1);
    asm volatile("cp.async.commit_group;");
    convert_x128(sm, X, m0, NN);
    asm volatile("cp.async.wait_group 0;");
    __syncthreads();

    float acc[2][8][4];
    mma_tile128(sm, acc);

    const int lane = threadIdx.x & 31;
    const int wid  = threadIdx.x >> 5;
    const int wm = wid & 3, wn = wid >> 2;
    const int g = lane >> 2, t2 = (lane & 3) * 2;

    const float* bias = (wn >= 2) ? b2 : b1;
    float2 bb[8];
    #pragma unroll
    for (int j = 0; j < 8; j++) {
        int colw = (wn & 1) * 64 + j * 8 + t2;
        bb[j] = *reinterpret_cast<const float2*>(&bias[colw]);
    }

    const bool f16out = (half == 0) || (wn < 2);
    __half* Yh = (half == 0) ? ((wn >= 2) ? kh : qh) : vh;

    #pragma unroll
    for (int i = 0; i < 2; i++) {
        int rlo = m0 + wm * 32 + i * 16 + g;
        int rhi = rlo + 8;
        #pragma unroll
        for (int j = 0; j < 8; j++) {
            int colw = (wn & 1) * 64 + j * 8 + t2;
            float2 o0 = make_float2(acc[i][j][0] + bb[j].x, acc[i][j][1] + bb[j].y);
            float2 o1 = make_float2(acc[i][j][2] + bb[j].x, acc[i][j][3] + bb[j].y);
            if (f16out) {
                if (rlo < NN)
                    *reinterpret_cast<__half2*>(&Yh[(size_t)rlo * 128 + colw]) =
                        __floats2half2_rn(o0.x, o0.y);
                if (rhi < NN)
                    *reinterpret_cast<__half2*>(&Yh[(size_t)rhi * 128 + colw]) =
                        __floats2half2_rn(o1.x, o1.y);
            } else {
                if (rlo < NN)
                    *reinterpret_cast<float2*>(&nres[(size_t)rlo * 128 + colw]) = o0;
                if (rhi < NN)
                    *reinterpret_cast<float2*>(&nres[(size_t)rhi * 128 + colw]) = o1;
            }
        }
    }
}

// ---------------------------------------------------------------------------
// Warp-specialized persistent edge kernel (R12-16 structure, fp16 q/k/v).
//   wid 0-3: MMA warps; wid 4-11: edge-math warps; wid 12-15: convert warps.
// X ring 3x8KB; P ring 2x33792 with 132-float padded rows.
// Barriers: XFULL s->1+s (256), XEMPTY s->4+s (256),
//           PFULL p->7+p (384), PEMPTY p->9+p (384).
// ---------------------------------------------------------------------------
__global__ __launch_bounds__(512, 1) void edge_ws(
    const float* __restrict__ edge_feats,
    const float* __restrict__ be, const float* __restrict__ bev,
    const int* __restrict__ src, const int* __restrict__ dst,
    const __half* __restrict__ qh, const __half* __restrict__ kh,
    const __half* __restrict__ vh,
    const float* __restrict__ ln_eg, const float* __restrict__ ln_eb,
    float* __restrict__ agg, float* __restrict__ y_out)
{
    extern __shared__ char sm[];
    const uint32_t smb = smem_u32(sm);
    const int tid  = threadIdx.x;
    const int lane = tid & 31;
    const int wid  = tid >> 5;
    const unsigned FULL = 0xffffffffu;

    copy_weights_async(sm, 4, 5);      // We, Wev
    asm volatile("cp.async.commit_group;");
    asm volatile("cp.async.wait_group 0;");
    __syncthreads();

    int it = 0;
    if (wid >= 12) {
        // ---------------- convert warps ----------------
        const int gtid = tid - 384;    // 0..127
        for (int t = blockIdx.x; t < ETILES32; t += gridDim.x, ++it) {
            const int s = it % 3;
            if (it >= 3) BAR_SYNC(4 + s, 256);
            convert_x32(sm + EXR0 + s * 8192, edge_feats, t * 32, gtid);
            BAR_ARRIVE(1 + s, 256);
        }
    } else if (wid < 4) {
        // ---------------- MMA warps ----------------
        const int gw = wid;
        const float* bias = (gw >= 2) ? bev : be;
        const int g = lane >> 2, t2 = (lane & 3) * 2;
        float2 bb[8];
        #pragma unroll
        for (int j = 0; j < 8; j++) {
            int colw = (gw & 1) * 64 + j * 8 + t2;
            bb[j] = *reinterpret_cast<const float2*>(&bias[colw]);
        }
        for (int t = blockIdx.x; t < ETILES32; t += gridDim.x, ++it) {
            const int s = it % 3;
            const int p = it & 1;
            BAR_SYNC(1 + s, 256);
            float acc[2][8][4];
            mma_tile32g(smb, smb + EXR0 + s * 8192, gw, lane, acc);
            BAR_ARRIVE(4 + s, 256);
            if (it >= 2) BAR_SYNC(9 + p, 384);
            float* Pp = reinterpret_cast<float*>(sm + EPR0 + p * PSTAGE)
                        + ((gw >= 2) ? PHALF : 0);
            #pragma unroll
            for (int i = 0; i < 2; i++) {
                int rlo = i * 16 + g;
                int rhi = rlo + 8;
                #pragma unroll
                for (int j = 0; j < 8; j++) {
                    int colw = (gw & 1) * 64 + j * 8 + t2;
                    Pp[rlo * PROW + colw]     = acc[i][j][0] + bb[j].x;
                    Pp[rlo * PROW + colw + 1] = acc[i][j][1] + bb[j].y;
                    Pp[rhi * PROW + colw]     = acc[i][j][2] + bb[j].x;
                    Pp[rhi * PROW + colw + 1] = acc[i][j][3] + bb[j].y;
                }
            }
            BAR_ARRIVE(7 + p, 384);
        }
    } else {
        // ---------------- edge-math warps ----------------
        const int ew = wid - 4;        // 0..7
        const int rbase = ew * 4;
        float4 ge = *reinterpret_cast<const float4*>(&ln_eg[4 * lane]);
        float4 gb = *reinterpret_cast<const float4*>(&ln_eb[4 * lane]);
        for (int t = blockIdx.x; t < ETILES32; t += gridDim.x, ++it) {
            const int p = it & 1;
            const int e0 = t * 32;
            int sd = 0;
            if (lane < 8)
                sd = __ldg(((lane < 4) ? src : dst) + e0 + rbase + (lane & 3));
            int se[4], de[4];
            #pragma unroll
            for (int e = 0; e < 4; e++) {
                se[e] = __shfl_sync(FULL, sd, e);
                de[e] = __shfl_sync(FULL, sd, e + 4);
            }
            // gather q/k/v (fp16, 8B per lane per row) for all 4 edges
            uint2 Qh[4], Kh[4], Vh[4];
            #pragma unroll
            for (int e = 0; e < 4; e++) {
                Qh[e] = __ldg(reinterpret_cast<const uint2*>(qh + (size_t)se[e] * 128 + 4 * lane));
                Kh[e] = __ldg(reinterpret_cast<const uint2*>(kh + (size_t)de[e] * 128 + 4 * lane));
                Vh[e] = __ldg(reinterpret_cast<const uint2*>(vh + (size_t)se[e] * 128 + 4 * lane));
            }
            BAR_SYNC(7 + p, 384);
            const float* Pe = reinterpret_cast<const float*>(sm + EPR0 + p * PSTAGE);
            const float* Pr = Pe + PHALF;   // eres plane
            #pragma unroll
            for (int e = 0; e < 4; e++) {
                int row = rbase + e;
                float2 q01 = __half22float2(*reinterpret_cast<const __half2*>(&Qh[e].x));
                float2 q23 = __half22float2(*reinterpret_cast<const __half2*>(&Qh[e].y));
                float2 k01 = __half22float2(*reinterpret_cast<const __half2*>(&Kh[e].x));
                float2 k23 = __half22float2(*reinterpret_cast<const __half2*>(&Kh[e].y));
                float2 v01 = __half22float2(*reinterpret_cast<const __half2*>(&Vh[e].x));
                float2 v23 = __half22float2(*reinterpret_cast<const __half2*>(&Vh[e].y));

                float pd = q01.x * k01.x + q01.y * k01.y + q23.x * k23.x + q23.y * k23.y;
                pd += __shfl_xor_sync(FULL, pd, 1);
                pd += __shfl_xor_sync(FULL, pd, 2);
                pd += __shfl_xor_sync(FULL, pd, 4);

                float4 m4 = *reinterpret_cast<const float4*>(&Pe[row * PROW + 4 * lane]);
                m4.x = fmaf(pd, INV_SCALE, m4.x);
                m4.y = fmaf(pd, INV_SCALE, m4.y);
                m4.z = fmaf(pd, INV_SCALE, m4.z);
                m4.w = fmaf(pd, INV_SCALE, m4.w);

                float4 ex;
                ex.x = __expf(m4.x); ex.y = __expf(m4.y);
                ex.z = __expf(m4.z); ex.w = __expf(m4.w);
                float4 sx = ex;
                #pragma unroll
                for (int off = 8; off <= 16; off <<= 1) {
                    sx.x += __shfl_xor_sync(FULL, sx.x, off);
                    sx.y += __shfl_xor_sync(FULL, sx.y, off);
                    sx.z += __shfl_xor_sync(FULL, sx.z, off);
                    sx.w += __shfl_xor_sync(FULL, sx.w, off);
                }
                float4 msg;
                msg.x = v01.x * ex.x * __fdividef(1.0f, sx.x);
                msg.y = v01.y * ex.y * __fdividef(1.0f, sx.y);
                msg.z = v23.x * ex.z * __fdividef(1.0f, sx.z);
                msg.w = v23.y * ex.w * __fdividef(1.0f, sx.w);
                float* ap = &agg[(size_t)de[e] * 128 + 4 * lane];
                asm volatile("red.global.add.v4.f32 [%0], {%1, %2, %3, %4};"
                             :: "l"(ap), "f"(msg.x), "f"(msg.y), "f"(msg.z), "f"(msg.w)
                             : "memory");

                float ls = m4.x + m4.y + m4.z + m4.w;
                float lq = m4.x * m4.x + m4.y * m4.y + m4.z * m4.z + m4.w * m4.w;
                #pragma unroll
                for (int off = 16; off > 0; off >>= 1) {
                    ls += __shfl_xor_sync(FULL, ls, off);
                    lq += __shfl_xor_sync(FULL, lq, off);
                }
                float mu = ls * (1.0f / 128.0f);
                float var = lq * (1.0f / 128.0f) - mu * mu;
                float rs = rsqrtf(var + LN_EPS);

                float t0 = fmaf((m4.x - mu) * rs, ge.x, gb.x);
                float t1 = fmaf((m4.y - mu) * rs, ge.y, gb.y);
                float t2f = fmaf((m4.z - mu) * rs, ge.z, gb.z);
                float t3 = fmaf((m4.w - mu) * rs, ge.w, gb.w);
                float4 er = *reinterpret_cast<const float4*>(&Pr[row * PROW + 4 * lane]);
                float4 o;
                o.x = t0 * __fdividef(1.0f, 1.0f + __expf(-t0)) + er.x;
                o.y = t1 * __fdividef(1.0f, 1.0f + __expf(-t1)) + er.y;
                o.z = t2f * __fdividef(1.0f, 1.0f + __expf(-t2f)) + er.z;
                o.w = t3 * __fdividef(1.0f, 1.0f + __expf(-t3)) + er.w;
                stg_stream4(&y_out[(size_t)(e0 + row) * 128 + 4 * lane], o);
            }
            BAR_ARRIVE(9 + p, 384);
        }
    }
}

// ---------------------------------------------------------------------------
// Node finalize
// ---------------------------------------------------------------------------
__global__ __launch_bounds__(256) void node_kernel(
    const float* __restrict__ agg, const float* __restrict__ nres,
    const float* __restrict__ ln_ng, const float* __restrict__ ln_nb,
    float* __restrict__ x_out)
{
    int node = (blockIdx.x * blockDim.x + threadIdx.x) >> 5;
    int lane = threadIdx.x & 31;
    if (node >= NN) return;
    const unsigned FULL = 0xffffffffu;

    size_t base = (size_t)node * 128 + 4 * lane;
    float4 a = __ldg(reinterpret_cast<const float4*>(&agg[base]));

    float ls = a.x + a.y + a.z + a.w;
    float lq = a.x * a.x + a.y * a.y + a.z * a.z + a.w * a.w;
    #pragma unroll
    for (int off = 16; off > 0; off >>= 1) {
        ls += __shfl_xor_sync(FULL, ls, off);
        lq += __shfl_xor_sync(FULL, lq, off);
    }
    float mu  = ls * (1.0f / 128.0f);
    float var = lq * (1.0f / 128.0f) - mu * mu;
    float rs  = rsqrtf(var + LN_EPS);

    float4 g = __ldg(reinterpret_cast<const float4*>(&ln_ng[4 * lane]));
    float4 b = __ldg(reinterpret_cast<const float4*>(&ln_nb[4 * lane]));
    float4 r = __ldg(reinterpret_cast<const float4*>(&nres[base]));

    float t0 = fmaf((a.x - mu) * rs, g.x, b.x);
    float t1 = fmaf((a.y - mu) * rs, g.y, b.y);
    float t2 = fmaf((a.z - mu) * rs, g.z, b.z);
    float t3 = fmaf((a.w - mu) * rs, g.w, b.w);
    float4 o;
    o.x = t0 * __fdividef(1.0f, 1.0f + __expf(-t0)) + r.x;
    o.y = t1 * __fdividef(1.0f, 1.0f + __expf(-t1)) + r.y;
    o.z = t2 * __fdividef(1.0f, 1.0f + __expf(-t2)) + r.z;
    o.w = t3 * __fdividef(1.0f, 1.0f + __expf(-t3)) + r.w;
    *reinterpret_cast<float4*>(&x_out[base]) = o;
}

// ---------------------------------------------------------------------------
// Launch
// ---------------------------------------------------------------------------
extern "C" void kernel_launch(void* const* d_in, const int* in_sizes, int n_in,
                              void* d_out, int out_size)
{
    const float* node_feats = (const float*)d_in[0];
    const float* edge_feats = (const float*)d_in[1];
    const int*   src        = (const int*)d_in[2];
    const int*   dst        = (const int*)d_in[3];
    const float* Wq   = (const float*)d_in[4];
    const float* bq   = (const float*)d_in[5];
    const float* Wk   = (const float*)d_in[6];
    const float* bk   = (const float*)d_in[7];
    const float* Wv   = (const float*)d_in[8];
    const float* bv   = (const float*)d_in[9];
    const float* We   = (const float*)d_in[10];
    const float* be   = (const float*)d_in[11];
    const float* Wev  = (const float*)d_in[12];
    const float* bev  = (const float*)d_in[13];
    const float* Wout = (const float*)d_in[14];
    const float* bout = (const float*)d_in[15];
    const float* ln_ng = (const float*)d_in[16];
    const float* ln_nb = (const float*)d_in[17];
    const float* ln_eg = (const float*)d_in[18];
    const float* ln_eb = (const float*)d_in[19];

    float* scratch = nullptr;
    cudaGetSymbolAddress((void**)&scratch, g_scratch);
    // fp16 q/k/v: each NN*128 halves = NN*64 floats
    __half* qh  = reinterpret_cast<__half*>(scratch);
    __half* kh  = reinterpret_cast<__half*>(scratch + (size_t)NN * 64);
    __half* vh  = reinterpret_cast<__half*>(scratch + (size_t)NN * 128);
    float* nres = scratch + (size_t)NN * 192;
    float* agg  = nres + (size_t)NN * 128;

    float* x_out = (float*)d_out;
    float* y_out = x_out + (size_t)NN * 128;

    static bool attr_set = false;
    if (!attr_set) {
        cudaFuncSetAttribute(gemm_node, cudaFuncAttributeMaxDynamicSharedMemorySize, SMEM_GEMM);
        cudaFuncSetAttribute(edge_ws, cudaFuncAttributeMaxDynamicSharedMemorySize, SMEM_EDGE_WS);
        attr_set = true;
    }

    int nsm = 148;
    cudaDeviceGetAttribute(&nsm, cudaDevAttrMultiProcessorCount, 0);

    // launch order: 0 prep_w, 1 gemm_node(+zero), 2 edge_ws, 3 node
    prep_w<<<48, 256>>>(Wq, Wk, Wv, Wout, We, Wev);
    gemm_node<<<2 * NBLK + ZBLK, 512, SMEM_GEMM>>>(
        node_feats, bq, bk, bv, bout, qh, kh, vh, nres, agg);
    edge_ws<<<nsm, 512, SMEM_EDGE_WS>>>(
        edge_feats, be, bev, src, dst, qh, kh, vh, ln_eg, ln_eb, agg, y_out);
    node_kernel<<<NN / 8, 256>>>(agg, nres, ln_ng, ln_nb, x_out);
}